// round 6
// baseline (speedup 1.0000x reference)
#include <cuda_runtime.h>
#include <cuda_bf16.h>
#include <stdint.h>

// Problem constants
#define B_  4
#define S_  512
#define J_  24
#define H_  128
#define NH_ 8
#define HS_ 16
#define BS_ (B_*S_)            // 2048 rows
#define INST_ (B_*NH_*J_)      // 768 attention instances

// Scratch (static device globals — allocation-free)
__device__ float g_q [B_*NH_*J_*S_*HS_];   // (b,n,j,s,d)
__device__ float g_k [B_*NH_*J_*S_*HS_];
__device__ float g_v [B_*NH_*J_*S_*HS_];
__device__ float g_ao[B_*S_*J_*H_];        // attention out, (b,s,j,h) h=n*16+d

// ===========================================================================
// Warp-MMA helpers (baseline PTX features only)
// ===========================================================================
__device__ __forceinline__ uint32_t smem_u32(const void* p) {
    uint32_t a;
    asm("{ .reg .u64 t; cvta.to.shared.u64 t, %1; cvt.u32.u64 %0, t; }"
        : "=r"(a) : "l"(p));
    return a;
}

__device__ __forceinline__ void ldsm_x4(uint32_t& r0, uint32_t& r1,
                                        uint32_t& r2, uint32_t& r3, uint32_t addr) {
    asm volatile("ldmatrix.sync.aligned.m8n8.x4.shared.b16 {%0,%1,%2,%3}, [%4];"
                 : "=r"(r0), "=r"(r1), "=r"(r2), "=r"(r3) : "r"(addr));
}
__device__ __forceinline__ void ldsm_x4_t(uint32_t& r0, uint32_t& r1,
                                          uint32_t& r2, uint32_t& r3, uint32_t addr) {
    asm volatile("ldmatrix.sync.aligned.m8n8.x4.trans.shared.b16 {%0,%1,%2,%3}, [%4];"
                 : "=r"(r0), "=r"(r1), "=r"(r2), "=r"(r3) : "r"(addr));
}

__device__ __forceinline__ void mma_bf16(float* c, const uint32_t a[4],
                                         uint32_t b0, uint32_t b1) {
    asm volatile(
        "mma.sync.aligned.m16n8k16.row.col.f32.bf16.bf16.f32 "
        "{%0,%1,%2,%3}, {%4,%5,%6,%7}, {%8,%9}, {%0,%1,%2,%3};"
        : "+f"(c[0]), "+f"(c[1]), "+f"(c[2]), "+f"(c[3])
        : "r"(a[0]), "r"(a[1]), "r"(a[2]), "r"(a[3]), "r"(b0), "r"(b1));
}

// split-fp32 -> (hi bf16x2, lo bf16x2); a -> low half, b -> high half
__device__ __forceinline__ void cvt_pair(float a, float b, uint32_t& hi, uint32_t& lo) {
    uint32_t h;
    asm("cvt.rn.bf16x2.f32 %0, %1, %2;" : "=r"(h) : "f"(b), "f"(a));
    float ha = __uint_as_float(h << 16);
    float hb = __uint_as_float(h & 0xffff0000u);
    float la = a - ha, lb = b - hb;
    asm("cvt.rn.bf16x2.f32 %0, %1, %2;" : "=r"(lo) : "f"(lb), "f"(la));
    hi = h;
}

#define SAB_B 272      // A row stride in bytes (136 bf16)
#define SBN   144      // B (transposed [k][n]) row stride in bytes (64 cols + pad)

// ===========================================================================
// Kernel 1: QKV projection. grid (16, 24, 2): rowtile, joint, col-half.
// block 256. C(128x64) = X(128x128) * W[:, c0:c0+64]. B stored [k][n] (trans).
// smem: Ah(34816) Al(34816) Bh(18432) Bl(18432) = 104 KB -> 2 CTAs/SM.
// ===========================================================================
#define QK_AHI 0
#define QK_ALO 34816
#define QK_BHI 69632
#define QK_BLO 88064
#define QK_TOTAL 106496

__global__ __launch_bounds__(256, 2)
void qkv_mma(const float* __restrict__ x,
             const float* __restrict__ qm,
             const float* __restrict__ km,
             const float* __restrict__ vm)
{
    extern __shared__ char smem[];
    const int j   = blockIdx.y;
    const int c0  = blockIdx.z * 64;     // output col-half
    const int nh0 = c0 >> 4;             // first head of this half
    const int r0  = blockIdx.x * 128;
    const int tid = threadIdx.x, wid = tid >> 5, lane = tid & 31;

    // --- Stage A (X rows r0..r0+127), hi/lo split, row-major [row][k] ---
    #pragma unroll 4
    for (int t = tid; t < 4096; t += 256) {
        int row = t >> 5, kk = (t & 31) << 2;
        const float4 xv = *(const float4*)(x + ((size_t)(r0 + row) * J_ + j) * H_ + kk);
        uint32_t h01, l01, h23, l23;
        cvt_pair(xv.x, xv.y, h01, l01);
        cvt_pair(xv.z, xv.w, h23, l23);
        *(uint2*)(smem + QK_AHI + row * SAB_B + kk * 2) = make_uint2(h01, h23);
        *(uint2*)(smem + QK_ALO + row * SAB_B + kk * 2) = make_uint2(l01, l23);
    }

    const float* mats[3] = {qm, km, vm};
    const int warpM = wid & 3, warpN = wid >> 2;

    // gemm addressing (set up once)
    const uint32_t sb = smem_u32(smem);
    const int ar = lane & 15, ac = (lane >> 4) << 3;
    const int bg = lane >> 3, blp = lane & 7;
    const int kt = ((bg & 1) << 3) + blp;    // k-row within k16 group (trans ldsm)
    const int nb = (bg >> 1) << 4;           // byte offset within 32B n-chunk
    const uint32_t aRow = (uint32_t)(warpM * 32 + ar) * SAB_B;

    for (int m = 0; m < 3; m++) {
        if (m > 0) __syncthreads();   // previous gemm done reading B
        // --- Stage B^T [k][n] for matrix m, coalesced float4 along d ---
        const float* mat = mats[m];
        #pragma unroll 4
        for (int t = tid; t < 2048; t += 256) {          // 2048 float4
            int nhl = t >> 9, f = t & 511;               // 4 heads x 512 float4
            int k = f >> 2, d0 = (f & 3) << 2;
            const float4 wv = *(const float4*)(mat +
                (((size_t)(nh0 + nhl) * J_ + j) * H_ + k) * HS_ + d0);
            uint32_t h01, l01, h23, l23;
            cvt_pair(wv.x, wv.y, h01, l01);
            cvt_pair(wv.z, wv.w, h23, l23);
            int nl2 = (nhl * 16 + d0) * 2;
            *(uint2*)(smem + QK_BHI + k * SBN + nl2) = make_uint2(h01, h23);
            *(uint2*)(smem + QK_BLO + k * SBN + nl2) = make_uint2(l01, l23);
        }
        __syncthreads();

        // --- GEMM: 3-split products, warp tile 32x32 ---
        float acc[2][4][4];
        #pragma unroll
        for (int mt = 0; mt < 2; mt++)
            #pragma unroll
            for (int nt = 0; nt < 4; nt++)
                #pragma unroll
                for (int i = 0; i < 4; i++) acc[mt][nt][i] = 0.f;

        #pragma unroll 1
        for (int sp = 0; sp < 3; sp++) {
            const uint32_t aB = sb + ((sp == 2) ? QK_ALO : QK_AHI) + aRow;
            const uint32_t bB = sb + ((sp == 1) ? QK_BLO : QK_BHI);
            #pragma unroll
            for (int k0 = 0; k0 < 8; k0++) {
                uint32_t a[2][4];
                #pragma unroll
                for (int mt = 0; mt < 2; mt++)
                    ldsm_x4(a[mt][0], a[mt][1], a[mt][2], a[mt][3],
                            aB + (uint32_t)(mt * 16) * SAB_B + (uint32_t)(k0 * 16 + ac) * 2);
                #pragma unroll
                for (int ntp = 0; ntp < 2; ntp++) {
                    uint32_t b[4];
                    ldsm_x4_t(b[0], b[1], b[2], b[3],
                              bB + (uint32_t)(k0 * 16 + kt) * SBN
                                 + (uint32_t)(warpN * 32 + ntp * 16) * 2 + nb);
                    #pragma unroll
                    for (int mt = 0; mt < 2; mt++) {
                        mma_bf16(acc[mt][ntp * 2],     a[mt], b[0], b[1]);
                        mma_bf16(acc[mt][ntp * 2 + 1], a[mt], b[2], b[3]);
                    }
                }
            }
        }

        // --- Scatter: col c -> head n=c>>4, d=c&15 ---
        float* out = (m == 0) ? g_q : (m == 1 ? g_k : g_v);
        #pragma unroll
        for (int mt = 0; mt < 2; mt++) {
            int rbase = r0 + warpM * 32 + mt * 16 + (lane >> 2);
            #pragma unroll
            for (int nt = 0; nt < 4; nt++) {
                int c = c0 + warpN * 32 + nt * 8 + ((lane & 3) << 1);
                int n = c >> 4, d = c & 15;
                #pragma unroll
                for (int h = 0; h < 2; h++) {
                    int r = rbase + h * 8;
                    int b = r >> 9, sI = r & 511;
                    *(float2*)(out + (((size_t)(b * NH_ + n) * J_ + j) * S_ + sI) * HS_ + d) =
                        make_float2(acc[mt][nt][h * 2], acc[mt][nt][h * 2 + 1]);
                }
            }
        }
    }
}

// ===========================================================================
// Kernel 2: tensor-core causal attention. 256 threads (8 warps); warp w
// processes bands {w, 15-w} (34 k-tiles each -> perfectly balanced).
// 2 CTAs/SM (128-reg cap) — the (256,3) variant spilled to local memory.
// ===========================================================================
#define AT_KH 0
#define AT_KL 16384
#define AT_VH 32768
#define AT_VL 49152
#define AT_TOTAL 65536

// 0.25 (softmax scale) * log2(e)  — folded into Q so p = exp2(S)
#define QSCALE 0.3606737602222409f

__global__ __launch_bounds__(256, 2)
void attn_mma()
{
    extern __shared__ char smem[];
    const int inst = blockIdx.x;
    const int j  = inst % J_;
    const int bn = inst / J_;
    const int n  = bn % NH_;
    const int b  = bn / NH_;
    const size_t base = (size_t)inst * S_ * HS_;

    const int tid = threadIdx.x, wid = tid >> 5, lane = tid & 31;

    // Stage K and V as hi/lo bf16, row layout [s][16] (32B rows)
    #pragma unroll 4
    for (int i = tid; i < 2048; i += 256) {
        int s = i >> 2, d0 = (i & 3) << 2;
        uint32_t h0, l0, h1, l1;
        float4 kv = *(const float4*)(g_k + base + s * 16 + d0);
        cvt_pair(kv.x, kv.y, h0, l0); cvt_pair(kv.z, kv.w, h1, l1);
        *(uint2*)(smem + AT_KH + s * 32 + d0 * 2) = make_uint2(h0, h1);
        *(uint2*)(smem + AT_KL + s * 32 + d0 * 2) = make_uint2(l0, l1);
        float4 vv = *(const float4*)(g_v + base + s * 16 + d0);
        cvt_pair(vv.x, vv.y, h0, l0); cvt_pair(vv.z, vv.w, h1, l1);
        *(uint2*)(smem + AT_VH + s * 32 + d0 * 2) = make_uint2(h0, h1);
        *(uint2*)(smem + AT_VL + s * 32 + d0 * 2) = make_uint2(l0, l1);
    }
    __syncthreads();

    const uint32_t Kh = smem_u32(smem) + AT_KH;
    const uint32_t Kl = smem_u32(smem) + AT_KL;
    const uint32_t Vh = smem_u32(smem) + AT_VH;
    const uint32_t Vl = smem_u32(smem) + AT_VL;

    const int bg = lane >> 3, bl = lane & 7;
    const int kn = ((bg >> 1) << 3) + bl;   // K non-trans addressing
    const int kk = (bg & 1) << 3;
    const int vt = ((bg & 1) << 3) + bl;    // V trans addressing
    const int vd = (bg >> 1) << 4;

    #pragma unroll 1
    for (int h2 = 0; h2 < 2; h2++) {
        const int band = h2 ? (15 - wid) : wid;
        const int R0 = band * 32;

        // Q fragments (a-frag layout) from global, pre-scaled, split hi/lo
        uint32_t qh[2][4], ql[2][4];
        {
            int r = R0 + (lane >> 2);
            int c = (lane & 3) << 1;
            #pragma unroll
            for (int mt = 0; mt < 2; mt++) {
                const float* qp = g_q + base + (size_t)(r + mt * 16) * HS_;
                float2 v00 = *(const float2*)(qp + c);
                float2 v01 = *(const float2*)(qp + c + 8);
                float2 v10 = *(const float2*)(qp + 8 * HS_ + c);
                float2 v11 = *(const float2*)(qp + 8 * HS_ + c + 8);
                cvt_pair(v00.x * QSCALE, v00.y * QSCALE, qh[mt][0], ql[mt][0]);
                cvt_pair(v10.x * QSCALE, v10.y * QSCALE, qh[mt][1], ql[mt][1]);
                cvt_pair(v01.x * QSCALE, v01.y * QSCALE, qh[mt][2], ql[mt][2]);
                cvt_pair(v11.x * QSCALE, v11.y * QSCALE, qh[mt][3], ql[mt][3]);
            }
        }

        float O[2][2][4];
        #pragma unroll
        for (int mt = 0; mt < 2; mt++)
            #pragma unroll
            for (int dt = 0; dt < 2; dt++)
                #pragma unroll
                for (int i = 0; i < 4; i++) O[mt][dt][i] = 0.f;
        float rs[2][2] = {{0.f, 0.f}, {0.f, 0.f}};

        const int ntp_max = 2 * band + 1;
        for (int ntp = 0; ntp <= ntp_max; ntp++) {
            const int C0 = ntp << 4;
            uint32_t kh[4], klr[4], vh[4], vlr[4];
            ldsm_x4(kh[0], kh[1], kh[2], kh[3],     Kh + (uint32_t)(C0 + kn) * 32 + kk * 2);
            ldsm_x4(klr[0], klr[1], klr[2], klr[3], Kl + (uint32_t)(C0 + kn) * 32 + kk * 2);
            ldsm_x4_t(vh[0], vh[1], vh[2], vh[3],   Vh + (uint32_t)(C0 + vt) * 32 + vd);
            ldsm_x4_t(vlr[0], vlr[1], vlr[2], vlr[3], Vl + (uint32_t)(C0 + vt) * 32 + vd);

            const bool diag = (ntp >= 2 * band);
            const int mt0 = (ntp == ntp_max) ? 1 : 0;

            for (int mt = mt0; mt < 2; mt++) {
                float S0[4] = {0.f, 0.f, 0.f, 0.f};
                float S1[4] = {0.f, 0.f, 0.f, 0.f};
                mma_bf16(S0, qh[mt], kh[0], kh[1]);
                mma_bf16(S0, ql[mt], kh[0], kh[1]);
                mma_bf16(S0, qh[mt], klr[0], klr[1]);
                mma_bf16(S1, qh[mt], kh[2], kh[3]);
                mma_bf16(S1, ql[mt], kh[2], kh[3]);
                mma_bf16(S1, qh[mt], klr[2], klr[3]);

                const int row0 = R0 + mt * 16 + (lane >> 2);
                const int col0 = C0 + ((lane & 3) << 1);
                float p[8];
                if (diag) {
                    p[0] = (col0     <= row0    ) ? exp2f(S0[0]) : 0.f;
                    p[1] = (col0 + 1 <= row0    ) ? exp2f(S0[1]) : 0.f;
                    p[2] = (col0     <= row0 + 8) ? exp2f(S0[2]) : 0.f;
                    p[3] = (col0 + 1 <= row0 + 8) ? exp2f(S0[3]) : 0.f;
                    p[4] = (col0 + 8 <= row0    ) ? exp2f(S1[0]) : 0.f;
                    p[5] = (col0 + 9 <= row0    ) ? exp2f(S1[1]) : 0.f;
                    p[6] = (col0 + 8 <= row0 + 8) ? exp2f(S1[2]) : 0.f;
                    p[7] = (col0 + 9 <= row0 + 8) ? exp2f(S1[3]) : 0.f;
                } else {
                    p[0] = exp2f(S0[0]);
                    p[1] = exp2f(S0[1]);
                    p[2] = exp2f(S0[2]);
                    p[3] = exp2f(S0[3]);
                    p[4] = exp2f(S1[0]);
                    p[5] = exp2f(S1[1]);
                    p[6] = exp2f(S1[2]);
                    p[7] = exp2f(S1[3]);
                }
                rs[mt][0] += (p[0] + p[1]) + (p[4] + p[5]);
                rs[mt][1] += (p[2] + p[3]) + (p[6] + p[7]);

                uint32_t ph[4], pl[4];
                cvt_pair(p[0], p[1], ph[0], pl[0]);
                cvt_pair(p[2], p[3], ph[1], pl[1]);
                cvt_pair(p[4], p[5], ph[2], pl[2]);
                cvt_pair(p[6], p[7], ph[3], pl[3]);

                mma_bf16(O[mt][0], ph, vh[0], vh[1]);
                mma_bf16(O[mt][0], pl, vh[0], vh[1]);
                mma_bf16(O[mt][0], ph, vlr[0], vlr[1]);
                mma_bf16(O[mt][1], ph, vh[2], vh[3]);
                mma_bf16(O[mt][1], pl, vh[2], vh[3]);
                mma_bf16(O[mt][1], ph, vlr[2], vlr[3]);
            }
        }

        // Row sums across 4 lanes, normalize, store.
        #pragma unroll
        for (int mt = 0; mt < 2; mt++) {
            float s0 = rs[mt][0], s1 = rs[mt][1];
            s0 += __shfl_xor_sync(0xffffffffu, s0, 1);
            s0 += __shfl_xor_sync(0xffffffffu, s0, 2);
            s1 += __shfl_xor_sync(0xffffffffu, s1, 1);
            s1 += __shfl_xor_sync(0xffffffffu, s1, 2);
            const float i0 = 1.f / s0, i1 = 1.f / s1;
            const int row = R0 + mt * 16 + (lane >> 2);
            const int dc  = (lane & 3) << 1;
            #pragma unroll
            for (int dt = 0; dt < 2; dt++) {
                const int d = dt * 8 + dc;
                float* o0 = g_ao + ((size_t)(b * S_ + row)     * J_ + j) * H_ + n * HS_ + d;
                float* o1 = g_ao + ((size_t)(b * S_ + row + 8) * J_ + j) * H_ + n * HS_ + d;
                *(float2*)o0 = make_float2(O[mt][dt][0] * i0, O[mt][dt][1] * i0);
                *(float2*)o1 = make_float2(O[mt][dt][2] * i1, O[mt][dt][3] * i1);
            }
        }
    }
}

// ===========================================================================
// Kernel 3: output projection + residual + LayerNorm.
// grid (32, 24): 64-row tiles. B in two 64-col halves sequentially.
// 2 CTAs/SM (128-reg cap; the (256,3) variant risked spills).
// ===========================================================================
#define P_AHI 0
#define P_ALO 17408
#define P_BHI 34816
#define P_BLO 53248
#define P_TOTAL 71680

__global__ __launch_bounds__(256, 2)
void proj_mma(const float* __restrict__ x,
              const float* __restrict__ proj,
              const float* __restrict__ gamma,
              const float* __restrict__ beta,
              float* __restrict__ out)
{
    extern __shared__ char smem[];
    const int j   = blockIdx.y;
    const int r0  = blockIdx.x * 64;
    const int tid = threadIdx.x, wid = tid >> 5, lane = tid & 31;

    // --- Stage A (attention-out rows r0..r0+63) ---
    #pragma unroll 4
    for (int t = tid; t < 2048; t += 256) {
        int row = t >> 5, kk = (t & 31) << 2;
        const float4 xv = *(const float4*)(g_ao + ((size_t)(r0 + row) * J_ + j) * H_ + kk);
        uint32_t h01, l01, h23, l23;
        cvt_pair(xv.x, xv.y, h01, l01);
        cvt_pair(xv.z, xv.w, h23, l23);
        *(uint2*)(smem + P_AHI + row * SAB_B + kk * 2) = make_uint2(h01, h23);
        *(uint2*)(smem + P_ALO + row * SAB_B + kk * 2) = make_uint2(l01, l23);
    }

    const int warpM = wid & 3, warpN = wid >> 2;
    const uint32_t sb = smem_u32(smem);
    const int ar = lane & 15, ac = (lane >> 4) << 3;
    const int bg = lane >> 3, blp = lane & 7;
    const int kt = ((bg & 1) << 3) + blp;
    const int nb = (bg >> 1) << 4;
    const uint32_t aRow = (uint32_t)(warpM * 16 + ar) * SAB_B;

    float acc[2][4][4];   // [pass][ntile][frag]
    #pragma unroll
    for (int p = 0; p < 2; p++)
        #pragma unroll
        for (int nt = 0; nt < 4; nt++)
            #pragma unroll
            for (int i = 0; i < 4; i++) acc[p][nt][i] = 0.f;

    #pragma unroll 1
    for (int p = 0; p < 2; p++) {
        if (p > 0) __syncthreads();      // previous gemm done reading B
        const int c0 = p * 64;
        // Stage B^T [h][kout] cols c0..c0+63 (proj is contiguous along kout)
        #pragma unroll 4
        for (int t = tid; t < 2048; t += 256) {
            int k = t >> 4, n0 = (t & 15) << 2;
            const float4 wv = *(const float4*)(proj + (size_t)j * H_ * H_ + k * H_ + c0 + n0);
            uint32_t h01, l01, h23, l23;
            cvt_pair(wv.x, wv.y, h01, l01);
            cvt_pair(wv.z, wv.w, h23, l23);
            *(uint2*)(smem + P_BHI + k * SBN + n0 * 2) = make_uint2(h01, h23);
            *(uint2*)(smem + P_BLO + k * SBN + n0 * 2) = make_uint2(l01, l23);
        }
        __syncthreads();

        #pragma unroll 1
        for (int sp = 0; sp < 3; sp++) {
            const uint32_t aB = sb + ((sp == 2) ? P_ALO : P_AHI) + aRow;
            const uint32_t bB = sb + ((sp == 1) ? P_BLO : P_BHI);
            #pragma unroll
            for (int k0 = 0; k0 < 8; k0++) {
                uint32_t a[4];
                ldsm_x4(a[0], a[1], a[2], a[3], aB + (uint32_t)(k0 * 16 + ac) * 2);
                #pragma unroll
                for (int ntp = 0; ntp < 2; ntp++) {
                    uint32_t bfr[4];
                    ldsm_x4_t(bfr[0], bfr[1], bfr[2], bfr[3],
                              bB + (uint32_t)(k0 * 16 + kt) * SBN
                                 + (uint32_t)(warpN * 32 + ntp * 16) * 2 + nb);
                    mma_bf16(acc[p][ntp * 2],     a, bfr[0], bfr[1]);
                    mma_bf16(acc[p][ntp * 2 + 1], a, bfr[2], bfr[3]);
                }
            }
        }
    }

    // Stage C into smem (aliases A region): [64][132] floats
    __syncthreads();
    float* Cs = (float*)smem;
    #pragma unroll
    for (int p = 0; p < 2; p++) {
        int rb = warpM * 16 + (lane >> 2);
        #pragma unroll
        for (int nt = 0; nt < 4; nt++) {
            int col = p * 64 + warpN * 32 + nt * 8 + ((lane & 3) << 1);
            #pragma unroll
            for (int h = 0; h < 2; h++) {
                Cs[(rb + h * 8) * 132 + col]     = acc[p][nt][h * 2];
                Cs[(rb + h * 8) * 132 + col + 1] = acc[p][nt][h * 2 + 1];
            }
        }
    }
    __syncthreads();

    // Residual + LN: 4 threads per row (32 cols each), combine via shfl.
    {
        const int row = tid >> 2;
        const int q   = tid & 3;
        const int r   = r0 + row;
        const float* xr = x + ((size_t)r * J_ + j) * H_ + q * 32;
        float* crow     = Cs + row * 132 + q * 32;

        float sum = 0.f, sq = 0.f;
        #pragma unroll
        for (int i = 0; i < 8; i++) {
            float4 c4 = *(float4*)(crow + i * 4);
            float4 xv = *(const float4*)(xr + i * 4);
            c4.x += xv.x; c4.y += xv.y; c4.z += xv.z; c4.w += xv.w;
            *(float4*)(crow + i * 4) = c4;
            sum += c4.x + c4.y + c4.z + c4.w;
            sq  += c4.x*c4.x + c4.y*c4.y + c4.z*c4.z + c4.w*c4.w;
        }
        sum += __shfl_xor_sync(0xffffffffu, sum, 1);
        sum += __shfl_xor_sync(0xffffffffu, sum, 2);
        sq  += __shfl_xor_sync(0xffffffffu, sq, 1);
        sq  += __shfl_xor_sync(0xffffffffu, sq, 2);
        const float mu   = sum * (1.f / 128.f);
        const float var  = sq * (1.f / 128.f) - mu * mu;
        const float rstd = rsqrtf(var + 1e-5f);

        float* orow = out + ((size_t)r * J_ + j) * H_ + q * 32;
        const float* gp  = gamma + q * 32;
        const float* bp2 = beta  + q * 32;
        #pragma unroll
        for (int i = 0; i < 8; i++) {
            float4 c4 = *(float4*)(crow + i * 4);
            float4 o;
            o.x = (c4.x - mu) * rstd * gp[i*4+0] + bp2[i*4+0];
            o.y = (c4.y - mu) * rstd * gp[i*4+1] + bp2[i*4+1];
            o.z = (c4.z - mu) * rstd * gp[i*4+2] + bp2[i*4+2];
            o.w = (c4.w - mu) * rstd * gp[i*4+3] + bp2[i*4+3];
            *(float4*)(orow + i * 4) = o;
        }
    }
}

// ===========================================================================
extern "C" void kernel_launch(void* const* d_in, const int* in_sizes, int n_in,
                              void* d_out, int out_size)
{
    const float* x     = (const float*)d_in[0];
    // d_in[1]: additive causal mask (= triu(-1e9)) — implemented as causal skip.
    const float* qm    = (const float*)d_in[2];
    const float* km    = (const float*)d_in[3];
    const float* vm    = (const float*)d_in[4];
    const float* proj  = (const float*)d_in[5];
    const float* gamma = (const float*)d_in[6];
    const float* beta  = (const float*)d_in[7];
    float* out = (float*)d_out;

    cudaFuncSetAttribute(qkv_mma,  cudaFuncAttributeMaxDynamicSharedMemorySize, QK_TOTAL);
    cudaFuncSetAttribute(attn_mma, cudaFuncAttributeMaxDynamicSharedMemorySize, AT_TOTAL);
    cudaFuncSetAttribute(proj_mma, cudaFuncAttributeMaxDynamicSharedMemorySize, P_TOTAL);

    qkv_mma<<<dim3(BS_/128, J_, 2), 256, QK_TOTAL>>>(x, qm, km, vm);
    attn_mma<<<INST_, 256, AT_TOTAL>>>();
    proj_mma<<<dim3(BS_/64, J_), 256, P_TOTAL>>>(x, proj, gamma, beta, out);
}

// round 7
// speedup vs baseline: 1.5094x; 1.5094x over previous
#include <cuda_runtime.h>
#include <cuda_bf16.h>
#include <stdint.h>

// Problem constants
#define B_  4
#define S_  512
#define J_  24
#define H_  128
#define NH_ 8
#define HS_ 16
#define BS_ (B_*S_)            // 2048 rows
#define INST_ (B_*NH_*J_)      // 768 attention instances

// Scratch (static device globals — allocation-free)
__device__ float g_q [B_*NH_*J_*S_*HS_];   // (b,n,j,s,d)
__device__ float g_k [B_*NH_*J_*S_*HS_];
__device__ float g_v [B_*NH_*J_*S_*HS_];
__device__ float g_ao[B_*S_*J_*H_];        // attention out, (b,s,j,h) h=n*16+d

// ===========================================================================
// Warp-MMA helpers (baseline PTX features only)
// ===========================================================================
__device__ __forceinline__ uint32_t smem_u32(const void* p) {
    uint32_t a;
    asm("{ .reg .u64 t; cvta.to.shared.u64 t, %1; cvt.u32.u64 %0, t; }"
        : "=r"(a) : "l"(p));
    return a;
}

__device__ __forceinline__ void ldsm_x4(uint32_t& r0, uint32_t& r1,
                                        uint32_t& r2, uint32_t& r3, uint32_t addr) {
    asm volatile("ldmatrix.sync.aligned.m8n8.x4.shared.b16 {%0,%1,%2,%3}, [%4];"
                 : "=r"(r0), "=r"(r1), "=r"(r2), "=r"(r3) : "r"(addr));
}
__device__ __forceinline__ void ldsm_x4_t(uint32_t& r0, uint32_t& r1,
                                          uint32_t& r2, uint32_t& r3, uint32_t addr) {
    asm volatile("ldmatrix.sync.aligned.m8n8.x4.trans.shared.b16 {%0,%1,%2,%3}, [%4];"
                 : "=r"(r0), "=r"(r1), "=r"(r2), "=r"(r3) : "r"(addr));
}

__device__ __forceinline__ void mma_bf16(float* c, const uint32_t a[4],
                                         uint32_t b0, uint32_t b1) {
    asm volatile(
        "mma.sync.aligned.m16n8k16.row.col.f32.bf16.bf16.f32 "
        "{%0,%1,%2,%3}, {%4,%5,%6,%7}, {%8,%9}, {%0,%1,%2,%3};"
        : "+f"(c[0]), "+f"(c[1]), "+f"(c[2]), "+f"(c[3])
        : "r"(a[0]), "r"(a[1]), "r"(a[2]), "r"(a[3]), "r"(b0), "r"(b1));
}

// split-fp32 -> (hi bf16x2, lo bf16x2); a -> low half, b -> high half
__device__ __forceinline__ void cvt_pair(float a, float b, uint32_t& hi, uint32_t& lo) {
    uint32_t h;
    asm("cvt.rn.bf16x2.f32 %0, %1, %2;" : "=r"(h) : "f"(b), "f"(a));
    float ha = __uint_as_float(h << 16);
    float hb = __uint_as_float(h & 0xffff0000u);
    float la = a - ha, lb = b - hb;
    asm("cvt.rn.bf16x2.f32 %0, %1, %2;" : "=r"(lo) : "f"(lb), "f"(la));
    hi = h;
}

#define SAB_B 272      // A row stride in bytes (136 bf16)
#define SBN   144      // B (transposed [k][n]) row stride in bytes (64 cols + pad)

// ===========================================================================
// Kernel 1: QKV projection. grid (16, 24, 2): rowtile, joint, col-half.
// block 256. C(128x64) = X(128x128) * W[:, c0:c0+64]. B stored [k][n] (trans).
// smem: Ah(34816) Al(34816) Bh(18432) Bl(18432) = 104 KB -> 2 CTAs/SM.
// ===========================================================================
#define QK_AHI 0
#define QK_ALO 34816
#define QK_BHI 69632
#define QK_BLO 88064
#define QK_TOTAL 106496

__global__ __launch_bounds__(256, 2)
void qkv_mma(const float* __restrict__ x,
             const float* __restrict__ qm,
             const float* __restrict__ km,
             const float* __restrict__ vm)
{
    extern __shared__ char smem[];
    const int j   = blockIdx.y;
    const int c0  = blockIdx.z * 64;     // output col-half
    const int nh0 = c0 >> 4;             // first head of this half
    const int r0  = blockIdx.x * 128;
    const int tid = threadIdx.x, wid = tid >> 5, lane = tid & 31;

    // --- Stage A (X rows r0..r0+127), hi/lo split, row-major [row][k] ---
    #pragma unroll 4
    for (int t = tid; t < 4096; t += 256) {
        int row = t >> 5, kk = (t & 31) << 2;
        const float4 xv = *(const float4*)(x + ((size_t)(r0 + row) * J_ + j) * H_ + kk);
        uint32_t h01, l01, h23, l23;
        cvt_pair(xv.x, xv.y, h01, l01);
        cvt_pair(xv.z, xv.w, h23, l23);
        *(uint2*)(smem + QK_AHI + row * SAB_B + kk * 2) = make_uint2(h01, h23);
        *(uint2*)(smem + QK_ALO + row * SAB_B + kk * 2) = make_uint2(l01, l23);
    }

    const float* mats[3] = {qm, km, vm};
    const int warpM = wid & 3, warpN = wid >> 2;

    // gemm addressing (set up once)
    const uint32_t sb = smem_u32(smem);
    const int ar = lane & 15, ac = (lane >> 4) << 3;
    const int bg = lane >> 3, blp = lane & 7;
    const int kt = ((bg & 1) << 3) + blp;    // k-row within k16 group (trans ldsm)
    const int nb = (bg >> 1) << 4;           // byte offset within 32B n-chunk
    const uint32_t aRow = (uint32_t)(warpM * 32 + ar) * SAB_B;

    for (int m = 0; m < 3; m++) {
        if (m > 0) __syncthreads();   // previous gemm done reading B
        // --- Stage B^T [k][n] for matrix m, coalesced float4 along d ---
        const float* mat = mats[m];
        #pragma unroll 4
        for (int t = tid; t < 2048; t += 256) {          // 2048 float4
            int nhl = t >> 9, f = t & 511;               // 4 heads x 512 float4
            int k = f >> 2, d0 = (f & 3) << 2;
            const float4 wv = *(const float4*)(mat +
                (((size_t)(nh0 + nhl) * J_ + j) * H_ + k) * HS_ + d0);
            uint32_t h01, l01, h23, l23;
            cvt_pair(wv.x, wv.y, h01, l01);
            cvt_pair(wv.z, wv.w, h23, l23);
            int nl2 = (nhl * 16 + d0) * 2;
            *(uint2*)(smem + QK_BHI + k * SBN + nl2) = make_uint2(h01, h23);
            *(uint2*)(smem + QK_BLO + k * SBN + nl2) = make_uint2(l01, l23);
        }
        __syncthreads();

        // --- GEMM: 3-split products, warp tile 32x32 ---
        float acc[2][4][4];
        #pragma unroll
        for (int mt = 0; mt < 2; mt++)
            #pragma unroll
            for (int nt = 0; nt < 4; nt++)
                #pragma unroll
                for (int i = 0; i < 4; i++) acc[mt][nt][i] = 0.f;

        #pragma unroll 1
        for (int sp = 0; sp < 3; sp++) {
            const uint32_t aB = sb + ((sp == 2) ? QK_ALO : QK_AHI) + aRow;
            const uint32_t bB = sb + ((sp == 1) ? QK_BLO : QK_BHI);
            #pragma unroll
            for (int k0 = 0; k0 < 8; k0++) {
                uint32_t a[2][4];
                #pragma unroll
                for (int mt = 0; mt < 2; mt++)
                    ldsm_x4(a[mt][0], a[mt][1], a[mt][2], a[mt][3],
                            aB + (uint32_t)(mt * 16) * SAB_B + (uint32_t)(k0 * 16 + ac) * 2);
                #pragma unroll
                for (int ntp = 0; ntp < 2; ntp++) {
                    uint32_t b[4];
                    ldsm_x4_t(b[0], b[1], b[2], b[3],
                              bB + (uint32_t)(k0 * 16 + kt) * SBN
                                 + (uint32_t)(warpN * 32 + ntp * 16) * 2 + nb);
                    #pragma unroll
                    for (int mt = 0; mt < 2; mt++) {
                        mma_bf16(acc[mt][ntp * 2],     a[mt], b[0], b[1]);
                        mma_bf16(acc[mt][ntp * 2 + 1], a[mt], b[2], b[3]);
                    }
                }
            }
        }

        // --- Scatter: col c -> head n=c>>4, d=c&15 ---
        float* out = (m == 0) ? g_q : (m == 1 ? g_k : g_v);
        #pragma unroll
        for (int mt = 0; mt < 2; mt++) {
            int rbase = r0 + warpM * 32 + mt * 16 + (lane >> 2);
            #pragma unroll
            for (int nt = 0; nt < 4; nt++) {
                int c = c0 + warpN * 32 + nt * 8 + ((lane & 3) << 1);
                int n = c >> 4, d = c & 15;
                #pragma unroll
                for (int h = 0; h < 2; h++) {
                    int r = rbase + h * 8;
                    int b = r >> 9, sI = r & 511;
                    *(float2*)(out + (((size_t)(b * NH_ + n) * J_ + j) * S_ + sI) * HS_ + d) =
                        make_float2(acc[mt][nt][h * 2], acc[mt][nt][h * 2 + 1]);
                }
            }
        }
    }
}

// ===========================================================================
// Kernel 2: tensor-core causal attention per (b,n,j) instance.
// block 512 (16 warps); warp -> 32-row band (SMSP-balanced permutation).
// 65 KB smem -> 3 CTAs/SM = 48 warps/SM. __expf (MUFU) only.
// ===========================================================================
#define AT_KH 0
#define AT_KL 16384
#define AT_VH 32768
#define AT_VL 49152
#define AT_TOTAL 65536

__global__ __launch_bounds__(512, 1)
void attn_mma()
{
    extern __shared__ char smem[];
    const int inst = blockIdx.x;
    const int j  = inst % J_;
    const int bn = inst / J_;
    const int n  = bn % NH_;
    const int b  = bn / NH_;
    const size_t base = (size_t)inst * S_ * HS_;

    const int tid = threadIdx.x, wid = tid >> 5, lane = tid & 31;

    // Stage K and V as hi/lo bf16, row layout [s][16] (32B rows)
    #pragma unroll 2
    for (int i = tid; i < 2048; i += 512) {
        int s = i >> 2, d0 = (i & 3) << 2;
        uint32_t h0, l0, h1, l1;
        float4 kv = *(const float4*)(g_k + base + s * 16 + d0);
        cvt_pair(kv.x, kv.y, h0, l0); cvt_pair(kv.z, kv.w, h1, l1);
        *(uint2*)(smem + AT_KH + s * 32 + d0 * 2) = make_uint2(h0, h1);
        *(uint2*)(smem + AT_KL + s * 32 + d0 * 2) = make_uint2(l0, l1);
        float4 vv = *(const float4*)(g_v + base + s * 16 + d0);
        cvt_pair(vv.x, vv.y, h0, l0); cvt_pair(vv.z, vv.w, h1, l1);
        *(uint2*)(smem + AT_VH + s * 32 + d0 * 2) = make_uint2(h0, h1);
        *(uint2*)(smem + AT_VL + s * 32 + d0 * 2) = make_uint2(l0, l1);
    }
    __syncthreads();

    // Warp -> band permutation: SMSP g gets bands {g, 7-g, 8+g, 15-g}
    const int g  = wid & 3, iq = wid >> 2;
    const int band = (iq == 0) ? g : (iq == 1) ? (7 - g) : (iq == 2) ? (8 + g) : (15 - g);
    const int R0 = band * 32;

    // Q fragments (a-frag layout) loaded directly from global, split hi/lo
    uint32_t qh[2][4], ql[2][4];
    {
        int r = R0 + (lane >> 2);
        int c = (lane & 3) << 1;
        #pragma unroll
        for (int mt = 0; mt < 2; mt++) {
            const float* qp = g_q + base + (size_t)(r + mt * 16) * HS_;
            float2 v00 = *(const float2*)(qp + c);
            float2 v01 = *(const float2*)(qp + c + 8);
            float2 v10 = *(const float2*)(qp + 8 * HS_ + c);
            float2 v11 = *(const float2*)(qp + 8 * HS_ + c + 8);
            cvt_pair(v00.x, v00.y, qh[mt][0], ql[mt][0]);
            cvt_pair(v10.x, v10.y, qh[mt][1], ql[mt][1]);
            cvt_pair(v01.x, v01.y, qh[mt][2], ql[mt][2]);
            cvt_pair(v11.x, v11.y, qh[mt][3], ql[mt][3]);
        }
    }

    float O[2][2][4];
    #pragma unroll
    for (int mt = 0; mt < 2; mt++)
        #pragma unroll
        for (int dt = 0; dt < 2; dt++)
            #pragma unroll
            for (int i = 0; i < 4; i++) O[mt][dt][i] = 0.f;
    float rs[2][2] = {{0.f, 0.f}, {0.f, 0.f}};

    const uint32_t Kh = smem_u32(smem) + AT_KH;
    const uint32_t Kl = smem_u32(smem) + AT_KL;
    const uint32_t Vh = smem_u32(smem) + AT_VH;
    const uint32_t Vl = smem_u32(smem) + AT_VL;

    const int bg = lane >> 3, bl = lane & 7;
    const int kn = ((bg >> 1) << 3) + bl;   // K non-trans addressing
    const int kk = (bg & 1) << 3;
    const int vt = ((bg & 1) << 3) + bl;    // V trans addressing
    const int vd = (bg >> 1) << 4;

    const int ntp_max = 2 * band + 1;
    for (int ntp = 0; ntp <= ntp_max; ntp++) {
        const int C0 = ntp << 4;
        uint32_t kh[4], klr[4], vh[4], vlr[4];
        ldsm_x4(kh[0], kh[1], kh[2], kh[3],     Kh + (uint32_t)(C0 + kn) * 32 + kk * 2);
        ldsm_x4(klr[0], klr[1], klr[2], klr[3], Kl + (uint32_t)(C0 + kn) * 32 + kk * 2);
        ldsm_x4_t(vh[0], vh[1], vh[2], vh[3],   Vh + (uint32_t)(C0 + vt) * 32 + vd);
        ldsm_x4_t(vlr[0], vlr[1], vlr[2], vlr[3], Vl + (uint32_t)(C0 + vt) * 32 + vd);

        const bool diag = (ntp >= 2 * band);
        const int mt0 = (ntp == ntp_max) ? 1 : 0;   // skip fully-masked block

        for (int mt = mt0; mt < 2; mt++) {
            float S0[4] = {0.f, 0.f, 0.f, 0.f};
            float S1[4] = {0.f, 0.f, 0.f, 0.f};
            mma_bf16(S0, qh[mt], kh[0], kh[1]);
            mma_bf16(S0, ql[mt], kh[0], kh[1]);
            mma_bf16(S0, qh[mt], klr[0], klr[1]);
            mma_bf16(S1, qh[mt], kh[2], kh[3]);
            mma_bf16(S1, ql[mt], kh[2], kh[3]);
            mma_bf16(S1, qh[mt], klr[2], klr[3]);

            const int row0 = R0 + mt * 16 + (lane >> 2);
            const int col0 = C0 + ((lane & 3) << 1);
            float p[8];
            if (diag) {
                p[0] = (col0     <= row0    ) ? __expf(S0[0] * 0.25f) : 0.f;
                p[1] = (col0 + 1 <= row0    ) ? __expf(S0[1] * 0.25f) : 0.f;
                p[2] = (col0     <= row0 + 8) ? __expf(S0[2] * 0.25f) : 0.f;
                p[3] = (col0 + 1 <= row0 + 8) ? __expf(S0[3] * 0.25f) : 0.f;
                p[4] = (col0 + 8 <= row0    ) ? __expf(S1[0] * 0.25f) : 0.f;
                p[5] = (col0 + 9 <= row0    ) ? __expf(S1[1] * 0.25f) : 0.f;
                p[6] = (col0 + 8 <= row0 + 8) ? __expf(S1[2] * 0.25f) : 0.f;
                p[7] = (col0 + 9 <= row0 + 8) ? __expf(S1[3] * 0.25f) : 0.f;
            } else {
                p[0] = __expf(S0[0] * 0.25f);
                p[1] = __expf(S0[1] * 0.25f);
                p[2] = __expf(S0[2] * 0.25f);
                p[3] = __expf(S0[3] * 0.25f);
                p[4] = __expf(S1[0] * 0.25f);
                p[5] = __expf(S1[1] * 0.25f);
                p[6] = __expf(S1[2] * 0.25f);
                p[7] = __expf(S1[3] * 0.25f);
            }
            rs[mt][0] += (p[0] + p[1]) + (p[4] + p[5]);
            rs[mt][1] += (p[2] + p[3]) + (p[6] + p[7]);

            uint32_t ph[4], pl[4];
            cvt_pair(p[0], p[1], ph[0], pl[0]);
            cvt_pair(p[2], p[3], ph[1], pl[1]);
            cvt_pair(p[4], p[5], ph[2], pl[2]);
            cvt_pair(p[6], p[7], ph[3], pl[3]);

            mma_bf16(O[mt][0], ph, vh[0], vh[1]);
            mma_bf16(O[mt][0], pl, vh[0], vh[1]);
            mma_bf16(O[mt][0], ph, vlr[0], vlr[1]);
            mma_bf16(O[mt][1], ph, vh[2], vh[3]);
            mma_bf16(O[mt][1], pl, vh[2], vh[3]);
            mma_bf16(O[mt][1], ph, vlr[2], vlr[3]);
        }
    }

    // Row sums: reduce across the 4 lanes of each row group, normalize, store.
    #pragma unroll
    for (int mt = 0; mt < 2; mt++) {
        float s0 = rs[mt][0], s1 = rs[mt][1];
        s0 += __shfl_xor_sync(0xffffffffu, s0, 1);
        s0 += __shfl_xor_sync(0xffffffffu, s0, 2);
        s1 += __shfl_xor_sync(0xffffffffu, s1, 1);
        s1 += __shfl_xor_sync(0xffffffffu, s1, 2);
        const float i0 = 1.f / s0, i1 = 1.f / s1;
        const int row = R0 + mt * 16 + (lane >> 2);
        const int dc  = (lane & 3) << 1;
        #pragma unroll
        for (int dt = 0; dt < 2; dt++) {
            const int d = dt * 8 + dc;
            float* o0 = g_ao + ((size_t)(b * S_ + row)     * J_ + j) * H_ + n * HS_ + d;
            float* o1 = g_ao + ((size_t)(b * S_ + row + 8) * J_ + j) * H_ + n * HS_ + d;
            *(float2*)o0 = make_float2(O[mt][dt][0] * i0, O[mt][dt][1] * i0);
            *(float2*)o1 = make_float2(O[mt][dt][2] * i1, O[mt][dt][3] * i1);
        }
    }
}

// ===========================================================================
// Kernel 3: output projection + residual + LayerNorm.
// grid (32, 24): 64-row tiles. B in two 64-col halves sequentially.
// smem 70 KB -> 3 CTAs/SM.
// ===========================================================================
#define P_AHI 0
#define P_ALO 17408
#define P_BHI 34816
#define P_BLO 53248
#define P_TOTAL 71680

__global__ __launch_bounds__(256, 3)
void proj_mma(const float* __restrict__ x,
              const float* __restrict__ proj,
              const float* __restrict__ gamma,
              const float* __restrict__ beta,
              float* __restrict__ out)
{
    extern __shared__ char smem[];
    const int j   = blockIdx.y;
    const int r0  = blockIdx.x * 64;
    const int tid = threadIdx.x, wid = tid >> 5, lane = tid & 31;

    // --- Stage A (attention-out rows r0..r0+63) ---
    #pragma unroll 4
    for (int t = tid; t < 2048; t += 256) {
        int row = t >> 5, kk = (t & 31) << 2;
        const float4 xv = *(const float4*)(g_ao + ((size_t)(r0 + row) * J_ + j) * H_ + kk);
        uint32_t h01, l01, h23, l23;
        cvt_pair(xv.x, xv.y, h01, l01);
        cvt_pair(xv.z, xv.w, h23, l23);
        *(uint2*)(smem + P_AHI + row * SAB_B + kk * 2) = make_uint2(h01, h23);
        *(uint2*)(smem + P_ALO + row * SAB_B + kk * 2) = make_uint2(l01, l23);
    }

    const int warpM = wid & 3, warpN = wid >> 2;
    const uint32_t sb = smem_u32(smem);
    const int ar = lane & 15, ac = (lane >> 4) << 3;
    const int bg = lane >> 3, blp = lane & 7;
    const int kt = ((bg & 1) << 3) + blp;
    const int nb = (bg >> 1) << 4;
    const uint32_t aRow = (uint32_t)(warpM * 16 + ar) * SAB_B;

    float acc[2][4][4];   // [pass][ntile][frag]
    #pragma unroll
    for (int p = 0; p < 2; p++)
        #pragma unroll
        for (int nt = 0; nt < 4; nt++)
            #pragma unroll
            for (int i = 0; i < 4; i++) acc[p][nt][i] = 0.f;

    #pragma unroll 1
    for (int p = 0; p < 2; p++) {
        if (p > 0) __syncthreads();      // previous gemm done reading B
        const int c0 = p * 64;
        // Stage B^T [h][kout] cols c0..c0+63 (proj is contiguous along kout)
        #pragma unroll 4
        for (int t = tid; t < 2048; t += 256) {
            int k = t >> 4, n0 = (t & 15) << 2;
            const float4 wv = *(const float4*)(proj + (size_t)j * H_ * H_ + k * H_ + c0 + n0);
            uint32_t h01, l01, h23, l23;
            cvt_pair(wv.x, wv.y, h01, l01);
            cvt_pair(wv.z, wv.w, h23, l23);
            *(uint2*)(smem + P_BHI + k * SBN + n0 * 2) = make_uint2(h01, h23);
            *(uint2*)(smem + P_BLO + k * SBN + n0 * 2) = make_uint2(l01, l23);
        }
        __syncthreads();

        #pragma unroll 1
        for (int sp = 0; sp < 3; sp++) {
            const uint32_t aB = sb + ((sp == 2) ? P_ALO : P_AHI) + aRow;
            const uint32_t bB = sb + ((sp == 1) ? P_BLO : P_BHI);
            #pragma unroll
            for (int k0 = 0; k0 < 8; k0++) {
                uint32_t a[4];
                ldsm_x4(a[0], a[1], a[2], a[3], aB + (uint32_t)(k0 * 16 + ac) * 2);
                #pragma unroll
                for (int ntp = 0; ntp < 2; ntp++) {
                    uint32_t bfr[4];
                    ldsm_x4_t(bfr[0], bfr[1], bfr[2], bfr[3],
                              bB + (uint32_t)(k0 * 16 + kt) * SBN
                                 + (uint32_t)(warpN * 32 + ntp * 16) * 2 + nb);
                    mma_bf16(acc[p][ntp * 2],     a, bfr[0], bfr[1]);
                    mma_bf16(acc[p][ntp * 2 + 1], a, bfr[2], bfr[3]);
                }
            }
        }
    }

    // Stage C into smem (aliases A region): [64][132] floats
    __syncthreads();
    float* Cs = (float*)smem;
    #pragma unroll
    for (int p = 0; p < 2; p++) {
        int rb = warpM * 16 + (lane >> 2);
        #pragma unroll
        for (int nt = 0; nt < 4; nt++) {
            int col = p * 64 + warpN * 32 + nt * 8 + ((lane & 3) << 1);
            #pragma unroll
            for (int h = 0; h < 2; h++) {
                Cs[(rb + h * 8) * 132 + col]     = acc[p][nt][h * 2];
                Cs[(rb + h * 8) * 132 + col + 1] = acc[p][nt][h * 2 + 1];
            }
        }
    }
    __syncthreads();

    // Residual + LN: 4 threads per row (32 cols each), combine via shfl.
    {
        const int row = tid >> 2;
        const int q   = tid & 3;
        const int r   = r0 + row;
        const float* xr = x + ((size_t)r * J_ + j) * H_ + q * 32;
        float* crow     = Cs + row * 132 + q * 32;

        float sum = 0.f, sq = 0.f;
        #pragma unroll
        for (int i = 0; i < 8; i++) {
            float4 c4 = *(float4*)(crow + i * 4);
            float4 xv = *(const float4*)(xr + i * 4);
            c4.x += xv.x; c4.y += xv.y; c4.z += xv.z; c4.w += xv.w;
            *(float4*)(crow + i * 4) = c4;
            sum += c4.x + c4.y + c4.z + c4.w;
            sq  += c4.x*c4.x + c4.y*c4.y + c4.z*c4.z + c4.w*c4.w;
        }
        sum += __shfl_xor_sync(0xffffffffu, sum, 1);
        sum += __shfl_xor_sync(0xffffffffu, sum, 2);
        sq  += __shfl_xor_sync(0xffffffffu, sq, 1);
        sq  += __shfl_xor_sync(0xffffffffu, sq, 2);
        const float mu   = sum * (1.f / 128.f);
        const float var  = sq * (1.f / 128.f) - mu * mu;
        const float rstd = rsqrtf(var + 1e-5f);

        float* orow = out + ((size_t)r * J_ + j) * H_ + q * 32;
        const float* gp  = gamma + q * 32;
        const float* bp2 = beta  + q * 32;
        #pragma unroll
        for (int i = 0; i < 8; i++) {
            float4 c4 = *(float4*)(crow + i * 4);
            float4 o;
            o.x = (c4.x - mu) * rstd * gp[i*4+0] + bp2[i*4+0];
            o.y = (c4.y - mu) * rstd * gp[i*4+1] + bp2[i*4+1];
            o.z = (c4.z - mu) * rstd * gp[i*4+2] + bp2[i*4+2];
            o.w = (c4.w - mu) * rstd * gp[i*4+3] + bp2[i*4+3];
            *(float4*)(orow + i * 4) = o;
        }
    }
}

// ===========================================================================
extern "C" void kernel_launch(void* const* d_in, const int* in_sizes, int n_in,
                              void* d_out, int out_size)
{
    const float* x     = (const float*)d_in[0];
    // d_in[1]: additive causal mask (= triu(-1e9)) — implemented as causal skip.
    const float* qm    = (const float*)d_in[2];
    const float* km    = (const float*)d_in[3];
    const float* vm    = (const float*)d_in[4];
    const float* proj  = (const float*)d_in[5];
    const float* gamma = (const float*)d_in[6];
    const float* beta  = (const float*)d_in[7];
    float* out = (float*)d_out;

    cudaFuncSetAttribute(qkv_mma,  cudaFuncAttributeMaxDynamicSharedMemorySize, QK_TOTAL);
    cudaFuncSetAttribute(attn_mma, cudaFuncAttributeMaxDynamicSharedMemorySize, AT_TOTAL);
    cudaFuncSetAttribute(proj_mma, cudaFuncAttributeMaxDynamicSharedMemorySize, P_TOTAL);

    qkv_mma<<<dim3(BS_/128, J_, 2), 256, QK_TOTAL>>>(x, qm, km, vm);
    attn_mma<<<INST_, 512, AT_TOTAL>>>();
    proj_mma<<<dim3(BS_/64, J_), 256, P_TOTAL>>>(x, proj, gamma, beta, out);
}

// round 9
// speedup vs baseline: 1.7691x; 1.1721x over previous
#include <cuda_runtime.h>
#include <cuda_bf16.h>
#include <stdint.h>

// Problem constants
#define B_  4
#define S_  512
#define J_  24
#define H_  128
#define NH_ 8
#define HS_ 16
#define BS_ (B_*S_)            // 2048 rows
#define INST_ (B_*NH_*J_)      // 768 attention instances

// Scratch (static device globals — allocation-free)
__device__ float g_q [B_*NH_*J_*S_*HS_];   // (b,n,j,s,d)
__device__ float g_k [B_*NH_*J_*S_*HS_];
__device__ float g_v [B_*NH_*J_*S_*HS_];
__device__ float g_ao[B_*S_*J_*H_];        // attention out, (b,s,j,h) h=n*16+d

// ===========================================================================
// Warp-MMA helpers (baseline PTX features only)
// ===========================================================================
__device__ __forceinline__ uint32_t smem_u32(const void* p) {
    uint32_t a;
    asm("{ .reg .u64 t; cvta.to.shared.u64 t, %1; cvt.u32.u64 %0, t; }"
        : "=r"(a) : "l"(p));
    return a;
}

__device__ __forceinline__ void ldsm_x4(uint32_t& r0, uint32_t& r1,
                                        uint32_t& r2, uint32_t& r3, uint32_t addr) {
    asm volatile("ldmatrix.sync.aligned.m8n8.x4.shared.b16 {%0,%1,%2,%3}, [%4];"
                 : "=r"(r0), "=r"(r1), "=r"(r2), "=r"(r3) : "r"(addr));
}
__device__ __forceinline__ void ldsm_x4_t(uint32_t& r0, uint32_t& r1,
                                          uint32_t& r2, uint32_t& r3, uint32_t addr) {
    asm volatile("ldmatrix.sync.aligned.m8n8.x4.trans.shared.b16 {%0,%1,%2,%3}, [%4];"
                 : "=r"(r0), "=r"(r1), "=r"(r2), "=r"(r3) : "r"(addr));
}

__device__ __forceinline__ void mma_bf16(float* c, const uint32_t a[4],
                                         uint32_t b0, uint32_t b1) {
    asm volatile(
        "mma.sync.aligned.m16n8k16.row.col.f32.bf16.bf16.f32 "
        "{%0,%1,%2,%3}, {%4,%5,%6,%7}, {%8,%9}, {%0,%1,%2,%3};"
        : "+f"(c[0]), "+f"(c[1]), "+f"(c[2]), "+f"(c[3])
        : "r"(a[0]), "r"(a[1]), "r"(a[2]), "r"(a[3]), "r"(b0), "r"(b1));
}

// split-fp32 -> (hi bf16x2, lo bf16x2); a -> low half, b -> high half
__device__ __forceinline__ void cvt_pair(float a, float b, uint32_t& hi, uint32_t& lo) {
    uint32_t h;
    asm("cvt.rn.bf16x2.f32 %0, %1, %2;" : "=r"(h) : "f"(b), "f"(a));
    float ha = __uint_as_float(h << 16);
    float hb = __uint_as_float(h & 0xffff0000u);
    float la = a - ha, lb = b - hb;
    asm("cvt.rn.bf16x2.f32 %0, %1, %2;" : "=r"(lo) : "f"(lb), "f"(la));
    hi = h;
}

#define SAB_B 272      // A row stride in bytes (136 bf16)
#define SBN   144      // B (transposed [k][n]) row stride in bytes (64 cols + pad)

// ===========================================================================
// Kernel 1: QKV projection. grid (16, 24, 2): rowtile, joint, col-half.
// block 256. C(128x64) = X(128x128) * W[:, c0:c0+64]. B stored [k][n] (trans).
// smem 104 KB -> 2 CTAs/SM.   (unchanged — measured 74.5 us)
// ===========================================================================
#define QK_AHI 0
#define QK_ALO 34816
#define QK_BHI 69632
#define QK_BLO 88064
#define QK_TOTAL 106496

__global__ __launch_bounds__(256, 2)
void qkv_mma(const float* __restrict__ x,
             const float* __restrict__ qm,
             const float* __restrict__ km,
             const float* __restrict__ vm)
{
    extern __shared__ char smem[];
    const int j   = blockIdx.y;
    const int c0  = blockIdx.z * 64;     // output col-half
    const int nh0 = c0 >> 4;             // first head of this half
    const int r0  = blockIdx.x * 128;
    const int tid = threadIdx.x, wid = tid >> 5, lane = tid & 31;

    // --- Stage A (X rows r0..r0+127), hi/lo split, row-major [row][k] ---
    #pragma unroll 4
    for (int t = tid; t < 4096; t += 256) {
        int row = t >> 5, kk = (t & 31) << 2;
        const float4 xv = *(const float4*)(x + ((size_t)(r0 + row) * J_ + j) * H_ + kk);
        uint32_t h01, l01, h23, l23;
        cvt_pair(xv.x, xv.y, h01, l01);
        cvt_pair(xv.z, xv.w, h23, l23);
        *(uint2*)(smem + QK_AHI + row * SAB_B + kk * 2) = make_uint2(h01, h23);
        *(uint2*)(smem + QK_ALO + row * SAB_B + kk * 2) = make_uint2(l01, l23);
    }

    const float* mats[3] = {qm, km, vm};
    const int warpM = wid & 3, warpN = wid >> 2;

    const uint32_t sb = smem_u32(smem);
    const int ar = lane & 15, ac = (lane >> 4) << 3;
    const int bg = lane >> 3, blp = lane & 7;
    const int kt = ((bg & 1) << 3) + blp;    // k-row within k16 group (trans ldsm)
    const int nb = (bg >> 1) << 4;           // byte offset within 32B n-chunk
    const uint32_t aRow = (uint32_t)(warpM * 32 + ar) * SAB_B;

    for (int m = 0; m < 3; m++) {
        if (m > 0) __syncthreads();   // previous gemm done reading B
        const float* mat = mats[m];
        #pragma unroll 4
        for (int t = tid; t < 2048; t += 256) {          // 2048 float4
            int nhl = t >> 9, f = t & 511;               // 4 heads x 512 float4
            int k = f >> 2, d0 = (f & 3) << 2;
            const float4 wv = *(const float4*)(mat +
                (((size_t)(nh0 + nhl) * J_ + j) * H_ + k) * HS_ + d0);
            uint32_t h01, l01, h23, l23;
            cvt_pair(wv.x, wv.y, h01, l01);
            cvt_pair(wv.z, wv.w, h23, l23);
            int nl2 = (nhl * 16 + d0) * 2;
            *(uint2*)(smem + QK_BHI + k * SBN + nl2) = make_uint2(h01, h23);
            *(uint2*)(smem + QK_BLO + k * SBN + nl2) = make_uint2(l01, l23);
        }
        __syncthreads();

        float acc[2][4][4];
        #pragma unroll
        for (int mt = 0; mt < 2; mt++)
            #pragma unroll
            for (int nt = 0; nt < 4; nt++)
                #pragma unroll
                for (int i = 0; i < 4; i++) acc[mt][nt][i] = 0.f;

        #pragma unroll 1
        for (int sp = 0; sp < 3; sp++) {
            const uint32_t aB = sb + ((sp == 2) ? QK_ALO : QK_AHI) + aRow;
            const uint32_t bB = sb + ((sp == 1) ? QK_BLO : QK_BHI);
            #pragma unroll
            for (int k0 = 0; k0 < 8; k0++) {
                uint32_t a[2][4];
                #pragma unroll
                for (int mt = 0; mt < 2; mt++)
                    ldsm_x4(a[mt][0], a[mt][1], a[mt][2], a[mt][3],
                            aB + (uint32_t)(mt * 16) * SAB_B + (uint32_t)(k0 * 16 + ac) * 2);
                #pragma unroll
                for (int ntp = 0; ntp < 2; ntp++) {
                    uint32_t b[4];
                    ldsm_x4_t(b[0], b[1], b[2], b[3],
                              bB + (uint32_t)(k0 * 16 + kt) * SBN
                                 + (uint32_t)(warpN * 32 + ntp * 16) * 2 + nb);
                    #pragma unroll
                    for (int mt = 0; mt < 2; mt++) {
                        mma_bf16(acc[mt][ntp * 2],     a[mt], b[0], b[1]);
                        mma_bf16(acc[mt][ntp * 2 + 1], a[mt], b[2], b[3]);
                    }
                }
            }
        }

        float* out = (m == 0) ? g_q : (m == 1 ? g_k : g_v);
        #pragma unroll
        for (int mt = 0; mt < 2; mt++) {
            int rbase = r0 + warpM * 32 + mt * 16 + (lane >> 2);
            #pragma unroll
            for (int nt = 0; nt < 4; nt++) {
                int c = c0 + warpN * 32 + nt * 8 + ((lane & 3) << 1);
                int n = c >> 4, d = c & 15;
                #pragma unroll
                for (int h = 0; h < 2; h++) {
                    int r = rbase + h * 8;
                    int b = r >> 9, sI = r & 511;
                    *(float2*)(out + (((size_t)(b * NH_ + n) * J_ + j) * S_ + sI) * HS_ + d) =
                        make_float2(acc[mt][nt][h * 2], acc[mt][nt][h * 2 + 1]);
                }
            }
        }
    }
}

// ===========================================================================
// Kernel 2: tensor-core causal attention per (b,n,j) instance.
// block 512 (16 warps); warp -> 32-row band (SMSP-balanced permutation).
// XOR-swizzled smem rows (injective, conflict-free ldmatrix) +
// fully-unrolled mt (main loop ntp 0..2b both mt; epilogue tile mt=1 only).
// ===========================================================================
// XOR swizzle: row r keeps its private 32B slot; the two 16B halves are
// conditionally swapped by bit ((r>>2)&1). off = byte offset within row [0,32).
#define KSWZ(r, off) ((((uint32_t)(r)) << 5) + \
                      (((uint32_t)(off)) ^ ((((uint32_t)(r) >> 2) & 1u) << 4)))
#define AT_KH 0
#define AT_KL 16384
#define AT_VH 32768
#define AT_VL 49152
#define AT_TOTAL 65536

__global__ __launch_bounds__(512, 1)
void attn_mma()
{
    extern __shared__ char smem[];
    const int inst = blockIdx.x;
    const int j  = inst % J_;
    const int bn = inst / J_;
    const int n  = bn % NH_;
    const int b  = bn / NH_;
    const size_t base = (size_t)inst * S_ * HS_;

    const int tid = threadIdx.x, wid = tid >> 5, lane = tid & 31;

    // Stage K and V as hi/lo bf16, swizzled rows (16 bf16 = 32B per row)
    #pragma unroll 2
    for (int i = tid; i < 2048; i += 512) {
        int s = i >> 2, d0 = (i & 3) << 2;
        uint32_t off = KSWZ(s, d0 * 2);
        uint32_t h0, l0, h1, l1;
        float4 kv = *(const float4*)(g_k + base + s * 16 + d0);
        cvt_pair(kv.x, kv.y, h0, l0); cvt_pair(kv.z, kv.w, h1, l1);
        *(uint2*)(smem + AT_KH + off) = make_uint2(h0, h1);
        *(uint2*)(smem + AT_KL + off) = make_uint2(l0, l1);
        float4 vv = *(const float4*)(g_v + base + s * 16 + d0);
        cvt_pair(vv.x, vv.y, h0, l0); cvt_pair(vv.z, vv.w, h1, l1);
        *(uint2*)(smem + AT_VH + off) = make_uint2(h0, h1);
        *(uint2*)(smem + AT_VL + off) = make_uint2(l0, l1);
    }
    __syncthreads();

    // Warp -> band permutation: SMSP g gets bands {g, 7-g, 8+g, 15-g}
    const int g  = wid & 3, iq = wid >> 2;
    const int band = (iq == 0) ? g : (iq == 1) ? (7 - g) : (iq == 2) ? (8 + g) : (15 - g);
    const int R0 = band * 32;

    // Q fragments (a-frag layout) loaded directly from global, split hi/lo
    uint32_t qh[2][4], ql[2][4];
    {
        int r = R0 + (lane >> 2);
        int c = (lane & 3) << 1;
        #pragma unroll
        for (int mt = 0; mt < 2; mt++) {
            const float* qp = g_q + base + (size_t)(r + mt * 16) * HS_;
            float2 v00 = *(const float2*)(qp + c);
            float2 v01 = *(const float2*)(qp + c + 8);
            float2 v10 = *(const float2*)(qp + 8 * HS_ + c);
            float2 v11 = *(const float2*)(qp + 8 * HS_ + c + 8);
            cvt_pair(v00.x, v00.y, qh[mt][0], ql[mt][0]);
            cvt_pair(v10.x, v10.y, qh[mt][1], ql[mt][1]);
            cvt_pair(v01.x, v01.y, qh[mt][2], ql[mt][2]);
            cvt_pair(v11.x, v11.y, qh[mt][3], ql[mt][3]);
        }
    }

    float O[2][2][4];
    #pragma unroll
    for (int mt = 0; mt < 2; mt++)
        #pragma unroll
        for (int dt = 0; dt < 2; dt++)
            #pragma unroll
            for (int i = 0; i < 4; i++) O[mt][dt][i] = 0.f;
    float rs[2][2] = {{0.f, 0.f}, {0.f, 0.f}};

    const uint32_t Kh = smem_u32(smem) + AT_KH;
    const uint32_t Kl = smem_u32(smem) + AT_KL;
    const uint32_t Vh = smem_u32(smem) + AT_VH;
    const uint32_t Vl = smem_u32(smem) + AT_VL;

    const int bg = lane >> 3, bl = lane & 7;
    const int kn = ((bg >> 1) << 3) + bl;   // K non-trans addressing
    const int kk = (bg & 1) << 3;           // bf16 offset within row (0 or 8)
    const int vt = ((bg & 1) << 3) + bl;    // V trans addressing
    const int vd = (bg >> 1) << 4;          // byte offset within row (0 or 16)

    const int last = 2 * band;              // main-loop upper bound (inclusive)
    const int qrow = lane >> 2, qcol = (lane & 3) << 1;

    for (int ntp = 0; ntp <= last; ntp++) {
        const int C0 = ntp << 4;
        uint32_t kh[4], klr[4], vh[4], vlr[4];
        ldsm_x4(kh[0], kh[1], kh[2], kh[3],     Kh + KSWZ(C0 + kn, kk * 2));
        ldsm_x4(klr[0], klr[1], klr[2], klr[3], Kl + KSWZ(C0 + kn, kk * 2));
        ldsm_x4_t(vh[0], vh[1], vh[2], vh[3],   Vh + KSWZ(C0 + vt, vd));
        ldsm_x4_t(vlr[0], vlr[1], vlr[2], vlr[3], Vl + KSWZ(C0 + vt, vd));

        // Scores for both m-tiles (4 independent accumulation chains)
        float S[2][2][4];
        #pragma unroll
        for (int mt = 0; mt < 2; mt++)
            #pragma unroll
            for (int q2 = 0; q2 < 2; q2++)
                #pragma unroll
                for (int i = 0; i < 4; i++) S[mt][q2][i] = 0.f;
        #pragma unroll
        for (int mt = 0; mt < 2; mt++) {
            mma_bf16(S[mt][0], qh[mt], kh[0], kh[1]);
            mma_bf16(S[mt][1], qh[mt], kh[2], kh[3]);
            mma_bf16(S[mt][0], ql[mt], kh[0], kh[1]);
            mma_bf16(S[mt][1], ql[mt], kh[2], kh[3]);
            mma_bf16(S[mt][0], qh[mt], klr[0], klr[1]);
            mma_bf16(S[mt][1], qh[mt], klr[2], klr[3]);
        }

        // Softmax numerators. Only (mt=0, ntp==last) is a diagonal tile;
        // mt=1 at ntp==last is provably full (col_max = 32b+15 < 32b+16 = row_min).
        #pragma unroll
        for (int mt = 0; mt < 2; mt++) {
            float p[8];
            if (mt == 0 && ntp == last) {
                const int row0 = R0 + qrow;
                const int col0 = C0 + qcol;
                p[0] = (col0     <= row0    ) ? __expf(S[0][0][0] * 0.25f) : 0.f;
                p[1] = (col0 + 1 <= row0    ) ? __expf(S[0][0][1] * 0.25f) : 0.f;
                p[2] = (col0     <= row0 + 8) ? __expf(S[0][0][2] * 0.25f) : 0.f;
                p[3] = (col0 + 1 <= row0 + 8) ? __expf(S[0][0][3] * 0.25f) : 0.f;
                p[4] = (col0 + 8 <= row0    ) ? __expf(S[0][1][0] * 0.25f) : 0.f;
                p[5] = (col0 + 9 <= row0    ) ? __expf(S[0][1][1] * 0.25f) : 0.f;
                p[6] = (col0 + 8 <= row0 + 8) ? __expf(S[0][1][2] * 0.25f) : 0.f;
                p[7] = (col0 + 9 <= row0 + 8) ? __expf(S[0][1][3] * 0.25f) : 0.f;
            } else {
                p[0] = __expf(S[mt][0][0] * 0.25f);
                p[1] = __expf(S[mt][0][1] * 0.25f);
                p[2] = __expf(S[mt][0][2] * 0.25f);
                p[3] = __expf(S[mt][0][3] * 0.25f);
                p[4] = __expf(S[mt][1][0] * 0.25f);
                p[5] = __expf(S[mt][1][1] * 0.25f);
                p[6] = __expf(S[mt][1][2] * 0.25f);
                p[7] = __expf(S[mt][1][3] * 0.25f);
            }
            rs[mt][0] += (p[0] + p[1]) + (p[4] + p[5]);
            rs[mt][1] += (p[2] + p[3]) + (p[6] + p[7]);

            uint32_t ph[4], pl[4];
            cvt_pair(p[0], p[1], ph[0], pl[0]);
            cvt_pair(p[2], p[3], ph[1], pl[1]);
            cvt_pair(p[4], p[5], ph[2], pl[2]);
            cvt_pair(p[6], p[7], ph[3], pl[3]);

            mma_bf16(O[mt][0], ph, vh[0], vh[1]);
            mma_bf16(O[mt][1], ph, vh[2], vh[3]);
            mma_bf16(O[mt][0], pl, vh[0], vh[1]);
            mma_bf16(O[mt][1], pl, vh[2], vh[3]);
            mma_bf16(O[mt][0], ph, vlr[0], vlr[1]);
            mma_bf16(O[mt][1], ph, vlr[2], vlr[3]);
        }
    }

    // Epilogue tile: ntp = last+1, mt = 1 only (diagonal)
    {
        const int C0 = (last + 1) << 4;
        uint32_t kh[4], klr[4], vh[4], vlr[4];
        ldsm_x4(kh[0], kh[1], kh[2], kh[3],     Kh + KSWZ(C0 + kn, kk * 2));
        ldsm_x4(klr[0], klr[1], klr[2], klr[3], Kl + KSWZ(C0 + kn, kk * 2));
        ldsm_x4_t(vh[0], vh[1], vh[2], vh[3],   Vh + KSWZ(C0 + vt, vd));
        ldsm_x4_t(vlr[0], vlr[1], vlr[2], vlr[3], Vl + KSWZ(C0 + vt, vd));

        float S0[4] = {0.f,0.f,0.f,0.f}, S1[4] = {0.f,0.f,0.f,0.f};
        mma_bf16(S0, qh[1], kh[0], kh[1]);
        mma_bf16(S1, qh[1], kh[2], kh[3]);
        mma_bf16(S0, ql[1], kh[0], kh[1]);
        mma_bf16(S1, ql[1], kh[2], kh[3]);
        mma_bf16(S0, qh[1], klr[0], klr[1]);
        mma_bf16(S1, qh[1], klr[2], klr[3]);

        const int row0 = R0 + 16 + qrow;
        const int col0 = C0 + qcol;
        float p[8];
        p[0] = (col0     <= row0    ) ? __expf(S0[0] * 0.25f) : 0.f;
        p[1] = (col0 + 1 <= row0    ) ? __expf(S0[1] * 0.25f) : 0.f;
        p[2] = (col0     <= row0 + 8) ? __expf(S0[2] * 0.25f) : 0.f;
        p[3] = (col0 + 1 <= row0 + 8) ? __expf(S0[3] * 0.25f) : 0.f;
        p[4] = (col0 + 8 <= row0    ) ? __expf(S1[0] * 0.25f) : 0.f;
        p[5] = (col0 + 9 <= row0    ) ? __expf(S1[1] * 0.25f) : 0.f;
        p[6] = (col0 + 8 <= row0 + 8) ? __expf(S1[2] * 0.25f) : 0.f;
        p[7] = (col0 + 9 <= row0 + 8) ? __expf(S1[3] * 0.25f) : 0.f;
        rs[1][0] += (p[0] + p[1]) + (p[4] + p[5]);
        rs[1][1] += (p[2] + p[3]) + (p[6] + p[7]);

        uint32_t ph[4], pl[4];
        cvt_pair(p[0], p[1], ph[0], pl[0]);
        cvt_pair(p[2], p[3], ph[1], pl[1]);
        cvt_pair(p[4], p[5], ph[2], pl[2]);
        cvt_pair(p[6], p[7], ph[3], pl[3]);

        mma_bf16(O[1][0], ph, vh[0], vh[1]);
        mma_bf16(O[1][1], ph, vh[2], vh[3]);
        mma_bf16(O[1][0], pl, vh[0], vh[1]);
        mma_bf16(O[1][1], pl, vh[2], vh[3]);
        mma_bf16(O[1][0], ph, vlr[0], vlr[1]);
        mma_bf16(O[1][1], ph, vlr[2], vlr[3]);
    }

    // Row sums: reduce across the 4 lanes of each row group, normalize, store.
    #pragma unroll
    for (int mt = 0; mt < 2; mt++) {
        float s0 = rs[mt][0], s1 = rs[mt][1];
        s0 += __shfl_xor_sync(0xffffffffu, s0, 1);
        s0 += __shfl_xor_sync(0xffffffffu, s0, 2);
        s1 += __shfl_xor_sync(0xffffffffu, s1, 1);
        s1 += __shfl_xor_sync(0xffffffffu, s1, 2);
        const float i0 = 1.f / s0, i1 = 1.f / s1;
        const int row = R0 + mt * 16 + (lane >> 2);
        const int dc  = (lane & 3) << 1;
        #pragma unroll
        for (int dt = 0; dt < 2; dt++) {
            const int d = dt * 8 + dc;
            float* o0 = g_ao + ((size_t)(b * S_ + row)     * J_ + j) * H_ + n * HS_ + d;
            float* o1 = g_ao + ((size_t)(b * S_ + row + 8) * J_ + j) * H_ + n * HS_ + d;
            *(float2*)o0 = make_float2(O[mt][dt][0] * i0, O[mt][dt][1] * i0);
            *(float2*)o1 = make_float2(O[mt][dt][2] * i1, O[mt][dt][3] * i1);
        }
    }
}

// ===========================================================================
// Kernel 3: output projection + residual + LayerNorm.  (unchanged)
// ===========================================================================
#define P_AHI 0
#define P_ALO 17408
#define P_BHI 34816
#define P_BLO 53248
#define P_TOTAL 71680

__global__ __launch_bounds__(256, 3)
void proj_mma(const float* __restrict__ x,
              const float* __restrict__ proj,
              const float* __restrict__ gamma,
              const float* __restrict__ beta,
              float* __restrict__ out)
{
    extern __shared__ char smem[];
    const int j   = blockIdx.y;
    const int r0  = blockIdx.x * 64;
    const int tid = threadIdx.x, wid = tid >> 5, lane = tid & 31;

    #pragma unroll 4
    for (int t = tid; t < 2048; t += 256) {
        int row = t >> 5, kk = (t & 31) << 2;
        const float4 xv = *(const float4*)(g_ao + ((size_t)(r0 + row) * J_ + j) * H_ + kk);
        uint32_t h01, l01, h23, l23;
        cvt_pair(xv.x, xv.y, h01, l01);
        cvt_pair(xv.z, xv.w, h23, l23);
        *(uint2*)(smem + P_AHI + row * SAB_B + kk * 2) = make_uint2(h01, h23);
        *(uint2*)(smem + P_ALO + row * SAB_B + kk * 2) = make_uint2(l01, l23);
    }

    const int warpM = wid & 3, warpN = wid >> 2;
    const uint32_t sb = smem_u32(smem);
    const int ar = lane & 15, ac = (lane >> 4) << 3;
    const int bg = lane >> 3, blp = lane & 7;
    const int kt = ((bg & 1) << 3) + blp;
    const int nb = (bg >> 1) << 4;
    const uint32_t aRow = (uint32_t)(warpM * 16 + ar) * SAB_B;

    float acc[2][4][4];   // [pass][ntile][frag]
    #pragma unroll
    for (int p = 0; p < 2; p++)
        #pragma unroll
        for (int nt = 0; nt < 4; nt++)
            #pragma unroll
            for (int i = 0; i < 4; i++) acc[p][nt][i] = 0.f;

    #pragma unroll 1
    for (int p = 0; p < 2; p++) {
        if (p > 0) __syncthreads();      // previous gemm done reading B
        const int c0 = p * 64;
        #pragma unroll 4
        for (int t = tid; t < 2048; t += 256) {
            int k = t >> 4, n0 = (t & 15) << 2;
            const float4 wv = *(const float4*)(proj + (size_t)j * H_ * H_ + k * H_ + c0 + n0);
            uint32_t h01, l01, h23, l23;
            cvt_pair(wv.x, wv.y, h01, l01);
            cvt_pair(wv.z, wv.w, h23, l23);
            *(uint2*)(smem + P_BHI + k * SBN + n0 * 2) = make_uint2(h01, h23);
            *(uint2*)(smem + P_BLO + k * SBN + n0 * 2) = make_uint2(l01, l23);
        }
        __syncthreads();

        #pragma unroll 1
        for (int sp = 0; sp < 3; sp++) {
            const uint32_t aB = sb + ((sp == 2) ? P_ALO : P_AHI) + aRow;
            const uint32_t bB = sb + ((sp == 1) ? P_BLO : P_BHI);
            #pragma unroll
            for (int k0 = 0; k0 < 8; k0++) {
                uint32_t a[4];
                ldsm_x4(a[0], a[1], a[2], a[3], aB + (uint32_t)(k0 * 16 + ac) * 2);
                #pragma unroll
                for (int ntp = 0; ntp < 2; ntp++) {
                    uint32_t bfr[4];
                    ldsm_x4_t(bfr[0], bfr[1], bfr[2], bfr[3],
                              bB + (uint32_t)(k0 * 16 + kt) * SBN
                                 + (uint32_t)(warpN * 32 + ntp * 16) * 2 + nb);
                    mma_bf16(acc[p][ntp * 2],     a, bfr[0], bfr[1]);
                    mma_bf16(acc[p][ntp * 2 + 1], a, bfr[2], bfr[3]);
                }
            }
        }
    }

    __syncthreads();
    float* Cs = (float*)smem;
    #pragma unroll
    for (int p = 0; p < 2; p++) {
        int rb = warpM * 16 + (lane >> 2);
        #pragma unroll
        for (int nt = 0; nt < 4; nt++) {
            int col = p * 64 + warpN * 32 + nt * 8 + ((lane & 3) << 1);
            #pragma unroll
            for (int h = 0; h < 2; h++) {
                Cs[(rb + h * 8) * 132 + col]     = acc[p][nt][h * 2];
                Cs[(rb + h * 8) * 132 + col + 1] = acc[p][nt][h * 2 + 1];
            }
        }
    }
    __syncthreads();

    {
        const int row = tid >> 2;
        const int q   = tid & 3;
        const int r   = r0 + row;
        const float* xr = x + ((size_t)r * J_ + j) * H_ + q * 32;
        float* crow     = Cs + row * 132 + q * 32;

        float sum = 0.f, sq = 0.f;
        #pragma unroll
        for (int i = 0; i < 8; i++) {
            float4 c4 = *(float4*)(crow + i * 4);
            float4 xv = *(const float4*)(xr + i * 4);
            c4.x += xv.x; c4.y += xv.y; c4.z += xv.z; c4.w += xv.w;
            *(float4*)(crow + i * 4) = c4;
            sum += c4.x + c4.y + c4.z + c4.w;
            sq  += c4.x*c4.x + c4.y*c4.y + c4.z*c4.z + c4.w*c4.w;
        }
        sum += __shfl_xor_sync(0xffffffffu, sum, 1);
        sum += __shfl_xor_sync(0xffffffffu, sum, 2);
        sq  += __shfl_xor_sync(0xffffffffu, sq, 1);
        sq  += __shfl_xor_sync(0xffffffffu, sq, 2);
        const float mu   = sum * (1.f / 128.f);
        const float var  = sq * (1.f / 128.f) - mu * mu;
        const float rstd = rsqrtf(var + 1e-5f);

        float* orow = out + ((size_t)r * J_ + j) * H_ + q * 32;
        const float* gp  = gamma + q * 32;
        const float* bp2 = beta  + q * 32;
        #pragma unroll
        for (int i = 0; i < 8; i++) {
            float4 c4 = *(float4*)(crow + i * 4);
            float4 o;
            o.x = (c4.x - mu) * rstd * gp[i*4+0] + bp2[i*4+0];
            o.y = (c4.y - mu) * rstd * gp[i*4+1] + bp2[i*4+1];
            o.z = (c4.z - mu) * rstd * gp[i*4+2] + bp2[i*4+2];
            o.w = (c4.w - mu) * rstd * gp[i*4+3] + bp2[i*4+3];
            *(float4*)(orow + i * 4) = o;
        }
    }
}

// ===========================================================================
extern "C" void kernel_launch(void* const* d_in, const int* in_sizes, int n_in,
                              void* d_out, int out_size)
{
    const float* x     = (const float*)d_in[0];
    // d_in[1]: additive causal mask (= triu(-1e9)) — implemented as causal skip.
    const float* qm    = (const float*)d_in[2];
    const float* km    = (const float*)d_in[3];
    const float* vm    = (const float*)d_in[4];
    const float* proj  = (const float*)d_in[5];
    const float* gamma = (const float*)d_in[6];
    const float* beta  = (const float*)d_in[7];
    float* out = (float*)d_out;

    cudaFuncSetAttribute(qkv_mma,  cudaFuncAttributeMaxDynamicSharedMemorySize, QK_TOTAL);
    cudaFuncSetAttribute(attn_mma, cudaFuncAttributeMaxDynamicSharedMemorySize, AT_TOTAL);
    cudaFuncSetAttribute(proj_mma, cudaFuncAttributeMaxDynamicSharedMemorySize, P_TOTAL);

    qkv_mma<<<dim3(BS_/128, J_, 2), 256, QK_TOTAL>>>(x, qm, km, vm);
    attn_mma<<<INST_, 512, AT_TOTAL>>>();
    proj_mma<<<dim3(BS_/64, J_), 256, P_TOTAL>>>(x, proj, gamma, beta, out);
}

// round 11
// speedup vs baseline: 1.9284x; 1.0900x over previous
#include <cuda_runtime.h>
#include <cuda_bf16.h>
#include <stdint.h>

// Problem constants
#define B_  4
#define S_  512
#define J_  24
#define H_  128
#define NH_ 8
#define HS_ 16
#define BS_ (B_*S_)            // 2048 rows
#define INST_ (B_*NH_*J_)      // 768 attention instances
#define QKV_E (B_*NH_*J_*S_*HS_)   // 6291456 elements
#define QSCALE 0.3606737602222409f // 0.25 * log2(e)

// Scratch (static device globals — allocation-free)
__device__ float g_ao[B_*S_*J_*H_];              // attention out (fp32)
__device__ __nv_bfloat16 g_xh[BS_*J_*H_];        // x split hi/lo
__device__ __nv_bfloat16 g_xl[BS_*J_*H_];
__device__ __nv_bfloat16 g_wh[3*J_*H_*H_];       // qkv weights [m][j][k][n]
__device__ __nv_bfloat16 g_wl[3*J_*H_*H_];
__device__ __nv_bfloat16 g_qh[QKV_E], g_ql[QKV_E];   // q pre-scaled by QSCALE
__device__ __nv_bfloat16 g_kh[QKV_E], g_kl[QKV_E];
__device__ __nv_bfloat16 g_vh[QKV_E], g_vl[QKV_E];

// ===========================================================================
// Helpers (baseline PTX features only)
// ===========================================================================
__device__ __forceinline__ uint32_t smem_u32(const void* p) {
    uint32_t a;
    asm("{ .reg .u64 t; cvta.to.shared.u64 t, %1; cvt.u32.u64 %0, t; }"
        : "=r"(a) : "l"(p));
    return a;
}
__device__ __forceinline__ void ldsm_x4(uint32_t& r0, uint32_t& r1,
                                        uint32_t& r2, uint32_t& r3, uint32_t addr) {
    asm volatile("ldmatrix.sync.aligned.m8n8.x4.shared.b16 {%0,%1,%2,%3}, [%4];"
                 : "=r"(r0), "=r"(r1), "=r"(r2), "=r"(r3) : "r"(addr));
}
__device__ __forceinline__ void ldsm_x4_t(uint32_t& r0, uint32_t& r1,
                                          uint32_t& r2, uint32_t& r3, uint32_t addr) {
    asm volatile("ldmatrix.sync.aligned.m8n8.x4.trans.shared.b16 {%0,%1,%2,%3}, [%4];"
                 : "=r"(r0), "=r"(r1), "=r"(r2), "=r"(r3) : "r"(addr));
}
__device__ __forceinline__ void mma_bf16(float* c, const uint32_t a[4],
                                         uint32_t b0, uint32_t b1) {
    asm volatile(
        "mma.sync.aligned.m16n8k16.row.col.f32.bf16.bf16.f32 "
        "{%0,%1,%2,%3}, {%4,%5,%6,%7}, {%8,%9}, {%0,%1,%2,%3};"
        : "+f"(c[0]), "+f"(c[1]), "+f"(c[2]), "+f"(c[3])
        : "r"(a[0]), "r"(a[1]), "r"(a[2]), "r"(a[3]), "r"(b0), "r"(b1));
}
// split-fp32 -> (hi bf16x2, lo bf16x2); a -> low half, b -> high half
__device__ __forceinline__ void cvt_pair(float a, float b, uint32_t& hi, uint32_t& lo) {
    uint32_t h;
    asm("cvt.rn.bf16x2.f32 %0, %1, %2;" : "=r"(h) : "f"(b), "f"(a));
    float ha = __uint_as_float(h << 16);
    float hb = __uint_as_float(h & 0xffff0000u);
    float la = a - ha, lb = b - hb;
    asm("cvt.rn.bf16x2.f32 %0, %1, %2;" : "=r"(lo) : "f"(lb), "f"(la));
    hi = h;
}
__device__ __forceinline__ float ex2f(float x) {
    float r; asm("ex2.approx.f32 %0, %1;" : "=f"(r) : "f"(x)); return r;
}
__device__ __forceinline__ void cpa16(uint32_t dst, const void* src) {
    asm volatile("cp.async.cg.shared.global [%0], [%1], 16;" :: "r"(dst), "l"(src));
}
#define CP_COMMIT asm volatile("cp.async.commit_group;" ::: "memory")
#define CP_WAIT0  asm volatile("cp.async.wait_group 0;" ::: "memory")

#define SAB_B 272      // A row stride in bytes (136 bf16)
#define SBN   144      // B (transposed [k][n]) row stride in bytes

// ===========================================================================
// Kernel 0: prep — convert x and qkv weights to split bf16 in global.
// ===========================================================================
#define XQUAD (BS_*J_*H_/4)               // 1572864 float4s
#define WPAIR (3*NH_*J_*H_*HS_/2)         // 589824 pairs
#define PREP_T ((XQUAD + WPAIR + 255) & ~255)

__global__ __launch_bounds__(256)
void prep(const float* __restrict__ x,
          const float* __restrict__ qm,
          const float* __restrict__ km,
          const float* __restrict__ vm)
{
    int t = blockIdx.x * 256 + threadIdx.x;
    if (t < XQUAD) {
        float4 v = ((const float4*)x)[t];
        uint32_t h01, l01, h23, l23;
        cvt_pair(v.x, v.y, h01, l01);
        cvt_pair(v.z, v.w, h23, l23);
        ((uint2*)g_xh)[t] = make_uint2(h01, h23);
        ((uint2*)g_xl)[t] = make_uint2(l01, l23);
    } else if (t < XQUAD + WPAIR) {
        int u  = t - XQUAD;
        int n2 = u & 63;  int u2 = u >> 6;
        int k  = u2 & 127; int u3 = u2 >> 7;
        int j  = u3 % J_;  int m  = u3 / J_;
        int n  = n2 * 2;
        const float* mat = (m == 0) ? qm : (m == 1 ? km : vm);
        const float2 w = *(const float2*)(mat +
            ((size_t)((n >> 4) * J_ + j) * H_ + k) * HS_ + (n & 15));
        uint32_t hi, lo;
        cvt_pair(w.x, w.y, hi, lo);
        size_t o = ((size_t)(m * J_ + j) * H_ + k) * H_ + n;
        *(uint32_t*)(g_wh + o) = hi;
        *(uint32_t*)(g_wl + o) = lo;
    }
}

// ===========================================================================
// Kernel 1: QKV projection. grid (16, 24, 2). block 256. cp.async staging
// from precomputed splits; B(m+1) copy overlapped with scatter(m).
// Outputs q (pre-scaled by QSCALE), k, v as split bf16.
// ===========================================================================
#define QK_AHI 0
#define QK_ALO 34816
#define QK_BHI 69632
#define QK_BLO 88064
#define QK_TOTAL 106496

__global__ __launch_bounds__(256, 2)
void qkv_mma()
{
    extern __shared__ char smem[];
    const int j   = blockIdx.y;
    const int c0  = blockIdx.z * 64;
    const int r0  = blockIdx.x * 128;
    const int tid = threadIdx.x, wid = tid >> 5, lane = tid & 31;
    const uint32_t sb = smem_u32(smem);

    // --- async stage A (x rows r0..r0+127, hi+lo) ---
    #pragma unroll 4
    for (int i = tid; i < 4096; i += 256) {
        int buf = i >> 11;               // 0 hi, 1 lo
        int row = (i >> 4) & 127;
        int ch  = i & 15;
        const char* src = (const char*)(buf ? g_xl : g_xh)
            + ((size_t)(r0 + row) * J_ + j) * H_ * 2 + ch * 16;
        cpa16(sb + (buf ? QK_ALO : QK_AHI) + row * SAB_B + ch * 16, src);
    }
    // --- async stage B(0) ---
    #pragma unroll 4
    for (int i = tid; i < 2048; i += 256) {
        int buf = i >> 10;
        int k   = (i >> 3) & 127;
        int ch  = i & 7;
        const char* src = (const char*)(buf ? g_wl : g_wh)
            + (((size_t)(0 * J_ + j) * H_ + k) * H_ + c0) * 2 + ch * 16;
        cpa16(sb + (buf ? QK_BLO : QK_BHI) + k * SBN + ch * 16, src);
    }
    CP_COMMIT;
    CP_WAIT0;
    __syncthreads();

    const int warpM = wid & 3, warpN = wid >> 2;
    const int ar = lane & 15, ac = (lane >> 4) << 3;
    const int bg = lane >> 3, blp = lane & 7;
    const int kt = ((bg & 1) << 3) + blp;
    const int nb = (bg >> 1) << 4;
    const uint32_t aRow = (uint32_t)(warpM * 32 + ar) * SAB_B;

    for (int m = 0; m < 3; m++) {
        float acc[2][4][4];
        #pragma unroll
        for (int mt = 0; mt < 2; mt++)
            #pragma unroll
            for (int nt = 0; nt < 4; nt++)
                #pragma unroll
                for (int i = 0; i < 4; i++) acc[mt][nt][i] = 0.f;

        #pragma unroll 1
        for (int sp = 0; sp < 3; sp++) {
            const uint32_t aB = sb + ((sp == 2) ? QK_ALO : QK_AHI) + aRow;
            const uint32_t bB = sb + ((sp == 1) ? QK_BLO : QK_BHI);
            #pragma unroll
            for (int k0 = 0; k0 < 8; k0++) {
                uint32_t a[2][4];
                #pragma unroll
                for (int mt = 0; mt < 2; mt++)
                    ldsm_x4(a[mt][0], a[mt][1], a[mt][2], a[mt][3],
                            aB + (uint32_t)(mt * 16) * SAB_B + (uint32_t)(k0 * 16 + ac) * 2);
                #pragma unroll
                for (int ntp = 0; ntp < 2; ntp++) {
                    uint32_t b[4];
                    ldsm_x4_t(b[0], b[1], b[2], b[3],
                              bB + (uint32_t)(k0 * 16 + kt) * SBN
                                 + (uint32_t)(warpN * 32 + ntp * 16) * 2 + nb);
                    #pragma unroll
                    for (int mt = 0; mt < 2; mt++) {
                        mma_bf16(acc[mt][ntp * 2],     a[mt], b[0], b[1]);
                        mma_bf16(acc[mt][ntp * 2 + 1], a[mt], b[2], b[3]);
                    }
                }
            }
        }

        if (m < 2) {
            __syncthreads();     // all warps done reading B(m)
            #pragma unroll 4
            for (int i = tid; i < 2048; i += 256) {
                int buf = i >> 10;
                int k   = (i >> 3) & 127;
                int ch  = i & 7;
                const char* src = (const char*)(buf ? g_wl : g_wh)
                    + (((size_t)((m + 1) * J_ + j) * H_ + k) * H_ + c0) * 2 + ch * 16;
                cpa16(sb + (buf ? QK_BLO : QK_BHI) + k * SBN + ch * 16, src);
            }
            CP_COMMIT;
        }

        // scatter (overlaps async B copy): split hi/lo bf16, q pre-scaled
        __nv_bfloat16* outh = (m == 0) ? g_qh : (m == 1 ? g_kh : g_vh);
        __nv_bfloat16* outl = (m == 0) ? g_ql : (m == 1 ? g_kl : g_vl);
        const float sc = (m == 0) ? QSCALE : 1.f;
        #pragma unroll
        for (int mt = 0; mt < 2; mt++) {
            int rbase = r0 + warpM * 32 + mt * 16 + (lane >> 2);
            #pragma unroll
            for (int nt = 0; nt < 4; nt++) {
                int c = c0 + warpN * 32 + nt * 8 + ((lane & 3) << 1);
                int n = c >> 4, d = c & 15;
                #pragma unroll
                for (int h = 0; h < 2; h++) {
                    int r = rbase + h * 8;
                    int b = r >> 9, sI = r & 511;
                    size_t idx = (((size_t)(b * NH_ + n) * J_ + j) * S_ + sI) * HS_ + d;
                    uint32_t hi, lo;
                    cvt_pair(acc[mt][nt][h * 2] * sc, acc[mt][nt][h * 2 + 1] * sc, hi, lo);
                    *(uint32_t*)(outh + idx) = hi;
                    *(uint32_t*)(outl + idx) = lo;
                }
            }
        }
        if (m < 2) { CP_WAIT0; __syncthreads(); }
    }
}

// ===========================================================================
// Kernel 2: tensor-core causal attention. block 512 (16 warps, band-permuted).
// cp.async staging of pre-split K/V; direct Q frag loads (pre-scaled);
// exp via bare MUFU ex2. XOR-swizzled conflict-free smem.
// ===========================================================================
#define KSWZ(r, off) ((((uint32_t)(r)) << 5) + \
                      (((uint32_t)(off)) ^ ((((uint32_t)(r) >> 2) & 1u) << 4)))
#define AT_TOTAL 65536

__global__ __launch_bounds__(512, 1)
void attn_mma()
{
    extern __shared__ char smem[];
    const int inst = blockIdx.x;
    const int j  = inst % J_;
    const int bn = inst / J_;
    const int n  = bn % NH_;
    const int b  = bn / NH_;
    const size_t base = (size_t)inst * S_ * HS_;   // element base

    const int tid = threadIdx.x, wid = tid >> 5, lane = tid & 31;
    const uint32_t sbase = smem_u32(smem);

    // Stage Kh,Kl,Vh,Vl via cp.async (buffers at sbase + buf*16384)
    #pragma unroll 8
    for (int i = tid; i < 4096; i += 512) {
        int buf = i >> 10;
        int row = (i >> 1) & 511;
        int ch  = i & 1;
        const char* srcb = (buf == 0) ? (const char*)g_kh :
                           (buf == 1) ? (const char*)g_kl :
                           (buf == 2) ? (const char*)g_vh : (const char*)g_vl;
        cpa16(sbase + buf * 16384 + KSWZ(row, ch << 4),
              srcb + base * 2 + row * 32 + ch * 16);
    }
    CP_COMMIT;
    CP_WAIT0;
    __syncthreads();

    // Warp -> band permutation: SMSP g gets bands {g, 7-g, 8+g, 15-g}
    const int g  = wid & 3, iq = wid >> 2;
    const int band = (iq == 0) ? g : (iq == 1) ? (7 - g) : (iq == 2) ? (8 + g) : (15 - g);
    const int R0 = band * 32;
    const int qrow = lane >> 2, qcol = (lane & 3) << 1;

    // Q fragments: direct uint32 loads of pre-scaled splits
    uint32_t qh[2][4], ql[2][4];
    #pragma unroll
    for (int mt = 0; mt < 2; mt++) {
        size_t eb = base + (size_t)(R0 + qrow + mt * 16) * HS_ + qcol;
        qh[mt][0] = *(const uint32_t*)(g_qh + eb);
        qh[mt][1] = *(const uint32_t*)(g_qh + eb + 8 * HS_);
        qh[mt][2] = *(const uint32_t*)(g_qh + eb + 8);
        qh[mt][3] = *(const uint32_t*)(g_qh + eb + 8 * HS_ + 8);
        ql[mt][0] = *(const uint32_t*)(g_ql + eb);
        ql[mt][1] = *(const uint32_t*)(g_ql + eb + 8 * HS_);
        ql[mt][2] = *(const uint32_t*)(g_ql + eb + 8);
        ql[mt][3] = *(const uint32_t*)(g_ql + eb + 8 * HS_ + 8);
    }

    float O[2][2][4];
    #pragma unroll
    for (int mt = 0; mt < 2; mt++)
        #pragma unroll
        for (int dt = 0; dt < 2; dt++)
            #pragma unroll
            for (int i = 0; i < 4; i++) O[mt][dt][i] = 0.f;
    float rs[2][2] = {{0.f, 0.f}, {0.f, 0.f}};

    const uint32_t Kh = sbase,          Kl = sbase + 16384;
    const uint32_t Vh = sbase + 32768,  Vl = sbase + 49152;

    const int bg = lane >> 3, bl = lane & 7;
    const int kn = ((bg >> 1) << 3) + bl;
    const int kk = (bg & 1) << 3;
    const int vt = ((bg & 1) << 3) + bl;
    const int vd = (bg >> 1) << 4;

    const int last = 2 * band;

    for (int ntp = 0; ntp <= last; ntp++) {
        const int C0 = ntp << 4;
        uint32_t kh[4], klr[4], vh[4], vlr[4];
        ldsm_x4(kh[0], kh[1], kh[2], kh[3],     Kh + KSWZ(C0 + kn, kk * 2));
        ldsm_x4(klr[0], klr[1], klr[2], klr[3], Kl + KSWZ(C0 + kn, kk * 2));
        ldsm_x4_t(vh[0], vh[1], vh[2], vh[3],   Vh + KSWZ(C0 + vt, vd));
        ldsm_x4_t(vlr[0], vlr[1], vlr[2], vlr[3], Vl + KSWZ(C0 + vt, vd));

        float S[2][2][4];
        #pragma unroll
        for (int mt = 0; mt < 2; mt++)
            #pragma unroll
            for (int q2 = 0; q2 < 2; q2++)
                #pragma unroll
                for (int i = 0; i < 4; i++) S[mt][q2][i] = 0.f;
        #pragma unroll
        for (int mt = 0; mt < 2; mt++) {
            mma_bf16(S[mt][0], qh[mt], kh[0], kh[1]);
            mma_bf16(S[mt][1], qh[mt], kh[2], kh[3]);
            mma_bf16(S[mt][0], ql[mt], kh[0], kh[1]);
            mma_bf16(S[mt][1], ql[mt], kh[2], kh[3]);
            mma_bf16(S[mt][0], qh[mt], klr[0], klr[1]);
            mma_bf16(S[mt][1], qh[mt], klr[2], klr[3]);
        }

        #pragma unroll
        for (int mt = 0; mt < 2; mt++) {
            float p[8];
            if (mt == 0 && ntp == last) {
                const int row0 = R0 + qrow;
                const int col0 = C0 + qcol;
                p[0] = (col0     <= row0    ) ? ex2f(S[0][0][0]) : 0.f;
                p[1] = (col0 + 1 <= row0    ) ? ex2f(S[0][0][1]) : 0.f;
                p[2] = (col0     <= row0 + 8) ? ex2f(S[0][0][2]) : 0.f;
                p[3] = (col0 + 1 <= row0 + 8) ? ex2f(S[0][0][3]) : 0.f;
                p[4] = (col0 + 8 <= row0    ) ? ex2f(S[0][1][0]) : 0.f;
                p[5] = (col0 + 9 <= row0    ) ? ex2f(S[0][1][1]) : 0.f;
                p[6] = (col0 + 8 <= row0 + 8) ? ex2f(S[0][1][2]) : 0.f;
                p[7] = (col0 + 9 <= row0 + 8) ? ex2f(S[0][1][3]) : 0.f;
            } else {
                p[0] = ex2f(S[mt][0][0]);
                p[1] = ex2f(S[mt][0][1]);
                p[2] = ex2f(S[mt][0][2]);
                p[3] = ex2f(S[mt][0][3]);
                p[4] = ex2f(S[mt][1][0]);
                p[5] = ex2f(S[mt][1][1]);
                p[6] = ex2f(S[mt][1][2]);
                p[7] = ex2f(S[mt][1][3]);
            }
            rs[mt][0] += (p[0] + p[1]) + (p[4] + p[5]);
            rs[mt][1] += (p[2] + p[3]) + (p[6] + p[7]);

            uint32_t ph[4], pl[4];
            cvt_pair(p[0], p[1], ph[0], pl[0]);
            cvt_pair(p[2], p[3], ph[1], pl[1]);
            cvt_pair(p[4], p[5], ph[2], pl[2]);
            cvt_pair(p[6], p[7], ph[3], pl[3]);

            mma_bf16(O[mt][0], ph, vh[0], vh[1]);
            mma_bf16(O[mt][1], ph, vh[2], vh[3]);
            mma_bf16(O[mt][0], pl, vh[0], vh[1]);
            mma_bf16(O[mt][1], pl, vh[2], vh[3]);
            mma_bf16(O[mt][0], ph, vlr[0], vlr[1]);
            mma_bf16(O[mt][1], ph, vlr[2], vlr[3]);
        }
    }

    // Epilogue tile: ntp = last+1, mt = 1 only (diagonal)
    {
        const int C0 = (last + 1) << 4;
        uint32_t kh[4], klr[4], vh[4], vlr[4];
        ldsm_x4(kh[0], kh[1], kh[2], kh[3],     Kh + KSWZ(C0 + kn, kk * 2));
        ldsm_x4(klr[0], klr[1], klr[2], klr[3], Kl + KSWZ(C0 + kn, kk * 2));
        ldsm_x4_t(vh[0], vh[1], vh[2], vh[3],   Vh + KSWZ(C0 + vt, vd));
        ldsm_x4_t(vlr[0], vlr[1], vlr[2], vlr[3], Vl + KSWZ(C0 + vt, vd));

        float S0[4] = {0.f,0.f,0.f,0.f}, S1[4] = {0.f,0.f,0.f,0.f};
        mma_bf16(S0, qh[1], kh[0], kh[1]);
        mma_bf16(S1, qh[1], kh[2], kh[3]);
        mma_bf16(S0, ql[1], kh[0], kh[1]);
        mma_bf16(S1, ql[1], kh[2], kh[3]);
        mma_bf16(S0, qh[1], klr[0], klr[1]);
        mma_bf16(S1, qh[1], klr[2], klr[3]);

        const int row0 = R0 + 16 + qrow;
        const int col0 = C0 + qcol;
        float p[8];
        p[0] = (col0     <= row0    ) ? ex2f(S0[0]) : 0.f;
        p[1] = (col0 + 1 <= row0    ) ? ex2f(S0[1]) : 0.f;
        p[2] = (col0     <= row0 + 8) ? ex2f(S0[2]) : 0.f;
        p[3] = (col0 + 1 <= row0 + 8) ? ex2f(S0[3]) : 0.f;
        p[4] = (col0 + 8 <= row0    ) ? ex2f(S1[0]) : 0.f;
        p[5] = (col0 + 9 <= row0    ) ? ex2f(S1[1]) : 0.f;
        p[6] = (col0 + 8 <= row0 + 8) ? ex2f(S1[2]) : 0.f;
        p[7] = (col0 + 9 <= row0 + 8) ? ex2f(S1[3]) : 0.f;
        rs[1][0] += (p[0] + p[1]) + (p[4] + p[5]);
        rs[1][1] += (p[2] + p[3]) + (p[6] + p[7]);

        uint32_t ph[4], pl[4];
        cvt_pair(p[0], p[1], ph[0], pl[0]);
        cvt_pair(p[2], p[3], ph[1], pl[1]);
        cvt_pair(p[4], p[5], ph[2], pl[2]);
        cvt_pair(p[6], p[7], ph[3], pl[3]);

        mma_bf16(O[1][0], ph, vh[0], vh[1]);
        mma_bf16(O[1][1], ph, vh[2], vh[3]);
        mma_bf16(O[1][0], pl, vh[0], vh[1]);
        mma_bf16(O[1][1], pl, vh[2], vh[3]);
        mma_bf16(O[1][0], ph, vlr[0], vlr[1]);
        mma_bf16(O[1][1], ph, vlr[2], vlr[3]);
    }

    // Row sums: reduce across the 4 lanes of each row group, normalize, store.
    #pragma unroll
    for (int mt = 0; mt < 2; mt++) {
        float s0 = rs[mt][0], s1 = rs[mt][1];
        s0 += __shfl_xor_sync(0xffffffffu, s0, 1);
        s0 += __shfl_xor_sync(0xffffffffu, s0, 2);
        s1 += __shfl_xor_sync(0xffffffffu, s1, 1);
        s1 += __shfl_xor_sync(0xffffffffu, s1, 2);
        const float i0 = 1.f / s0, i1 = 1.f / s1;
        const int row = R0 + mt * 16 + (lane >> 2);
        const int dc  = (lane & 3) << 1;
        #pragma unroll
        for (int dt = 0; dt < 2; dt++) {
            const int d = dt * 8 + dc;
            float* o0 = g_ao + ((size_t)(b * S_ + row)     * J_ + j) * H_ + n * HS_ + d;
            float* o1 = g_ao + ((size_t)(b * S_ + row + 8) * J_ + j) * H_ + n * HS_ + d;
            *(float2*)o0 = make_float2(O[mt][dt][0] * i0, O[mt][dt][1] * i0);
            *(float2*)o1 = make_float2(O[mt][dt][2] * i1, O[mt][dt][3] * i1);
        }
    }
}

// ===========================================================================
// Kernel 3: output projection + residual + LayerNorm.  (unchanged from best)
// ===========================================================================
#define P_AHI 0
#define P_ALO 17408
#define P_BHI 34816
#define P_BLO 53248
#define P_TOTAL 71680

__global__ __launch_bounds__(256, 3)
void proj_mma(const float* __restrict__ x,
              const float* __restrict__ proj,
              const float* __restrict__ gamma,
              const float* __restrict__ beta,
              float* __restrict__ out)
{
    extern __shared__ char smem[];
    const int j   = blockIdx.y;
    const int r0  = blockIdx.x * 64;
    const int tid = threadIdx.x, wid = tid >> 5, lane = tid & 31;

    #pragma unroll 4
    for (int t = tid; t < 2048; t += 256) {
        int row = t >> 5, kk = (t & 31) << 2;
        const float4 xv = *(const float4*)(g_ao + ((size_t)(r0 + row) * J_ + j) * H_ + kk);
        uint32_t h01, l01, h23, l23;
        cvt_pair(xv.x, xv.y, h01, l01);
        cvt_pair(xv.z, xv.w, h23, l23);
        *(uint2*)(smem + P_AHI + row * SAB_B + kk * 2) = make_uint2(h01, h23);
        *(uint2*)(smem + P_ALO + row * SAB_B + kk * 2) = make_uint2(l01, l23);
    }

    const int warpM = wid & 3, warpN = wid >> 2;
    const uint32_t sb = smem_u32(smem);
    const int ar = lane & 15, ac = (lane >> 4) << 3;
    const int bg = lane >> 3, blp = lane & 7;
    const int kt = ((bg & 1) << 3) + blp;
    const int nb = (bg >> 1) << 4;
    const uint32_t aRow = (uint32_t)(warpM * 16 + ar) * SAB_B;

    float acc[2][4][4];
    #pragma unroll
    for (int p = 0; p < 2; p++)
        #pragma unroll
        for (int nt = 0; nt < 4; nt++)
            #pragma unroll
            for (int i = 0; i < 4; i++) acc[p][nt][i] = 0.f;

    #pragma unroll 1
    for (int p = 0; p < 2; p++) {
        if (p > 0) __syncthreads();
        const int c0 = p * 64;
        #pragma unroll 4
        for (int t = tid; t < 2048; t += 256) {
            int k = t >> 4, n0 = (t & 15) << 2;
            const float4 wv = *(const float4*)(proj + (size_t)j * H_ * H_ + k * H_ + c0 + n0);
            uint32_t h01, l01, h23, l23;
            cvt_pair(wv.x, wv.y, h01, l01);
            cvt_pair(wv.z, wv.w, h23, l23);
            *(uint2*)(smem + P_BHI + k * SBN + n0 * 2) = make_uint2(h01, h23);
            *(uint2*)(smem + P_BLO + k * SBN + n0 * 2) = make_uint2(l01, l23);
        }
        __syncthreads();

        #pragma unroll 1
        for (int sp = 0; sp < 3; sp++) {
            const uint32_t aB = sb + ((sp == 2) ? P_ALO : P_AHI) + aRow;
            const uint32_t bB = sb + ((sp == 1) ? P_BLO : P_BHI);
            #pragma unroll
            for (int k0 = 0; k0 < 8; k0++) {
                uint32_t a[4];
                ldsm_x4(a[0], a[1], a[2], a[3], aB + (uint32_t)(k0 * 16 + ac) * 2);
                #pragma unroll
                for (int ntp = 0; ntp < 2; ntp++) {
                    uint32_t bfr[4];
                    ldsm_x4_t(bfr[0], bfr[1], bfr[2], bfr[3],
                              bB + (uint32_t)(k0 * 16 + kt) * SBN
                                 + (uint32_t)(warpN * 32 + ntp * 16) * 2 + nb);
                    mma_bf16(acc[p][ntp * 2],     a, bfr[0], bfr[1]);
                    mma_bf16(acc[p][ntp * 2 + 1], a, bfr[2], bfr[3]);
                }
            }
        }
    }

    __syncthreads();
    float* Cs = (float*)smem;
    #pragma unroll
    for (int p = 0; p < 2; p++) {
        int rb = warpM * 16 + (lane >> 2);
        #pragma unroll
        for (int nt = 0; nt < 4; nt++) {
            int col = p * 64 + warpN * 32 + nt * 8 + ((lane & 3) << 1);
            #pragma unroll
            for (int h = 0; h < 2; h++) {
                Cs[(rb + h * 8) * 132 + col]     = acc[p][nt][h * 2];
                Cs[(rb + h * 8) * 132 + col + 1] = acc[p][nt][h * 2 + 1];
            }
        }
    }
    __syncthreads();

    {
        const int row = tid >> 2;
        const int q   = tid & 3;
        const int r   = r0 + row;
        const float* xr = x + ((size_t)r * J_ + j) * H_ + q * 32;
        float* crow     = Cs + row * 132 + q * 32;

        float sum = 0.f, sq = 0.f;
        #pragma unroll
        for (int i = 0; i < 8; i++) {
            float4 c4 = *(float4*)(crow + i * 4);
            float4 xv = *(const float4*)(xr + i * 4);
            c4.x += xv.x; c4.y += xv.y; c4.z += xv.z; c4.w += xv.w;
            *(float4*)(crow + i * 4) = c4;
            sum += c4.x + c4.y + c4.z + c4.w;
            sq  += c4.x*c4.x + c4.y*c4.y + c4.z*c4.z + c4.w*c4.w;
        }
        sum += __shfl_xor_sync(0xffffffffu, sum, 1);
        sum += __shfl_xor_sync(0xffffffffu, sum, 2);
        sq  += __shfl_xor_sync(0xffffffffu, sq, 1);
        sq  += __shfl_xor_sync(0xffffffffu, sq, 2);
        const float mu   = sum * (1.f / 128.f);
        const float var  = sq * (1.f / 128.f) - mu * mu;
        const float rstd = rsqrtf(var + 1e-5f);

        float* orow = out + ((size_t)r * J_ + j) * H_ + q * 32;
        const float* gp  = gamma + q * 32;
        const float* bp2 = beta  + q * 32;
        #pragma unroll
        for (int i = 0; i < 8; i++) {
            float4 c4 = *(float4*)(crow + i * 4);
            float4 o;
            o.x = (c4.x - mu) * rstd * gp[i*4+0] + bp2[i*4+0];
            o.y = (c4.y - mu) * rstd * gp[i*4+1] + bp2[i*4+1];
            o.z = (c4.z - mu) * rstd * gp[i*4+2] + bp2[i*4+2];
            o.w = (c4.w - mu) * rstd * gp[i*4+3] + bp2[i*4+3];
            *(float4*)(orow + i * 4) = o;
        }
    }
}

// ===========================================================================
extern "C" void kernel_launch(void* const* d_in, const int* in_sizes, int n_in,
                              void* d_out, int out_size)
{
    const float* x     = (const float*)d_in[0];
    // d_in[1]: additive causal mask (= triu(-1e9)) — implemented as causal skip.
    const float* qm    = (const float*)d_in[2];
    const float* km    = (const float*)d_in[3];
    const float* vm    = (const float*)d_in[4];
    const float* proj  = (const float*)d_in[5];
    const float* gamma = (const float*)d_in[6];
    const float* beta  = (const float*)d_in[7];
    float* out = (float*)d_out;

    cudaFuncSetAttribute(qkv_mma,  cudaFuncAttributeMaxDynamicSharedMemorySize, QK_TOTAL);
    cudaFuncSetAttribute(attn_mma, cudaFuncAttributeMaxDynamicSharedMemorySize, AT_TOTAL);
    cudaFuncSetAttribute(proj_mma, cudaFuncAttributeMaxDynamicSharedMemorySize, P_TOTAL);

    prep<<<PREP_T / 256, 256>>>(x, qm, km, vm);
    qkv_mma<<<dim3(BS_/128, J_, 2), 256, QK_TOTAL>>>();
    attn_mma<<<INST_, 512, AT_TOTAL>>>();
    proj_mma<<<dim3(BS_/64, J_), 256, P_TOTAL>>>(x, proj, gamma, beta, out);
}

// round 13
// speedup vs baseline: 1.9350x; 1.0034x over previous
#include <cuda_runtime.h>
#include <cuda_bf16.h>
#include <stdint.h>

// Problem constants
#define B_  4
#define S_  512
#define J_  24
#define H_  128
#define NH_ 8
#define HS_ 16
#define BS_ (B_*S_)            // 2048 rows
#define INST_ (B_*NH_*J_)      // 768 attention instances
#define QKV_E (B_*NH_*J_*S_*HS_)   // 6291456 elements
#define QSCALE 0.3606737602222409f // 0.25 * log2(e)

// Scratch (static device globals — allocation-free)
__device__ __nv_bfloat16 g_xh[BS_*J_*H_];        // x split hi/lo
__device__ __nv_bfloat16 g_xl[BS_*J_*H_];
__device__ __nv_bfloat16 g_wh[3*J_*H_*H_];       // qkv weights [m][j][k][n]
__device__ __nv_bfloat16 g_wl[3*J_*H_*H_];
__device__ __nv_bfloat16 g_ph[J_*H_*H_];         // proj weights [j][k][n]
__device__ __nv_bfloat16 g_pl[J_*H_*H_];
__device__ __nv_bfloat16 g_qh[QKV_E], g_ql[QKV_E];   // q pre-scaled by QSCALE
__device__ __nv_bfloat16 g_kh[QKV_E], g_kl[QKV_E];
__device__ __nv_bfloat16 g_vh[QKV_E], g_vl[QKV_E];
__device__ __nv_bfloat16 g_aoh[BS_*J_*H_];       // attention out split hi/lo
__device__ __nv_bfloat16 g_aol[BS_*J_*H_];

// ===========================================================================
// Helpers (baseline PTX features only)
// ===========================================================================
__device__ __forceinline__ uint32_t smem_u32(const void* p) {
    uint32_t a;
    asm("{ .reg .u64 t; cvta.to.shared.u64 t, %1; cvt.u32.u64 %0, t; }"
        : "=r"(a) : "l"(p));
    return a;
}
__device__ __forceinline__ void ldsm_x4(uint32_t& r0, uint32_t& r1,
                                        uint32_t& r2, uint32_t& r3, uint32_t addr) {
    asm volatile("ldmatrix.sync.aligned.m8n8.x4.shared.b16 {%0,%1,%2,%3}, [%4];"
                 : "=r"(r0), "=r"(r1), "=r"(r2), "=r"(r3) : "r"(addr));
}
__device__ __forceinline__ void ldsm_x4_t(uint32_t& r0, uint32_t& r1,
                                          uint32_t& r2, uint32_t& r3, uint32_t addr) {
    asm volatile("ldmatrix.sync.aligned.m8n8.x4.trans.shared.b16 {%0,%1,%2,%3}, [%4];"
                 : "=r"(r0), "=r"(r1), "=r"(r2), "=r"(r3) : "r"(addr));
}
__device__ __forceinline__ void mma_bf16(float* c, const uint32_t a[4],
                                         uint32_t b0, uint32_t b1) {
    asm volatile(
        "mma.sync.aligned.m16n8k16.row.col.f32.bf16.bf16.f32 "
        "{%0,%1,%2,%3}, {%4,%5,%6,%7}, {%8,%9}, {%0,%1,%2,%3};"
        : "+f"(c[0]), "+f"(c[1]), "+f"(c[2]), "+f"(c[3])
        : "r"(a[0]), "r"(a[1]), "r"(a[2]), "r"(a[3]), "r"(b0), "r"(b1));
}
// split-fp32 -> (hi bf16x2, lo bf16x2); a -> low half, b -> high half
__device__ __forceinline__ void cvt_pair(float a, float b, uint32_t& hi, uint32_t& lo) {
    uint32_t h;
    asm("cvt.rn.bf16x2.f32 %0, %1, %2;" : "=r"(h) : "f"(b), "f"(a));
    float ha = __uint_as_float(h << 16);
    float hb = __uint_as_float(h & 0xffff0000u);
    float la = a - ha, lb = b - hb;
    asm("cvt.rn.bf16x2.f32 %0, %1, %2;" : "=r"(lo) : "f"(lb), "f"(la));
    hi = h;
}
__device__ __forceinline__ float ex2f(float x) {
    float r; asm("ex2.approx.f32 %0, %1;" : "=f"(r) : "f"(x)); return r;
}
__device__ __forceinline__ void cpa16(uint32_t dst, const void* src) {
    asm volatile("cp.async.cg.shared.global [%0], [%1], 16;" :: "r"(dst), "l"(src));
}
#define CP_COMMIT asm volatile("cp.async.commit_group;" ::: "memory")
#define CP_WAIT0  asm volatile("cp.async.wait_group 0;" ::: "memory")

#define SAB_B 272      // A row stride in bytes (136 bf16)
#define SBN   144      // B (transposed [k][n]) row stride in bytes

// ===========================================================================
// Kernel 0: prep — convert x, qkv weights and proj weights to split bf16.
// ===========================================================================
#define XQUAD (BS_*J_*H_/4)               // 1572864 float4s
#define WPAIR (3*NH_*J_*H_*HS_/2)         // 589824 pairs
#define PPAIR (J_*H_*H_/2)                // 196608 pairs
#define PREP_T ((XQUAD + WPAIR + PPAIR + 255) & ~255)

__global__ __launch_bounds__(256)
void prep(const float* __restrict__ x,
          const float* __restrict__ qm,
          const float* __restrict__ km,
          const float* __restrict__ vm,
          const float* __restrict__ proj)
{
    int t = blockIdx.x * 256 + threadIdx.x;
    if (t < XQUAD) {
        float4 v = ((const float4*)x)[t];
        uint32_t h01, l01, h23, l23;
        cvt_pair(v.x, v.y, h01, l01);
        cvt_pair(v.z, v.w, h23, l23);
        ((uint2*)g_xh)[t] = make_uint2(h01, h23);
        ((uint2*)g_xl)[t] = make_uint2(l01, l23);
    } else if (t < XQUAD + WPAIR) {
        int u  = t - XQUAD;
        int n2 = u & 63;  int u2 = u >> 6;
        int k  = u2 & 127; int u3 = u2 >> 7;
        int j  = u3 % J_;  int m  = u3 / J_;
        int n  = n2 * 2;
        const float* mat = (m == 0) ? qm : (m == 1 ? km : vm);
        const float2 w = *(const float2*)(mat +
            ((size_t)((n >> 4) * J_ + j) * H_ + k) * HS_ + (n & 15));
        uint32_t hi, lo;
        cvt_pair(w.x, w.y, hi, lo);
        size_t o = ((size_t)(m * J_ + j) * H_ + k) * H_ + n;
        *(uint32_t*)(g_wh + o) = hi;
        *(uint32_t*)(g_wl + o) = lo;
    } else if (t < XQUAD + WPAIR + PPAIR) {
        int u = t - XQUAD - WPAIR;      // proj is [j][k][n], n contiguous
        const float2 w = ((const float2*)proj)[u];
        uint32_t hi, lo;
        cvt_pair(w.x, w.y, hi, lo);
        ((uint32_t*)g_ph)[u] = hi;
        ((uint32_t*)g_pl)[u] = lo;
    }
}

// ===========================================================================
// Kernel 1: QKV projection. grid (16, 24, 2). block 256. cp.async staging
// from precomputed splits; B(m+1) copy overlapped with scatter(m).
// Outputs q (pre-scaled by QSCALE), k, v as split bf16.  (unchanged)
// ===========================================================================
#define QK_AHI 0
#define QK_ALO 34816
#define QK_BHI 69632
#define QK_BLO 88064
#define QK_TOTAL 106496

__global__ __launch_bounds__(256, 2)
void qkv_mma()
{
    extern __shared__ char smem[];
    const int j   = blockIdx.y;
    const int c0  = blockIdx.z * 64;
    const int r0  = blockIdx.x * 128;
    const int tid = threadIdx.x, wid = tid >> 5, lane = tid & 31;
    const uint32_t sb = smem_u32(smem);

    // --- async stage A (x rows r0..r0+127, hi+lo) ---
    #pragma unroll 4
    for (int i = tid; i < 4096; i += 256) {
        int buf = i >> 11;               // 0 hi, 1 lo
        int row = (i >> 4) & 127;
        int ch  = i & 15;
        const char* src = (const char*)(buf ? g_xl : g_xh)
            + ((size_t)(r0 + row) * J_ + j) * H_ * 2 + ch * 16;
        cpa16(sb + (buf ? QK_ALO : QK_AHI) + row * SAB_B + ch * 16, src);
    }
    // --- async stage B(0) ---
    #pragma unroll 4
    for (int i = tid; i < 2048; i += 256) {
        int buf = i >> 10;
        int k   = (i >> 3) & 127;
        int ch  = i & 7;
        const char* src = (const char*)(buf ? g_wl : g_wh)
            + (((size_t)(0 * J_ + j) * H_ + k) * H_ + c0) * 2 + ch * 16;
        cpa16(sb + (buf ? QK_BLO : QK_BHI) + k * SBN + ch * 16, src);
    }
    CP_COMMIT;
    CP_WAIT0;
    __syncthreads();

    const int warpM = wid & 3, warpN = wid >> 2;
    const int ar = lane & 15, ac = (lane >> 4) << 3;
    const int bg = lane >> 3, blp = lane & 7;
    const int kt = ((bg & 1) << 3) + blp;
    const int nb = (bg >> 1) << 4;
    const uint32_t aRow = (uint32_t)(warpM * 32 + ar) * SAB_B;

    for (int m = 0; m < 3; m++) {
        float acc[2][4][4];
        #pragma unroll
        for (int mt = 0; mt < 2; mt++)
            #pragma unroll
            for (int nt = 0; nt < 4; nt++)
                #pragma unroll
                for (int i = 0; i < 4; i++) acc[mt][nt][i] = 0.f;

        #pragma unroll 1
        for (int sp = 0; sp < 3; sp++) {
            const uint32_t aB = sb + ((sp == 2) ? QK_ALO : QK_AHI) + aRow;
            const uint32_t bB = sb + ((sp == 1) ? QK_BLO : QK_BHI);
            #pragma unroll
            for (int k0 = 0; k0 < 8; k0++) {
                uint32_t a[2][4];
                #pragma unroll
                for (int mt = 0; mt < 2; mt++)
                    ldsm_x4(a[mt][0], a[mt][1], a[mt][2], a[mt][3],
                            aB + (uint32_t)(mt * 16) * SAB_B + (uint32_t)(k0 * 16 + ac) * 2);
                #pragma unroll
                for (int ntp = 0; ntp < 2; ntp++) {
                    uint32_t b[4];
                    ldsm_x4_t(b[0], b[1], b[2], b[3],
                              bB + (uint32_t)(k0 * 16 + kt) * SBN
                                 + (uint32_t)(warpN * 32 + ntp * 16) * 2 + nb);
                    #pragma unroll
                    for (int mt = 0; mt < 2; mt++) {
                        mma_bf16(acc[mt][ntp * 2],     a[mt], b[0], b[1]);
                        mma_bf16(acc[mt][ntp * 2 + 1], a[mt], b[2], b[3]);
                    }
                }
            }
        }

        if (m < 2) {
            __syncthreads();     // all warps done reading B(m)
            #pragma unroll 4
            for (int i = tid; i < 2048; i += 256) {
                int buf = i >> 10;
                int k   = (i >> 3) & 127;
                int ch  = i & 7;
                const char* src = (const char*)(buf ? g_wl : g_wh)
                    + (((size_t)((m + 1) * J_ + j) * H_ + k) * H_ + c0) * 2 + ch * 16;
                cpa16(sb + (buf ? QK_BLO : QK_BHI) + k * SBN + ch * 16, src);
            }
            CP_COMMIT;
        }

        // scatter (overlaps async B copy): split hi/lo bf16, q pre-scaled
        __nv_bfloat16* outh = (m == 0) ? g_qh : (m == 1 ? g_kh : g_vh);
        __nv_bfloat16* outl = (m == 0) ? g_ql : (m == 1 ? g_kl : g_vl);
        const float sc = (m == 0) ? QSCALE : 1.f;
        #pragma unroll
        for (int mt = 0; mt < 2; mt++) {
            int rbase = r0 + warpM * 32 + mt * 16 + (lane >> 2);
            #pragma unroll
            for (int nt = 0; nt < 4; nt++) {
                int c = c0 + warpN * 32 + nt * 8 + ((lane & 3) << 1);
                int n = c >> 4, d = c & 15;
                #pragma unroll
                for (int h = 0; h < 2; h++) {
                    int r = rbase + h * 8;
                    int b = r >> 9, sI = r & 511;
                    size_t idx = (((size_t)(b * NH_ + n) * J_ + j) * S_ + sI) * HS_ + d;
                    uint32_t hi, lo;
                    cvt_pair(acc[mt][nt][h * 2] * sc, acc[mt][nt][h * 2 + 1] * sc, hi, lo);
                    *(uint32_t*)(outh + idx) = hi;
                    *(uint32_t*)(outl + idx) = lo;
                }
            }
        }
        if (m < 2) { CP_WAIT0; __syncthreads(); }
    }
}

// ===========================================================================
// Kernel 2: tensor-core causal attention. block 512 (16 warps, band-permuted).
// Epilogue writes attention-out as split hi/lo bf16 (for proj cp.async).
// ===========================================================================
#define KSWZ(r, off) ((((uint32_t)(r)) << 5) + \
                      (((uint32_t)(off)) ^ ((((uint32_t)(r) >> 2) & 1u) << 4)))
#define AT_TOTAL 65536

__global__ __launch_bounds__(512, 1)
void attn_mma()
{
    extern __shared__ char smem[];
    const int inst = blockIdx.x;
    const int j  = inst % J_;
    const int bn = inst / J_;
    const int n  = bn % NH_;
    const int b  = bn / NH_;
    const size_t base = (size_t)inst * S_ * HS_;   // element base

    const int tid = threadIdx.x, wid = tid >> 5, lane = tid & 31;
    const uint32_t sbase = smem_u32(smem);

    // Stage Kh,Kl,Vh,Vl via cp.async (buffers at sbase + buf*16384)
    #pragma unroll 8
    for (int i = tid; i < 4096; i += 512) {
        int buf = i >> 10;
        int row = (i >> 1) & 511;
        int ch  = i & 1;
        const char* srcb = (buf == 0) ? (const char*)g_kh :
                           (buf == 1) ? (const char*)g_kl :
                           (buf == 2) ? (const char*)g_vh : (const char*)g_vl;
        cpa16(sbase + buf * 16384 + KSWZ(row, ch << 4),
              srcb + base * 2 + row * 32 + ch * 16);
    }
    CP_COMMIT;
    CP_WAIT0;
    __syncthreads();

    // Warp -> band permutation: SMSP g gets bands {g, 7-g, 8+g, 15-g}
    const int g  = wid & 3, iq = wid >> 2;
    const int band = (iq == 0) ? g : (iq == 1) ? (7 - g) : (iq == 2) ? (8 + g) : (15 - g);
    const int R0 = band * 32;
    const int qrow = lane >> 2, qcol = (lane & 3) << 1;

    // Q fragments: direct uint32 loads of pre-scaled splits
    uint32_t qh[2][4], ql[2][4];
    #pragma unroll
    for (int mt = 0; mt < 2; mt++) {
        size_t eb = base + (size_t)(R0 + qrow + mt * 16) * HS_ + qcol;
        qh[mt][0] = *(const uint32_t*)(g_qh + eb);
        qh[mt][1] = *(const uint32_t*)(g_qh + eb + 8 * HS_);
        qh[mt][2] = *(const uint32_t*)(g_qh + eb + 8);
        qh[mt][3] = *(const uint32_t*)(g_qh + eb + 8 * HS_ + 8);
        ql[mt][0] = *(const uint32_t*)(g_ql + eb);
        ql[mt][1] = *(const uint32_t*)(g_ql + eb + 8 * HS_);
        ql[mt][2] = *(const uint32_t*)(g_ql + eb + 8);
        ql[mt][3] = *(const uint32_t*)(g_ql + eb + 8 * HS_ + 8);
    }

    float O[2][2][4];
    #pragma unroll
    for (int mt = 0; mt < 2; mt++)
        #pragma unroll
        for (int dt = 0; dt < 2; dt++)
            #pragma unroll
            for (int i = 0; i < 4; i++) O[mt][dt][i] = 0.f;
    float rs[2][2] = {{0.f, 0.f}, {0.f, 0.f}};

    const uint32_t Kh = sbase,          Kl = sbase + 16384;
    const uint32_t Vh = sbase + 32768,  Vl = sbase + 49152;

    const int bg = lane >> 3, bl = lane & 7;
    const int kn = ((bg >> 1) << 3) + bl;
    const int kk = (bg & 1) << 3;
    const int vt = ((bg & 1) << 3) + bl;
    const int vd = (bg >> 1) << 4;

    const int last = 2 * band;

    for (int ntp = 0; ntp <= last; ntp++) {
        const int C0 = ntp << 4;
        uint32_t kh[4], klr[4], vh[4], vlr[4];
        ldsm_x4(kh[0], kh[1], kh[2], kh[3],     Kh + KSWZ(C0 + kn, kk * 2));
        ldsm_x4(klr[0], klr[1], klr[2], klr[3], Kl + KSWZ(C0 + kn, kk * 2));
        ldsm_x4_t(vh[0], vh[1], vh[2], vh[3],   Vh + KSWZ(C0 + vt, vd));
        ldsm_x4_t(vlr[0], vlr[1], vlr[2], vlr[3], Vl + KSWZ(C0 + vt, vd));

        float S[2][2][4];
        #pragma unroll
        for (int mt = 0; mt < 2; mt++)
            #pragma unroll
            for (int q2 = 0; q2 < 2; q2++)
                #pragma unroll
                for (int i = 0; i < 4; i++) S[mt][q2][i] = 0.f;
        #pragma unroll
        for (int mt = 0; mt < 2; mt++) {
            mma_bf16(S[mt][0], qh[mt], kh[0], kh[1]);
            mma_bf16(S[mt][1], qh[mt], kh[2], kh[3]);
            mma_bf16(S[mt][0], ql[mt], kh[0], kh[1]);
            mma_bf16(S[mt][1], ql[mt], kh[2], kh[3]);
            mma_bf16(S[mt][0], qh[mt], klr[0], klr[1]);
            mma_bf16(S[mt][1], qh[mt], klr[2], klr[3]);
        }

        #pragma unroll
        for (int mt = 0; mt < 2; mt++) {
            float p[8];
            if (mt == 0 && ntp == last) {
                const int row0 = R0 + qrow;
                const int col0 = C0 + qcol;
                p[0] = (col0     <= row0    ) ? ex2f(S[0][0][0]) : 0.f;
                p[1] = (col0 + 1 <= row0    ) ? ex2f(S[0][0][1]) : 0.f;
                p[2] = (col0     <= row0 + 8) ? ex2f(S[0][0][2]) : 0.f;
                p[3] = (col0 + 1 <= row0 + 8) ? ex2f(S[0][0][3]) : 0.f;
                p[4] = (col0 + 8 <= row0    ) ? ex2f(S[0][1][0]) : 0.f;
                p[5] = (col0 + 9 <= row0    ) ? ex2f(S[0][1][1]) : 0.f;
                p[6] = (col0 + 8 <= row0 + 8) ? ex2f(S[0][1][2]) : 0.f;
                p[7] = (col0 + 9 <= row0 + 8) ? ex2f(S[0][1][3]) : 0.f;
            } else {
                p[0] = ex2f(S[mt][0][0]);
                p[1] = ex2f(S[mt][0][1]);
                p[2] = ex2f(S[mt][0][2]);
                p[3] = ex2f(S[mt][0][3]);
                p[4] = ex2f(S[mt][1][0]);
                p[5] = ex2f(S[mt][1][1]);
                p[6] = ex2f(S[mt][1][2]);
                p[7] = ex2f(S[mt][1][3]);
            }
            rs[mt][0] += (p[0] + p[1]) + (p[4] + p[5]);
            rs[mt][1] += (p[2] + p[3]) + (p[6] + p[7]);

            uint32_t ph[4], pl[4];
            cvt_pair(p[0], p[1], ph[0], pl[0]);
            cvt_pair(p[2], p[3], ph[1], pl[1]);
            cvt_pair(p[4], p[5], ph[2], pl[2]);
            cvt_pair(p[6], p[7], ph[3], pl[3]);

            mma_bf16(O[mt][0], ph, vh[0], vh[1]);
            mma_bf16(O[mt][1], ph, vh[2], vh[3]);
            mma_bf16(O[mt][0], pl, vh[0], vh[1]);
            mma_bf16(O[mt][1], pl, vh[2], vh[3]);
            mma_bf16(O[mt][0], ph, vlr[0], vlr[1]);
            mma_bf16(O[mt][1], ph, vlr[2], vlr[3]);
        }
    }

    // Epilogue tile: ntp = last+1, mt = 1 only (diagonal)
    {
        const int C0 = (last + 1) << 4;
        uint32_t kh[4], klr[4], vh[4], vlr[4];
        ldsm_x4(kh[0], kh[1], kh[2], kh[3],     Kh + KSWZ(C0 + kn, kk * 2));
        ldsm_x4(klr[0], klr[1], klr[2], klr[3], Kl + KSWZ(C0 + kn, kk * 2));
        ldsm_x4_t(vh[0], vh[1], vh[2], vh[3],   Vh + KSWZ(C0 + vt, vd));
        ldsm_x4_t(vlr[0], vlr[1], vlr[2], vlr[3], Vl + KSWZ(C0 + vt, vd));

        float S0[4] = {0.f,0.f,0.f,0.f}, S1[4] = {0.f,0.f,0.f,0.f};
        mma_bf16(S0, qh[1], kh[0], kh[1]);
        mma_bf16(S1, qh[1], kh[2], kh[3]);
        mma_bf16(S0, ql[1], kh[0], kh[1]);
        mma_bf16(S1, ql[1], kh[2], kh[3]);
        mma_bf16(S0, qh[1], klr[0], klr[1]);
        mma_bf16(S1, qh[1], klr[2], klr[3]);

        const int row0 = R0 + 16 + qrow;
        const int col0 = C0 + qcol;
        float p[8];
        p[0] = (col0     <= row0    ) ? ex2f(S0[0]) : 0.f;
        p[1] = (col0 + 1 <= row0    ) ? ex2f(S0[1]) : 0.f;
        p[2] = (col0     <= row0 + 8) ? ex2f(S0[2]) : 0.f;
        p[3] = (col0 + 1 <= row0 + 8) ? ex2f(S0[3]) : 0.f;
        p[4] = (col0 + 8 <= row0    ) ? ex2f(S1[0]) : 0.f;
        p[5] = (col0 + 9 <= row0    ) ? ex2f(S1[1]) : 0.f;
        p[6] = (col0 + 8 <= row0 + 8) ? ex2f(S1[2]) : 0.f;
        p[7] = (col0 + 9 <= row0 + 8) ? ex2f(S1[3]) : 0.f;
        rs[1][0] += (p[0] + p[1]) + (p[4] + p[5]);
        rs[1][1] += (p[2] + p[3]) + (p[6] + p[7]);

        uint32_t ph[4], pl[4];
        cvt_pair(p[0], p[1], ph[0], pl[0]);
        cvt_pair(p[2], p[3], ph[1], pl[1]);
        cvt_pair(p[4], p[5], ph[2], pl[2]);
        cvt_pair(p[6], p[7], ph[3], pl[3]);

        mma_bf16(O[1][0], ph, vh[0], vh[1]);
        mma_bf16(O[1][1], ph, vh[2], vh[3]);
        mma_bf16(O[1][0], pl, vh[0], vh[1]);
        mma_bf16(O[1][1], pl, vh[2], vh[3]);
        mma_bf16(O[1][0], ph, vlr[0], vlr[1]);
        mma_bf16(O[1][1], ph, vlr[2], vlr[3]);
    }

    // Row sums: reduce, normalize, write split hi/lo bf16 attention-out.
    #pragma unroll
    for (int mt = 0; mt < 2; mt++) {
        float s0 = rs[mt][0], s1 = rs[mt][1];
        s0 += __shfl_xor_sync(0xffffffffu, s0, 1);
        s0 += __shfl_xor_sync(0xffffffffu, s0, 2);
        s1 += __shfl_xor_sync(0xffffffffu, s1, 1);
        s1 += __shfl_xor_sync(0xffffffffu, s1, 2);
        const float i0 = 1.f / s0, i1 = 1.f / s1;
        const int row = R0 + mt * 16 + (lane >> 2);
        const int dc  = (lane & 3) << 1;
        #pragma unroll
        for (int dt = 0; dt < 2; dt++) {
            const int d = dt * 8 + dc;
            size_t i0x = ((size_t)(b * S_ + row)     * J_ + j) * H_ + n * HS_ + d;
            size_t i1x = ((size_t)(b * S_ + row + 8) * J_ + j) * H_ + n * HS_ + d;
            uint32_t hi, lo;
            cvt_pair(O[mt][dt][0] * i0, O[mt][dt][1] * i0, hi, lo);
            *(uint32_t*)(g_aoh + i0x) = hi;
            *(uint32_t*)(g_aol + i0x) = lo;
            cvt_pair(O[mt][dt][2] * i1, O[mt][dt][3] * i1, hi, lo);
            *(uint32_t*)(g_aoh + i1x) = hi;
            *(uint32_t*)(g_aol + i1x) = lo;
        }
    }
}

// ===========================================================================
// Kernel 3: output projection + residual + LayerNorm.
// cp.async staging from pre-split attention-out and proj weights — zero
// conversion math in-kernel. grid (32, 24), 64-row tiles, 3 CTAs/SM.
// ===========================================================================
#define P_AHI 0
#define P_ALO 17408
#define P_BHI 34816
#define P_BLO 53248
#define P_TOTAL 71680

__global__ __launch_bounds__(256, 3)
void proj_mma(const float* __restrict__ x,
              const float* __restrict__ gamma,
              const float* __restrict__ beta,
              float* __restrict__ out)
{
    extern __shared__ char smem[];
    const int j   = blockIdx.y;
    const int r0  = blockIdx.x * 64;
    const int tid = threadIdx.x, wid = tid >> 5, lane = tid & 31;
    const uint32_t sb = smem_u32(smem);

    // --- async stage A (attention-out rows r0..r0+63, hi+lo): 256B/row ---
    #pragma unroll 4
    for (int i = tid; i < 2048; i += 256) {
        int buf = i >> 10;               // 0 hi, 1 lo
        int row = (i >> 4) & 63;
        int ch  = i & 15;
        const char* src = (const char*)(buf ? g_aol : g_aoh)
            + ((size_t)(r0 + row) * J_ + j) * H_ * 2 + ch * 16;
        cpa16(sb + (buf ? P_ALO : P_AHI) + row * SAB_B + ch * 16, src);
    }
    // --- async stage B(0): proj cols 0..63, 128B per k-row = 8 chunks ---
    #pragma unroll 4
    for (int i = tid; i < 2048; i += 256) {
        int buf = i >> 10;
        int k   = (i >> 3) & 127;
        int ch  = i & 7;
        const char* src = (const char*)(buf ? g_pl : g_ph)
            + ((size_t)j * H_ * H_ + (size_t)k * H_) * 2 + ch * 16;
        cpa16(sb + (buf ? P_BLO : P_BHI) + k * SBN + ch * 16, src);
    }
    CP_COMMIT;
    CP_WAIT0;
    __syncthreads();

    const int warpM = wid & 3, warpN = wid >> 2;
    const int ar = lane & 15, ac = (lane >> 4) << 3;
    const int bg = lane >> 3, blp = lane & 7;
    const int kt = ((bg & 1) << 3) + blp;
    const int nb = (bg >> 1) << 4;
    const uint32_t aRow = (uint32_t)(warpM * 16 + ar) * SAB_B;

    float acc[2][4][4];   // [pass][ntile][frag]
    #pragma unroll
    for (int p = 0; p < 2; p++)
        #pragma unroll
        for (int nt = 0; nt < 4; nt++)
            #pragma unroll
            for (int i = 0; i < 4; i++) acc[p][nt][i] = 0.f;

    #pragma unroll 1
    for (int p = 0; p < 2; p++) {
        #pragma unroll 1
        for (int sp = 0; sp < 3; sp++) {
            const uint32_t aB = sb + ((sp == 2) ? P_ALO : P_AHI) + aRow;
            const uint32_t bB = sb + ((sp == 1) ? P_BLO : P_BHI);
            #pragma unroll
            for (int k0 = 0; k0 < 8; k0++) {
                uint32_t a[4];
                ldsm_x4(a[0], a[1], a[2], a[3], aB + (uint32_t)(k0 * 16 + ac) * 2);
                #pragma unroll
                for (int ntp = 0; ntp < 2; ntp++) {
                    uint32_t bfr[4];
                    ldsm_x4_t(bfr[0], bfr[1], bfr[2], bfr[3],
                              bB + (uint32_t)(k0 * 16 + kt) * SBN
                                 + (uint32_t)(warpN * 32 + ntp * 16) * 2 + nb);
                    mma_bf16(acc[p][ntp * 2],     a, bfr[0], bfr[1]);
                    mma_bf16(acc[p][ntp * 2 + 1], a, bfr[2], bfr[3]);
                }
            }
        }
        if (p == 0) {
            __syncthreads();     // done reading B(0)
            // async stage B(1): proj cols 64..127, 8 chunks per k-row
            #pragma unroll 4
            for (int i = tid; i < 2048; i += 256) {
                int buf = i >> 10;
                int k   = (i >> 3) & 127;
                int ch  = i & 7;
                const char* src = (const char*)(buf ? g_pl : g_ph)
                    + ((size_t)j * H_ * H_ + (size_t)k * H_ + 64) * 2 + ch * 16;
                cpa16(sb + (buf ? P_BLO : P_BHI) + k * SBN + ch * 16, src);
            }
            CP_COMMIT;
            CP_WAIT0;
            __syncthreads();
        }
    }

    // Stage C into smem (aliases A region): [64][132] floats
    __syncthreads();
    float* Cs = (float*)smem;
    #pragma unroll
    for (int p = 0; p < 2; p++) {
        int rb = warpM * 16 + (lane >> 2);
        #pragma unroll
        for (int nt = 0; nt < 4; nt++) {
            int col = p * 64 + warpN * 32 + nt * 8 + ((lane & 3) << 1);
            #pragma unroll
            for (int h = 0; h < 2; h++) {
                Cs[(rb + h * 8) * 132 + col]     = acc[p][nt][h * 2];
                Cs[(rb + h * 8) * 132 + col + 1] = acc[p][nt][h * 2 + 1];
            }
        }
    }
    __syncthreads();

    // Residual + LN: 4 threads per row (32 cols each), combine via shfl.
    {
        const int row = tid >> 2;
        const int q   = tid & 3;
        const int r   = r0 + row;
        const float* xr = x + ((size_t)r * J_ + j) * H_ + q * 32;
        float* crow     = Cs + row * 132 + q * 32;

        float sum = 0.f, sq = 0.f;
        #pragma unroll
        for (int i = 0; i < 8; i++) {
            float4 c4 = *(float4*)(crow + i * 4);
            float4 xv = *(const float4*)(xr + i * 4);
            c4.x += xv.x; c4.y += xv.y; c4.z += xv.z; c4.w += xv.w;
            *(float4*)(crow + i * 4) = c4;
            sum += c4.x + c4.y + c4.z + c4.w;
            sq  += c4.x*c4.x + c4.y*c4.y + c4.z*c4.z + c4.w*c4.w;
        }
        sum += __shfl_xor_sync(0xffffffffu, sum, 1);
        sum += __shfl_xor_sync(0xffffffffu, sum, 2);
        sq  += __shfl_xor_sync(0xffffffffu, sq, 1);
        sq  += __shfl_xor_sync(0xffffffffu, sq, 2);
        const float mu   = sum * (1.f / 128.f);
        const float var  = sq * (1.f / 128.f) - mu * mu;
        const float rstd = rsqrtf(var + 1e-5f);

        float* orow = out + ((size_t)r * J_ + j) * H_ + q * 32;
        const float* gp  = gamma + q * 32;
        const float* bp2 = beta  + q * 32;
        #pragma unroll
        for (int i = 0; i < 8; i++) {
            float4 c4 = *(float4*)(crow + i * 4);
            float4 o;
            o.x = (c4.x - mu) * rstd * gp[i*4+0] + bp2[i*4+0];
            o.y = (c4.y - mu) * rstd * gp[i*4+1] + bp2[i*4+1];
            o.z = (c4.z - mu) * rstd * gp[i*4+2] + bp2[i*4+2];
            o.w = (c4.w - mu) * rstd * gp[i*4+3] + bp2[i*4+3];
            *(float4*)(orow + i * 4) = o;
        }
    }
}

// ===========================================================================
extern "C" void kernel_launch(void* const* d_in, const int* in_sizes, int n_in,
                              void* d_out, int out_size)
{
    const float* x     = (const float*)d_in[0];
    // d_in[1]: additive causal mask (= triu(-1e9)) — implemented as causal skip.
    const float* qm    = (const float*)d_in[2];
    const float* km    = (const float*)d_in[3];
    const float* vm    = (const float*)d_in[4];
    const float* proj  = (const float*)d_in[5];
    const float* gamma = (const float*)d_in[6];
    const float* beta  = (const float*)d_in[7];
    float* out = (float*)d_out;

    cudaFuncSetAttribute(qkv_mma,  cudaFuncAttributeMaxDynamicSharedMemorySize, QK_TOTAL);
    cudaFuncSetAttribute(attn_mma, cudaFuncAttributeMaxDynamicSharedMemorySize, AT_TOTAL);
    cudaFuncSetAttribute(proj_mma, cudaFuncAttributeMaxDynamicSharedMemorySize, P_TOTAL);

    prep<<<PREP_T / 256, 256>>>(x, qm, km, vm, proj);
    qkv_mma<<<dim3(BS_/128, J_, 2), 256, QK_TOTAL>>>();
    attn_mma<<<INST_, 512, AT_TOTAL>>>();
    proj_mma<<<dim3(BS_/64, J_), 256, P_TOTAL>>>(x, gamma, beta, out);
}

// round 14
// speedup vs baseline: 2.1358x; 1.1038x over previous
#include <cuda_runtime.h>
#include <cuda_bf16.h>
#include <stdint.h>

// Problem constants
#define B_  4
#define S_  512
#define J_  24
#define H_  128
#define NH_ 8
#define HS_ 16
#define BS_ (B_*S_)            // 2048 rows
#define INST_ (B_*NH_*J_)      // 768 attention instances
#define QKV_E (B_*NH_*J_*S_*HS_)   // 6291456 elements
#define QSCALE 0.3606737602222409f // 0.25 * log2(e)

// Scratch (static device globals — allocation-free)
__device__ __nv_bfloat16 g_xh[BS_*J_*H_];        // x split hi/lo
__device__ __nv_bfloat16 g_xl[BS_*J_*H_];
__device__ __nv_bfloat16 g_wh[3*J_*H_*H_];       // qkv weights [m][j][k][n]
__device__ __nv_bfloat16 g_wl[3*J_*H_*H_];
__device__ __nv_bfloat16 g_ph[J_*H_*H_];         // proj weights [j][k][n]
__device__ __nv_bfloat16 g_pl[J_*H_*H_];
__device__ __nv_bfloat16 g_qh[QKV_E], g_ql[QKV_E];   // q pre-scaled by QSCALE
__device__ __nv_bfloat16 g_kh[QKV_E], g_kl[QKV_E];
__device__ __nv_bfloat16 g_vh[QKV_E], g_vl[QKV_E];
__device__ __nv_bfloat16 g_aoh[BS_*J_*H_];       // attention out split hi/lo
__device__ __nv_bfloat16 g_aol[BS_*J_*H_];

// ===========================================================================
// Helpers (baseline PTX features only)
// ===========================================================================
__device__ __forceinline__ uint32_t smem_u32(const void* p) {
    uint32_t a;
    asm("{ .reg .u64 t; cvta.to.shared.u64 t, %1; cvt.u32.u64 %0, t; }"
        : "=r"(a) : "l"(p));
    return a;
}
__device__ __forceinline__ void ldsm_x4(uint32_t& r0, uint32_t& r1,
                                        uint32_t& r2, uint32_t& r3, uint32_t addr) {
    asm volatile("ldmatrix.sync.aligned.m8n8.x4.shared.b16 {%0,%1,%2,%3}, [%4];"
                 : "=r"(r0), "=r"(r1), "=r"(r2), "=r"(r3) : "r"(addr));
}
__device__ __forceinline__ void ldsm_x4_t(uint32_t& r0, uint32_t& r1,
                                          uint32_t& r2, uint32_t& r3, uint32_t addr) {
    asm volatile("ldmatrix.sync.aligned.m8n8.x4.trans.shared.b16 {%0,%1,%2,%3}, [%4];"
                 : "=r"(r0), "=r"(r1), "=r"(r2), "=r"(r3) : "r"(addr));
}
__device__ __forceinline__ void mma_bf16(float* c, const uint32_t a[4],
                                         uint32_t b0, uint32_t b1) {
    asm volatile(
        "mma.sync.aligned.m16n8k16.row.col.f32.bf16.bf16.f32 "
        "{%0,%1,%2,%3}, {%4,%5,%6,%7}, {%8,%9}, {%0,%1,%2,%3};"
        : "+f"(c[0]), "+f"(c[1]), "+f"(c[2]), "+f"(c[3])
        : "r"(a[0]), "r"(a[1]), "r"(a[2]), "r"(a[3]), "r"(b0), "r"(b1));
}
// split-fp32 -> (hi bf16x2, lo bf16x2); a -> low half, b -> high half
__device__ __forceinline__ void cvt_pair(float a, float b, uint32_t& hi, uint32_t& lo) {
    uint32_t h;
    asm("cvt.rn.bf16x2.f32 %0, %1, %2;" : "=r"(h) : "f"(b), "f"(a));
    float ha = __uint_as_float(h << 16);
    float hb = __uint_as_float(h & 0xffff0000u);
    float la = a - ha, lb = b - hb;
    asm("cvt.rn.bf16x2.f32 %0, %1, %2;" : "=r"(lo) : "f"(lb), "f"(la));
    hi = h;
}
__device__ __forceinline__ float ex2f(float x) {
    float r; asm("ex2.approx.f32 %0, %1;" : "=f"(r) : "f"(x)); return r;
}
__device__ __forceinline__ void cpa16(uint32_t dst, const void* src) {
    asm volatile("cp.async.cg.shared.global [%0], [%1], 16;" :: "r"(dst), "l"(src));
}
#define CP_COMMIT asm volatile("cp.async.commit_group;" ::: "memory")
#define CP_WAIT0  asm volatile("cp.async.wait_group 0;" ::: "memory")
#define CP_WAIT1  asm volatile("cp.async.wait_group 1;" ::: "memory")

#define SAB_B 272      // A row stride in bytes (136 bf16)
#define SBN   144      // B (transposed [k][n]) row stride in bytes

// ===========================================================================
// Kernel 0: prep — convert x, qkv weights and proj weights to split bf16.
// ===========================================================================
#define XQUAD (BS_*J_*H_/4)               // 1572864 float4s
#define WPAIR (3*NH_*J_*H_*HS_/2)         // 589824 pairs
#define PPAIR (J_*H_*H_/2)                // 196608 pairs
#define PREP_T ((XQUAD + WPAIR + PPAIR + 255) & ~255)

__global__ __launch_bounds__(256)
void prep(const float* __restrict__ x,
          const float* __restrict__ qm,
          const float* __restrict__ km,
          const float* __restrict__ vm,
          const float* __restrict__ proj)
{
    int t = blockIdx.x * 256 + threadIdx.x;
    if (t < XQUAD) {
        float4 v = ((const float4*)x)[t];
        uint32_t h01, l01, h23, l23;
        cvt_pair(v.x, v.y, h01, l01);
        cvt_pair(v.z, v.w, h23, l23);
        ((uint2*)g_xh)[t] = make_uint2(h01, h23);
        ((uint2*)g_xl)[t] = make_uint2(l01, l23);
    } else if (t < XQUAD + WPAIR) {
        int u  = t - XQUAD;
        int n2 = u & 63;  int u2 = u >> 6;
        int k  = u2 & 127; int u3 = u2 >> 7;
        int j  = u3 % J_;  int m  = u3 / J_;
        int n  = n2 * 2;
        const float* mat = (m == 0) ? qm : (m == 1 ? km : vm);
        const float2 w = *(const float2*)(mat +
            ((size_t)((n >> 4) * J_ + j) * H_ + k) * HS_ + (n & 15));
        uint32_t hi, lo;
        cvt_pair(w.x, w.y, hi, lo);
        size_t o = ((size_t)(m * J_ + j) * H_ + k) * H_ + n;
        *(uint32_t*)(g_wh + o) = hi;
        *(uint32_t*)(g_wl + o) = lo;
    } else if (t < XQUAD + WPAIR + PPAIR) {
        int u = t - XQUAD - WPAIR;      // proj is [j][k][n], n contiguous
        const float2 w = ((const float2*)proj)[u];
        uint32_t hi, lo;
        cvt_pair(w.x, w.y, hi, lo);
        ((uint32_t*)g_ph)[u] = hi;
        ((uint32_t*)g_pl)[u] = lo;
    }
}

// ===========================================================================
// Kernel 1: QKV projection. grid (16, 24, 2). block 256. cp.async staging
// from precomputed splits; B(m+1) copy overlapped with scatter(m).
// Outputs q (pre-scaled by QSCALE), k, v as split bf16.  (unchanged)
// ===========================================================================
#define QK_AHI 0
#define QK_ALO 34816
#define QK_BHI 69632
#define QK_BLO 88064
#define QK_TOTAL 106496

__global__ __launch_bounds__(256, 2)
void qkv_mma()
{
    extern __shared__ char smem[];
    const int j   = blockIdx.y;
    const int c0  = blockIdx.z * 64;
    const int r0  = blockIdx.x * 128;
    const int tid = threadIdx.x, wid = tid >> 5, lane = tid & 31;
    const uint32_t sb = smem_u32(smem);

    // --- async stage A (x rows r0..r0+127, hi+lo) ---
    #pragma unroll 4
    for (int i = tid; i < 4096; i += 256) {
        int buf = i >> 11;               // 0 hi, 1 lo
        int row = (i >> 4) & 127;
        int ch  = i & 15;
        const char* src = (const char*)(buf ? g_xl : g_xh)
            + ((size_t)(r0 + row) * J_ + j) * H_ * 2 + ch * 16;
        cpa16(sb + (buf ? QK_ALO : QK_AHI) + row * SAB_B + ch * 16, src);
    }
    // --- async stage B(0) ---
    #pragma unroll 4
    for (int i = tid; i < 2048; i += 256) {
        int buf = i >> 10;
        int k   = (i >> 3) & 127;
        int ch  = i & 7;
        const char* src = (const char*)(buf ? g_wl : g_wh)
            + (((size_t)(0 * J_ + j) * H_ + k) * H_ + c0) * 2 + ch * 16;
        cpa16(sb + (buf ? QK_BLO : QK_BHI) + k * SBN + ch * 16, src);
    }
    CP_COMMIT;
    CP_WAIT0;
    __syncthreads();

    const int warpM = wid & 3, warpN = wid >> 2;
    const int ar = lane & 15, ac = (lane >> 4) << 3;
    const int bg = lane >> 3, blp = lane & 7;
    const int kt = ((bg & 1) << 3) + blp;
    const int nb = (bg >> 1) << 4;
    const uint32_t aRow = (uint32_t)(warpM * 32 + ar) * SAB_B;

    for (int m = 0; m < 3; m++) {
        float acc[2][4][4];
        #pragma unroll
        for (int mt = 0; mt < 2; mt++)
            #pragma unroll
            for (int nt = 0; nt < 4; nt++)
                #pragma unroll
                for (int i = 0; i < 4; i++) acc[mt][nt][i] = 0.f;

        #pragma unroll 1
        for (int sp = 0; sp < 3; sp++) {
            const uint32_t aB = sb + ((sp == 2) ? QK_ALO : QK_AHI) + aRow;
            const uint32_t bB = sb + ((sp == 1) ? QK_BLO : QK_BHI);
            #pragma unroll
            for (int k0 = 0; k0 < 8; k0++) {
                uint32_t a[2][4];
                #pragma unroll
                for (int mt = 0; mt < 2; mt++)
                    ldsm_x4(a[mt][0], a[mt][1], a[mt][2], a[mt][3],
                            aB + (uint32_t)(mt * 16) * SAB_B + (uint32_t)(k0 * 16 + ac) * 2);
                #pragma unroll
                for (int ntp = 0; ntp < 2; ntp++) {
                    uint32_t b[4];
                    ldsm_x4_t(b[0], b[1], b[2], b[3],
                              bB + (uint32_t)(k0 * 16 + kt) * SBN
                                 + (uint32_t)(warpN * 32 + ntp * 16) * 2 + nb);
                    #pragma unroll
                    for (int mt = 0; mt < 2; mt++) {
                        mma_bf16(acc[mt][ntp * 2],     a[mt], b[0], b[1]);
                        mma_bf16(acc[mt][ntp * 2 + 1], a[mt], b[2], b[3]);
                    }
                }
            }
        }

        if (m < 2) {
            __syncthreads();     // all warps done reading B(m)
            #pragma unroll 4
            for (int i = tid; i < 2048; i += 256) {
                int buf = i >> 10;
                int k   = (i >> 3) & 127;
                int ch  = i & 7;
                const char* src = (const char*)(buf ? g_wl : g_wh)
                    + (((size_t)((m + 1) * J_ + j) * H_ + k) * H_ + c0) * 2 + ch * 16;
                cpa16(sb + (buf ? QK_BLO : QK_BHI) + k * SBN + ch * 16, src);
            }
            CP_COMMIT;
        }

        // scatter (overlaps async B copy): split hi/lo bf16, q pre-scaled
        __nv_bfloat16* outh = (m == 0) ? g_qh : (m == 1 ? g_kh : g_vh);
        __nv_bfloat16* outl = (m == 0) ? g_ql : (m == 1 ? g_kl : g_vl);
        const float sc = (m == 0) ? QSCALE : 1.f;
        #pragma unroll
        for (int mt = 0; mt < 2; mt++) {
            int rbase = r0 + warpM * 32 + mt * 16 + (lane >> 2);
            #pragma unroll
            for (int nt = 0; nt < 4; nt++) {
                int c = c0 + warpN * 32 + nt * 8 + ((lane & 3) << 1);
                int n = c >> 4, d = c & 15;
                #pragma unroll
                for (int h = 0; h < 2; h++) {
                    int r = rbase + h * 8;
                    int b = r >> 9, sI = r & 511;
                    size_t idx = (((size_t)(b * NH_ + n) * J_ + j) * S_ + sI) * HS_ + d;
                    uint32_t hi, lo;
                    cvt_pair(acc[mt][nt][h * 2] * sc, acc[mt][nt][h * 2 + 1] * sc, hi, lo);
                    *(uint32_t*)(outh + idx) = hi;
                    *(uint32_t*)(outl + idx) = lo;
                }
            }
        }
        if (m < 2) { CP_WAIT0; __syncthreads(); }
    }
}

// ===========================================================================
// Kernel 2: tensor-core causal attention. block 512 (16 warps, band-permuted).
// Epilogue writes attention-out as split hi/lo bf16.  (unchanged)
// ===========================================================================
#define KSWZ(r, off) ((((uint32_t)(r)) << 5) + \
                      (((uint32_t)(off)) ^ ((((uint32_t)(r) >> 2) & 1u) << 4)))
#define AT_TOTAL 65536

__global__ __launch_bounds__(512, 1)
void attn_mma()
{
    extern __shared__ char smem[];
    const int inst = blockIdx.x;
    const int j  = inst % J_;
    const int bn = inst / J_;
    const int n  = bn % NH_;
    const int b  = bn / NH_;
    const size_t base = (size_t)inst * S_ * HS_;   // element base

    const int tid = threadIdx.x, wid = tid >> 5, lane = tid & 31;
    const uint32_t sbase = smem_u32(smem);

    // Stage Kh,Kl,Vh,Vl via cp.async (buffers at sbase + buf*16384)
    #pragma unroll 8
    for (int i = tid; i < 4096; i += 512) {
        int buf = i >> 10;
        int row = (i >> 1) & 511;
        int ch  = i & 1;
        const char* srcb = (buf == 0) ? (const char*)g_kh :
                           (buf == 1) ? (const char*)g_kl :
                           (buf == 2) ? (const char*)g_vh : (const char*)g_vl;
        cpa16(sbase + buf * 16384 + KSWZ(row, ch << 4),
              srcb + base * 2 + row * 32 + ch * 16);
    }
    CP_COMMIT;
    CP_WAIT0;
    __syncthreads();

    // Warp -> band permutation: SMSP g gets bands {g, 7-g, 8+g, 15-g}
    const int g  = wid & 3, iq = wid >> 2;
    const int band = (iq == 0) ? g : (iq == 1) ? (7 - g) : (iq == 2) ? (8 + g) : (15 - g);
    const int R0 = band * 32;
    const int qrow = lane >> 2, qcol = (lane & 3) << 1;

    // Q fragments: direct uint32 loads of pre-scaled splits
    uint32_t qh[2][4], ql[2][4];
    #pragma unroll
    for (int mt = 0; mt < 2; mt++) {
        size_t eb = base + (size_t)(R0 + qrow + mt * 16) * HS_ + qcol;
        qh[mt][0] = *(const uint32_t*)(g_qh + eb);
        qh[mt][1] = *(const uint32_t*)(g_qh + eb + 8 * HS_);
        qh[mt][2] = *(const uint32_t*)(g_qh + eb + 8);
        qh[mt][3] = *(const uint32_t*)(g_qh + eb + 8 * HS_ + 8);
        ql[mt][0] = *(const uint32_t*)(g_ql + eb);
        ql[mt][1] = *(const uint32_t*)(g_ql + eb + 8 * HS_);
        ql[mt][2] = *(const uint32_t*)(g_ql + eb + 8);
        ql[mt][3] = *(const uint32_t*)(g_ql + eb + 8 * HS_ + 8);
    }

    float O[2][2][4];
    #pragma unroll
    for (int mt = 0; mt < 2; mt++)
        #pragma unroll
        for (int dt = 0; dt < 2; dt++)
            #pragma unroll
            for (int i = 0; i < 4; i++) O[mt][dt][i] = 0.f;
    float rs[2][2] = {{0.f, 0.f}, {0.f, 0.f}};

    const uint32_t Kh = sbase,          Kl = sbase + 16384;
    const uint32_t Vh = sbase + 32768,  Vl = sbase + 49152;

    const int bg = lane >> 3, bl = lane & 7;
    const int kn = ((bg >> 1) << 3) + bl;
    const int kk = (bg & 1) << 3;
    const int vt = ((bg & 1) << 3) + bl;
    const int vd = (bg >> 1) << 4;

    const int last = 2 * band;

    for (int ntp = 0; ntp <= last; ntp++) {
        const int C0 = ntp << 4;
        uint32_t kh[4], klr[4], vh[4], vlr[4];
        ldsm_x4(kh[0], kh[1], kh[2], kh[3],     Kh + KSWZ(C0 + kn, kk * 2));
        ldsm_x4(klr[0], klr[1], klr[2], klr[3], Kl + KSWZ(C0 + kn, kk * 2));
        ldsm_x4_t(vh[0], vh[1], vh[2], vh[3],   Vh + KSWZ(C0 + vt, vd));
        ldsm_x4_t(vlr[0], vlr[1], vlr[2], vlr[3], Vl + KSWZ(C0 + vt, vd));

        float S[2][2][4];
        #pragma unroll
        for (int mt = 0; mt < 2; mt++)
            #pragma unroll
            for (int q2 = 0; q2 < 2; q2++)
                #pragma unroll
                for (int i = 0; i < 4; i++) S[mt][q2][i] = 0.f;
        #pragma unroll
        for (int mt = 0; mt < 2; mt++) {
            mma_bf16(S[mt][0], qh[mt], kh[0], kh[1]);
            mma_bf16(S[mt][1], qh[mt], kh[2], kh[3]);
            mma_bf16(S[mt][0], ql[mt], kh[0], kh[1]);
            mma_bf16(S[mt][1], ql[mt], kh[2], kh[3]);
            mma_bf16(S[mt][0], qh[mt], klr[0], klr[1]);
            mma_bf16(S[mt][1], qh[mt], klr[2], klr[3]);
        }

        #pragma unroll
        for (int mt = 0; mt < 2; mt++) {
            float p[8];
            if (mt == 0 && ntp == last) {
                const int row0 = R0 + qrow;
                const int col0 = C0 + qcol;
                p[0] = (col0     <= row0    ) ? ex2f(S[0][0][0]) : 0.f;
                p[1] = (col0 + 1 <= row0    ) ? ex2f(S[0][0][1]) : 0.f;
                p[2] = (col0     <= row0 + 8) ? ex2f(S[0][0][2]) : 0.f;
                p[3] = (col0 + 1 <= row0 + 8) ? ex2f(S[0][0][3]) : 0.f;
                p[4] = (col0 + 8 <= row0    ) ? ex2f(S[0][1][0]) : 0.f;
                p[5] = (col0 + 9 <= row0    ) ? ex2f(S[0][1][1]) : 0.f;
                p[6] = (col0 + 8 <= row0 + 8) ? ex2f(S[0][1][2]) : 0.f;
                p[7] = (col0 + 9 <= row0 + 8) ? ex2f(S[0][1][3]) : 0.f;
            } else {
                p[0] = ex2f(S[mt][0][0]);
                p[1] = ex2f(S[mt][0][1]);
                p[2] = ex2f(S[mt][0][2]);
                p[3] = ex2f(S[mt][0][3]);
                p[4] = ex2f(S[mt][1][0]);
                p[5] = ex2f(S[mt][1][1]);
                p[6] = ex2f(S[mt][1][2]);
                p[7] = ex2f(S[mt][1][3]);
            }
            rs[mt][0] += (p[0] + p[1]) + (p[4] + p[5]);
            rs[mt][1] += (p[2] + p[3]) + (p[6] + p[7]);

            uint32_t ph[4], pl[4];
            cvt_pair(p[0], p[1], ph[0], pl[0]);
            cvt_pair(p[2], p[3], ph[1], pl[1]);
            cvt_pair(p[4], p[5], ph[2], pl[2]);
            cvt_pair(p[6], p[7], ph[3], pl[3]);

            mma_bf16(O[mt][0], ph, vh[0], vh[1]);
            mma_bf16(O[mt][1], ph, vh[2], vh[3]);
            mma_bf16(O[mt][0], pl, vh[0], vh[1]);
            mma_bf16(O[mt][1], pl, vh[2], vh[3]);
            mma_bf16(O[mt][0], ph, vlr[0], vlr[1]);
            mma_bf16(O[mt][1], ph, vlr[2], vlr[3]);
        }
    }

    // Epilogue tile: ntp = last+1, mt = 1 only (diagonal)
    {
        const int C0 = (last + 1) << 4;
        uint32_t kh[4], klr[4], vh[4], vlr[4];
        ldsm_x4(kh[0], kh[1], kh[2], kh[3],     Kh + KSWZ(C0 + kn, kk * 2));
        ldsm_x4(klr[0], klr[1], klr[2], klr[3], Kl + KSWZ(C0 + kn, kk * 2));
        ldsm_x4_t(vh[0], vh[1], vh[2], vh[3],   Vh + KSWZ(C0 + vt, vd));
        ldsm_x4_t(vlr[0], vlr[1], vlr[2], vlr[3], Vl + KSWZ(C0 + vt, vd));

        float S0[4] = {0.f,0.f,0.f,0.f}, S1[4] = {0.f,0.f,0.f,0.f};
        mma_bf16(S0, qh[1], kh[0], kh[1]);
        mma_bf16(S1, qh[1], kh[2], kh[3]);
        mma_bf16(S0, ql[1], kh[0], kh[1]);
        mma_bf16(S1, ql[1], kh[2], kh[3]);
        mma_bf16(S0, qh[1], klr[0], klr[1]);
        mma_bf16(S1, qh[1], klr[2], klr[3]);

        const int row0 = R0 + 16 + qrow;
        const int col0 = C0 + qcol;
        float p[8];
        p[0] = (col0     <= row0    ) ? ex2f(S0[0]) : 0.f;
        p[1] = (col0 + 1 <= row0    ) ? ex2f(S0[1]) : 0.f;
        p[2] = (col0     <= row0 + 8) ? ex2f(S0[2]) : 0.f;
        p[3] = (col0 + 1 <= row0 + 8) ? ex2f(S0[3]) : 0.f;
        p[4] = (col0 + 8 <= row0    ) ? ex2f(S1[0]) : 0.f;
        p[5] = (col0 + 9 <= row0    ) ? ex2f(S1[1]) : 0.f;
        p[6] = (col0 + 8 <= row0 + 8) ? ex2f(S1[2]) : 0.f;
        p[7] = (col0 + 9 <= row0 + 8) ? ex2f(S1[3]) : 0.f;
        rs[1][0] += (p[0] + p[1]) + (p[4] + p[5]);
        rs[1][1] += (p[2] + p[3]) + (p[6] + p[7]);

        uint32_t ph[4], pl[4];
        cvt_pair(p[0], p[1], ph[0], pl[0]);
        cvt_pair(p[2], p[3], ph[1], pl[1]);
        cvt_pair(p[4], p[5], ph[2], pl[2]);
        cvt_pair(p[6], p[7], ph[3], pl[3]);

        mma_bf16(O[1][0], ph, vh[0], vh[1]);
        mma_bf16(O[1][1], ph, vh[2], vh[3]);
        mma_bf16(O[1][0], pl, vh[0], vh[1]);
        mma_bf16(O[1][1], pl, vh[2], vh[3]);
        mma_bf16(O[1][0], ph, vlr[0], vlr[1]);
        mma_bf16(O[1][1], ph, vlr[2], vlr[3]);
    }

    // Row sums: reduce, normalize, write split hi/lo bf16 attention-out.
    #pragma unroll
    for (int mt = 0; mt < 2; mt++) {
        float s0 = rs[mt][0], s1 = rs[mt][1];
        s0 += __shfl_xor_sync(0xffffffffu, s0, 1);
        s0 += __shfl_xor_sync(0xffffffffu, s0, 2);
        s1 += __shfl_xor_sync(0xffffffffu, s1, 1);
        s1 += __shfl_xor_sync(0xffffffffu, s1, 2);
        const float i0 = 1.f / s0, i1 = 1.f / s1;
        const int row = R0 + mt * 16 + (lane >> 2);
        const int dc  = (lane & 3) << 1;
        #pragma unroll
        for (int dt = 0; dt < 2; dt++) {
            const int d = dt * 8 + dc;
            size_t i0x = ((size_t)(b * S_ + row)     * J_ + j) * H_ + n * HS_ + d;
            size_t i1x = ((size_t)(b * S_ + row + 8) * J_ + j) * H_ + n * HS_ + d;
            uint32_t hi, lo;
            cvt_pair(O[mt][dt][0] * i0, O[mt][dt][1] * i0, hi, lo);
            *(uint32_t*)(g_aoh + i0x) = hi;
            *(uint32_t*)(g_aol + i0x) = lo;
            cvt_pair(O[mt][dt][2] * i1, O[mt][dt][3] * i1, hi, lo);
            *(uint32_t*)(g_aoh + i1x) = hi;
            *(uint32_t*)(g_aol + i1x) = lo;
        }
    }
}

// ===========================================================================
// Kernel 3: output projection + residual + LayerNorm — fully pipelined.
// B1 prefetched at start (hides under gemm p0); x residual tile prefetched
// into retired B0 region (hides under gemm p1). C staged into retired A
// region. One exposed memory wait total. smem 106 KB -> 2 CTAs/SM.
// ===========================================================================
#define P_AHI  0
#define P_ALO  17408
#define P_B0HI 34816
#define P_B0LO 53248
#define P_B1HI 71680
#define P_B1LO 90112
#define P_XS   34816          // x tile aliases B0 region (after p0 retires it)
#define P_XROW 544            // x row stride bytes (512 data + 32 pad)
#define P_TOTAL 108544

__global__ __launch_bounds__(256, 2)
void proj_mma(const float* __restrict__ x,
              const float* __restrict__ gamma,
              const float* __restrict__ beta,
              float* __restrict__ out)
{
    extern __shared__ char smem[];
    const int j   = blockIdx.y;
    const int r0  = blockIdx.x * 64;
    const int tid = threadIdx.x, wid = tid >> 5, lane = tid & 31;
    const uint32_t sb = smem_u32(smem);

    // --- group 0: A (attention-out rows, hi+lo) + B0 (proj cols 0..63) ---
    #pragma unroll 4
    for (int i = tid; i < 2048; i += 256) {
        int buf = i >> 10;               // 0 hi, 1 lo
        int row = (i >> 4) & 63;
        int ch  = i & 15;
        const char* src = (const char*)(buf ? g_aol : g_aoh)
            + ((size_t)(r0 + row) * J_ + j) * H_ * 2 + ch * 16;
        cpa16(sb + (buf ? P_ALO : P_AHI) + row * SAB_B + ch * 16, src);
    }
    #pragma unroll 4
    for (int i = tid; i < 2048; i += 256) {
        int buf = i >> 10;
        int k   = (i >> 3) & 127;
        int ch  = i & 7;
        const char* src = (const char*)(buf ? g_pl : g_ph)
            + ((size_t)j * H_ * H_ + (size_t)k * H_) * 2 + ch * 16;
        cpa16(sb + (buf ? P_B0LO : P_B0HI) + k * SBN + ch * 16, src);
    }
    CP_COMMIT;
    // --- group 1: B1 (proj cols 64..127) — arrives under gemm p0 ---
    #pragma unroll 4
    for (int i = tid; i < 2048; i += 256) {
        int buf = i >> 10;
        int k   = (i >> 3) & 127;
        int ch  = i & 7;
        const char* src = (const char*)(buf ? g_pl : g_ph)
            + ((size_t)j * H_ * H_ + (size_t)k * H_ + 64) * 2 + ch * 16;
        cpa16(sb + (buf ? P_B1LO : P_B1HI) + k * SBN + ch * 16, src);
    }
    CP_COMMIT;
    CP_WAIT1;          // A + B0 ready (B1 may still be in flight)
    __syncthreads();

    const int warpM = wid & 3, warpN = wid >> 2;
    const int ar = lane & 15, ac = (lane >> 4) << 3;
    const int bg = lane >> 3, blp = lane & 7;
    const int kt = ((bg & 1) << 3) + blp;
    const int nb = (bg >> 1) << 4;
    const uint32_t aRow = (uint32_t)(warpM * 16 + ar) * SAB_B;

    float acc[2][4][4];   // [pass][ntile][frag]
    #pragma unroll
    for (int p = 0; p < 2; p++)
        #pragma unroll
        for (int nt = 0; nt < 4; nt++)
            #pragma unroll
            for (int i = 0; i < 4; i++) acc[p][nt][i] = 0.f;

    // ---- gemm pass 0 (B0) ----
    #pragma unroll 1
    for (int sp = 0; sp < 3; sp++) {
        const uint32_t aB = sb + ((sp == 2) ? P_ALO : P_AHI) + aRow;
        const uint32_t bB = sb + ((sp == 1) ? P_B0LO : P_B0HI);
        #pragma unroll
        for (int k0 = 0; k0 < 8; k0++) {
            uint32_t a[4];
            ldsm_x4(a[0], a[1], a[2], a[3], aB + (uint32_t)(k0 * 16 + ac) * 2);
            #pragma unroll
            for (int ntp = 0; ntp < 2; ntp++) {
                uint32_t bfr[4];
                ldsm_x4_t(bfr[0], bfr[1], bfr[2], bfr[3],
                          bB + (uint32_t)(k0 * 16 + kt) * SBN
                             + (uint32_t)(warpN * 32 + ntp * 16) * 2 + nb);
                mma_bf16(acc[0][ntp * 2],     a, bfr[0], bfr[1]);
                mma_bf16(acc[0][ntp * 2 + 1], a, bfr[2], bfr[3]);
            }
        }
    }
    __syncthreads();   // all warps done reading B0 region

    // --- group 2: x residual tile into retired B0 region (under gemm p1) ---
    #pragma unroll 4
    for (int i = tid; i < 2048; i += 256) {
        int row = i >> 5;                // 64 rows x 32 chunks (512B/row)
        int ch  = i & 31;
        const char* src = (const char*)x
            + ((size_t)(r0 + row) * J_ + j) * H_ * 4 + ch * 16;
        cpa16(sb + P_XS + row * P_XROW + ch * 16, src);
    }
    CP_COMMIT;
    CP_WAIT1;          // B1 ready (x may still be in flight)
    __syncthreads();

    // ---- gemm pass 1 (B1) ----
    #pragma unroll 1
    for (int sp = 0; sp < 3; sp++) {
        const uint32_t aB = sb + ((sp == 2) ? P_ALO : P_AHI) + aRow;
        const uint32_t bB = sb + ((sp == 1) ? P_B1LO : P_B1HI);
        #pragma unroll
        for (int k0 = 0; k0 < 8; k0++) {
            uint32_t a[4];
            ldsm_x4(a[0], a[1], a[2], a[3], aB + (uint32_t)(k0 * 16 + ac) * 2);
            #pragma unroll
            for (int ntp = 0; ntp < 2; ntp++) {
                uint32_t bfr[4];
                ldsm_x4_t(bfr[0], bfr[1], bfr[2], bfr[3],
                          bB + (uint32_t)(k0 * 16 + kt) * SBN
                             + (uint32_t)(warpN * 32 + ntp * 16) * 2 + nb);
                mma_bf16(acc[1][ntp * 2],     a, bfr[0], bfr[1]);
                mma_bf16(acc[1][ntp * 2 + 1], a, bfr[2], bfr[3]);
            }
        }
    }
    CP_WAIT0;          // x arrived
    __syncthreads();   // all warps done reading A region

    // Stage C into retired A region: [64][132] floats (33792 B <= 34816 B)
    float* Cs = (float*)smem;
    #pragma unroll
    for (int p = 0; p < 2; p++) {
        int rb = warpM * 16 + (lane >> 2);
        #pragma unroll
        for (int nt = 0; nt < 4; nt++) {
            int col = p * 64 + warpN * 32 + nt * 8 + ((lane & 3) << 1);
            #pragma unroll
            for (int h = 0; h < 2; h++) {
                Cs[(rb + h * 8) * 132 + col]     = acc[p][nt][h * 2];
                Cs[(rb + h * 8) * 132 + col + 1] = acc[p][nt][h * 2 + 1];
            }
        }
    }
    __syncthreads();

    // Residual + LN: 4 threads per row (32 cols each); x from smem.
    {
        const int row = tid >> 2;
        const int q   = tid & 3;
        const int r   = r0 + row;
        const float* xr = (const float*)(smem + P_XS + row * P_XROW) + q * 32;
        float* crow     = Cs + row * 132 + q * 32;

        float sum = 0.f, sq = 0.f;
        #pragma unroll
        for (int i = 0; i < 8; i++) {
            float4 c4 = *(float4*)(crow + i * 4);
            float4 xv = *(const float4*)(xr + i * 4);
            c4.x += xv.x; c4.y += xv.y; c4.z += xv.z; c4.w += xv.w;
            *(float4*)(crow + i * 4) = c4;
            sum += c4.x + c4.y + c4.z + c4.w;
            sq  += c4.x*c4.x + c4.y*c4.y + c4.z*c4.z + c4.w*c4.w;
        }
        sum += __shfl_xor_sync(0xffffffffu, sum, 1);
        sum += __shfl_xor_sync(0xffffffffu, sum, 2);
        sq  += __shfl_xor_sync(0xffffffffu, sq, 1);
        sq  += __shfl_xor_sync(0xffffffffu, sq, 2);
        const float mu   = sum * (1.f / 128.f);
        const float var  = sq * (1.f / 128.f) - mu * mu;
        const float rstd = rsqrtf(var + 1e-5f);

        float* orow = out + ((size_t)r * J_ + j) * H_ + q * 32;
        const float* gp  = gamma + q * 32;
        const float* bp2 = beta  + q * 32;
        #pragma unroll
        for (int i = 0; i < 8; i++) {
            float4 c4 = *(float4*)(crow + i * 4);
            float4 o;
            o.x = (c4.x - mu) * rstd * gp[i*4+0] + bp2[i*4+0];
            o.y = (c4.y - mu) * rstd * gp[i*4+1] + bp2[i*4+1];
            o.z = (c4.z - mu) * rstd * gp[i*4+2] + bp2[i*4+2];
            o.w = (c4.w - mu) * rstd * gp[i*4+3] + bp2[i*4+3];
            *(float4*)(orow + i * 4) = o;
        }
    }
}

// ===========================================================================
extern "C" void kernel_launch(void* const* d_in, const int* in_sizes, int n_in,
                              void* d_out, int out_size)
{
    const float* x     = (const float*)d_in[0];
    // d_in[1]: additive causal mask (= triu(-1e9)) — implemented as causal skip.
    const float* qm    = (const float*)d_in[2];
    const float* km    = (const float*)d_in[3];
    const float* vm    = (const float*)d_in[4];
    const float* proj  = (const float*)d_in[5];
    const float* gamma = (const float*)d_in[6];
    const float* beta  = (const float*)d_in[7];
    float* out = (float*)d_out;

    cudaFuncSetAttribute(qkv_mma,  cudaFuncAttributeMaxDynamicSharedMemorySize, QK_TOTAL);
    cudaFuncSetAttribute(attn_mma, cudaFuncAttributeMaxDynamicSharedMemorySize, AT_TOTAL);
    cudaFuncSetAttribute(proj_mma, cudaFuncAttributeMaxDynamicSharedMemorySize, P_TOTAL);

    prep<<<PREP_T / 256, 256>>>(x, qm, km, vm, proj);
    qkv_mma<<<dim3(BS_/128, J_, 2), 256, QK_TOTAL>>>();
    attn_mma<<<INST_, 512, AT_TOTAL>>>();
    proj_mma<<<dim3(BS_/64, J_), 256, P_TOTAL>>>(x, gamma, beta, out);
}

// round 16
// speedup vs baseline: 2.1795x; 1.0204x over previous
#include <cuda_runtime.h>
#include <cuda_bf16.h>
#include <stdint.h>

// Problem constants
#define B_  4
#define S_  512
#define J_  24
#define H_  128
#define NH_ 8
#define HS_ 16
#define BS_ (B_*S_)            // 2048 rows
#define INST_ (B_*NH_*J_)      // 768 attention instances
#define QKV_E (B_*NH_*J_*S_*HS_)   // 6291456 elements
#define QSCALE 0.3606737602222409f // 0.25 * log2(e)

// Scratch (static device globals — allocation-free)
__device__ __nv_bfloat16 g_xh[BS_*J_*H_];        // x split hi/lo
__device__ __nv_bfloat16 g_xl[BS_*J_*H_];
__device__ __nv_bfloat16 g_wh[3*J_*H_*H_];       // qkv weights [m][j][k][n]
__device__ __nv_bfloat16 g_wl[3*J_*H_*H_];
__device__ __nv_bfloat16 g_ph[J_*H_*H_];         // proj weights [j][k][n]
__device__ __nv_bfloat16 g_pl[J_*H_*H_];
__device__ __nv_bfloat16 g_qh[QKV_E], g_ql[QKV_E];   // q pre-scaled by QSCALE
__device__ __nv_bfloat16 g_kh[QKV_E], g_kl[QKV_E];
__device__ __nv_bfloat16 g_vh[QKV_E], g_vl[QKV_E];
__device__ __nv_bfloat16 g_aoh[BS_*J_*H_];       // attention out split hi/lo
__device__ __nv_bfloat16 g_aol[BS_*J_*H_];

// ===========================================================================
// Helpers (baseline PTX features only)
// ===========================================================================
__device__ __forceinline__ uint32_t smem_u32(const void* p) {
    uint32_t a;
    asm("{ .reg .u64 t; cvta.to.shared.u64 t, %1; cvt.u32.u64 %0, t; }"
        : "=r"(a) : "l"(p));
    return a;
}
__device__ __forceinline__ void ldsm_x4(uint32_t& r0, uint32_t& r1,
                                        uint32_t& r2, uint32_t& r3, uint32_t addr) {
    asm volatile("ldmatrix.sync.aligned.m8n8.x4.shared.b16 {%0,%1,%2,%3}, [%4];"
                 : "=r"(r0), "=r"(r1), "=r"(r2), "=r"(r3) : "r"(addr));
}
__device__ __forceinline__ void ldsm_x4_t(uint32_t& r0, uint32_t& r1,
                                          uint32_t& r2, uint32_t& r3, uint32_t addr) {
    asm volatile("ldmatrix.sync.aligned.m8n8.x4.trans.shared.b16 {%0,%1,%2,%3}, [%4];"
                 : "=r"(r0), "=r"(r1), "=r"(r2), "=r"(r3) : "r"(addr));
}
__device__ __forceinline__ void mma_bf16(float* c, const uint32_t a[4],
                                         uint32_t b0, uint32_t b1) {
    asm volatile(
        "mma.sync.aligned.m16n8k16.row.col.f32.bf16.bf16.f32 "
        "{%0,%1,%2,%3}, {%4,%5,%6,%7}, {%8,%9}, {%0,%1,%2,%3};"
        : "+f"(c[0]), "+f"(c[1]), "+f"(c[2]), "+f"(c[3])
        : "r"(a[0]), "r"(a[1]), "r"(a[2]), "r"(a[3]), "r"(b0), "r"(b1));
}
// split-fp32 -> (hi bf16x2, lo bf16x2); a -> low half, b -> high half
__device__ __forceinline__ void cvt_pair(float a, float b, uint32_t& hi, uint32_t& lo) {
    uint32_t h;
    asm("cvt.rn.bf16x2.f32 %0, %1, %2;" : "=r"(h) : "f"(b), "f"(a));
    float ha = __uint_as_float(h << 16);
    float hb = __uint_as_float(h & 0xffff0000u);
    float la = a - ha, lb = b - hb;
    asm("cvt.rn.bf16x2.f32 %0, %1, %2;" : "=r"(lo) : "f"(lb), "f"(la));
    hi = h;
}
__device__ __forceinline__ float ex2f(float x) {
    float r; asm("ex2.approx.f32 %0, %1;" : "=f"(r) : "f"(x)); return r;
}
__device__ __forceinline__ void cpa16(uint32_t dst, const void* src) {
    asm volatile("cp.async.cg.shared.global [%0], [%1], 16;" :: "r"(dst), "l"(src));
}
#define CP_COMMIT asm volatile("cp.async.commit_group;" ::: "memory")
#define CP_WAIT0  asm volatile("cp.async.wait_group 0;" ::: "memory")
#define CP_WAIT1  asm volatile("cp.async.wait_group 1;" ::: "memory")

#define SAB_B 272      // A row stride in bytes (136 bf16)
#define SBN   144      // B (transposed [k][n]) row stride in bytes

// ===========================================================================
// Kernel 0: prep — convert x, qkv weights and proj weights to split bf16.
// ===========================================================================
#define XQUAD (BS_*J_*H_/4)               // 1572864 float4s
#define WPAIR (3*NH_*J_*H_*HS_/2)         // 589824 pairs
#define PPAIR (J_*H_*H_/2)                // 196608 pairs
#define PREP_T ((XQUAD + WPAIR + PPAIR + 255) & ~255)

__global__ __launch_bounds__(256)
void prep(const float* __restrict__ x,
          const float* __restrict__ qm,
          const float* __restrict__ km,
          const float* __restrict__ vm,
          const float* __restrict__ proj)
{
    int t = blockIdx.x * 256 + threadIdx.x;
    if (t < XQUAD) {
        float4 v = ((const float4*)x)[t];
        uint32_t h01, l01, h23, l23;
        cvt_pair(v.x, v.y, h01, l01);
        cvt_pair(v.z, v.w, h23, l23);
        ((uint2*)g_xh)[t] = make_uint2(h01, h23);
        ((uint2*)g_xl)[t] = make_uint2(l01, l23);
    } else if (t < XQUAD + WPAIR) {
        int u  = t - XQUAD;
        int n2 = u & 63;  int u2 = u >> 6;
        int k  = u2 & 127; int u3 = u2 >> 7;
        int j  = u3 % J_;  int m  = u3 / J_;
        int n  = n2 * 2;
        const float* mat = (m == 0) ? qm : (m == 1 ? km : vm);
        const float2 w = *(const float2*)(mat +
            ((size_t)((n >> 4) * J_ + j) * H_ + k) * HS_ + (n & 15));
        uint32_t hi, lo;
        cvt_pair(w.x, w.y, hi, lo);
        size_t o = ((size_t)(m * J_ + j) * H_ + k) * H_ + n;
        *(uint32_t*)(g_wh + o) = hi;
        *(uint32_t*)(g_wl + o) = lo;
    } else if (t < XQUAD + WPAIR + PPAIR) {
        int u = t - XQUAD - WPAIR;      // proj is [j][k][n], n contiguous
        const float2 w = ((const float2*)proj)[u];
        uint32_t hi, lo;
        cvt_pair(w.x, w.y, hi, lo);
        ((uint32_t*)g_ph)[u] = hi;
        ((uint32_t*)g_pl)[u] = lo;
    }
}

// ===========================================================================
// Kernel 1: QKV projection. grid (16, 24, 2). block 256. cp.async staging
// from precomputed splits; B(m+1) copy overlapped with scatter(m).
// Outputs q (pre-scaled by QSCALE), k, v as split bf16.  (unchanged)
// ===========================================================================
#define QK_AHI 0
#define QK_ALO 34816
#define QK_BHI 69632
#define QK_BLO 88064
#define QK_TOTAL 106496

__global__ __launch_bounds__(256, 2)
void qkv_mma()
{
    extern __shared__ char smem[];
    const int j   = blockIdx.y;
    const int c0  = blockIdx.z * 64;
    const int r0  = blockIdx.x * 128;
    const int tid = threadIdx.x, wid = tid >> 5, lane = tid & 31;
    const uint32_t sb = smem_u32(smem);

    // --- async stage A (x rows r0..r0+127, hi+lo) ---
    #pragma unroll 4
    for (int i = tid; i < 4096; i += 256) {
        int buf = i >> 11;               // 0 hi, 1 lo
        int row = (i >> 4) & 127;
        int ch  = i & 15;
        const char* src = (const char*)(buf ? g_xl : g_xh)
            + ((size_t)(r0 + row) * J_ + j) * H_ * 2 + ch * 16;
        cpa16(sb + (buf ? QK_ALO : QK_AHI) + row * SAB_B + ch * 16, src);
    }
    // --- async stage B(0) ---
    #pragma unroll 4
    for (int i = tid; i < 2048; i += 256) {
        int buf = i >> 10;
        int k   = (i >> 3) & 127;
        int ch  = i & 7;
        const char* src = (const char*)(buf ? g_wl : g_wh)
            + (((size_t)(0 * J_ + j) * H_ + k) * H_ + c0) * 2 + ch * 16;
        cpa16(sb + (buf ? QK_BLO : QK_BHI) + k * SBN + ch * 16, src);
    }
    CP_COMMIT;
    CP_WAIT0;
    __syncthreads();

    const int warpM = wid & 3, warpN = wid >> 2;
    const int ar = lane & 15, ac = (lane >> 4) << 3;
    const int bg = lane >> 3, blp = lane & 7;
    const int kt = ((bg & 1) << 3) + blp;
    const int nb = (bg >> 1) << 4;
    const uint32_t aRow = (uint32_t)(warpM * 32 + ar) * SAB_B;

    for (int m = 0; m < 3; m++) {
        float acc[2][4][4];
        #pragma unroll
        for (int mt = 0; mt < 2; mt++)
            #pragma unroll
            for (int nt = 0; nt < 4; nt++)
                #pragma unroll
                for (int i = 0; i < 4; i++) acc[mt][nt][i] = 0.f;

        #pragma unroll 1
        for (int sp = 0; sp < 3; sp++) {
            const uint32_t aB = sb + ((sp == 2) ? QK_ALO : QK_AHI) + aRow;
            const uint32_t bB = sb + ((sp == 1) ? QK_BLO : QK_BHI);
            #pragma unroll
            for (int k0 = 0; k0 < 8; k0++) {
                uint32_t a[2][4];
                #pragma unroll
                for (int mt = 0; mt < 2; mt++)
                    ldsm_x4(a[mt][0], a[mt][1], a[mt][2], a[mt][3],
                            aB + (uint32_t)(mt * 16) * SAB_B + (uint32_t)(k0 * 16 + ac) * 2);
                #pragma unroll
                for (int ntp = 0; ntp < 2; ntp++) {
                    uint32_t b[4];
                    ldsm_x4_t(b[0], b[1], b[2], b[3],
                              bB + (uint32_t)(k0 * 16 + kt) * SBN
                                 + (uint32_t)(warpN * 32 + ntp * 16) * 2 + nb);
                    #pragma unroll
                    for (int mt = 0; mt < 2; mt++) {
                        mma_bf16(acc[mt][ntp * 2],     a[mt], b[0], b[1]);
                        mma_bf16(acc[mt][ntp * 2 + 1], a[mt], b[2], b[3]);
                    }
                }
            }
        }

        if (m < 2) {
            __syncthreads();     // all warps done reading B(m)
            #pragma unroll 4
            for (int i = tid; i < 2048; i += 256) {
                int buf = i >> 10;
                int k   = (i >> 3) & 127;
                int ch  = i & 7;
                const char* src = (const char*)(buf ? g_wl : g_wh)
                    + (((size_t)((m + 1) * J_ + j) * H_ + k) * H_ + c0) * 2 + ch * 16;
                cpa16(sb + (buf ? QK_BLO : QK_BHI) + k * SBN + ch * 16, src);
            }
            CP_COMMIT;
        }

        // scatter (overlaps async B copy): split hi/lo bf16, q pre-scaled
        __nv_bfloat16* outh = (m == 0) ? g_qh : (m == 1 ? g_kh : g_vh);
        __nv_bfloat16* outl = (m == 0) ? g_ql : (m == 1 ? g_kl : g_vl);
        const float sc = (m == 0) ? QSCALE : 1.f;
        #pragma unroll
        for (int mt = 0; mt < 2; mt++) {
            int rbase = r0 + warpM * 32 + mt * 16 + (lane >> 2);
            #pragma unroll
            for (int nt = 0; nt < 4; nt++) {
                int c = c0 + warpN * 32 + nt * 8 + ((lane & 3) << 1);
                int n = c >> 4, d = c & 15;
                #pragma unroll
                for (int h = 0; h < 2; h++) {
                    int r = rbase + h * 8;
                    int b = r >> 9, sI = r & 511;
                    size_t idx = (((size_t)(b * NH_ + n) * J_ + j) * S_ + sI) * HS_ + d;
                    uint32_t hi, lo;
                    cvt_pair(acc[mt][nt][h * 2] * sc, acc[mt][nt][h * 2 + 1] * sc, hi, lo);
                    *(uint32_t*)(outh + idx) = hi;
                    *(uint32_t*)(outl + idx) = lo;
                }
            }
        }
        if (m < 2) { CP_WAIT0; __syncthreads(); }
    }
}

// ===========================================================================
// Kernel 2: tensor-core causal attention. block 512 (16 warps, band-permuted).
// NEW: 2 instances per CTA, double-buffered smem (group0/group1); instance 1's
// K/V staging hides under instance 0's compute. Q LDGs issued before waits.
// ===========================================================================
#define KSWZ(r, off) ((((uint32_t)(r)) << 5) + \
                      (((uint32_t)(off)) ^ ((((uint32_t)(r) >> 2) & 1u) << 4)))
#define AT_HALF  65536
#define AT_TOTAL 131072

__device__ __forceinline__ void stage_kv(uint32_t dst, int inst, int tid)
{
    const size_t base2 = (size_t)inst * S_ * HS_ * 2;   // byte base
    #pragma unroll 8
    for (int i = tid; i < 4096; i += 512) {
        int buf = i >> 10;
        int row = (i >> 1) & 511;
        int ch  = i & 1;
        const char* srcb = (buf == 0) ? (const char*)g_kh :
                           (buf == 1) ? (const char*)g_kl :
                           (buf == 2) ? (const char*)g_vh : (const char*)g_vl;
        cpa16(dst + buf * 16384 + KSWZ(row, ch << 4),
              srcb + base2 + row * 32 + ch * 16);
    }
}

__device__ __forceinline__ void load_q(int inst, int band, int lane,
                                       uint32_t qh[2][4], uint32_t ql[2][4])
{
    const size_t base = (size_t)inst * S_ * HS_;
    const int qrow = lane >> 2, qcol = (lane & 3) << 1;
    #pragma unroll
    for (int mt = 0; mt < 2; mt++) {
        size_t eb = base + (size_t)(band * 32 + qrow + mt * 16) * HS_ + qcol;
        qh[mt][0] = *(const uint32_t*)(g_qh + eb);
        qh[mt][1] = *(const uint32_t*)(g_qh + eb + 8 * HS_);
        qh[mt][2] = *(const uint32_t*)(g_qh + eb + 8);
        qh[mt][3] = *(const uint32_t*)(g_qh + eb + 8 * HS_ + 8);
        ql[mt][0] = *(const uint32_t*)(g_ql + eb);
        ql[mt][1] = *(const uint32_t*)(g_ql + eb + 8 * HS_);
        ql[mt][2] = *(const uint32_t*)(g_ql + eb + 8);
        ql[mt][3] = *(const uint32_t*)(g_ql + eb + 8 * HS_ + 8);
    }
}

__device__ __forceinline__ void attn_one(uint32_t sbase, int inst, int band,
                                         int lane,
                                         uint32_t qh[2][4], uint32_t ql[2][4])
{
    const int j  = inst % J_;
    const int bn = inst / J_;
    const int n  = bn % NH_;
    const int b  = bn / NH_;
    const int R0 = band * 32;
    const int qrow = lane >> 2, qcol = (lane & 3) << 1;

    float O[2][2][4];
    #pragma unroll
    for (int mt = 0; mt < 2; mt++)
        #pragma unroll
        for (int dt = 0; dt < 2; dt++)
            #pragma unroll
            for (int i = 0; i < 4; i++) O[mt][dt][i] = 0.f;
    float rs[2][2] = {{0.f, 0.f}, {0.f, 0.f}};

    const uint32_t Kh = sbase,          Kl = sbase + 16384;
    const uint32_t Vh = sbase + 32768,  Vl = sbase + 49152;

    const int bg = lane >> 3, bl = lane & 7;
    const int kn = ((bg >> 1) << 3) + bl;
    const int kk = (bg & 1) << 3;
    const int vt = ((bg & 1) << 3) + bl;
    const int vd = (bg >> 1) << 4;

    const int last = 2 * band;

    for (int ntp = 0; ntp <= last; ntp++) {
        const int C0 = ntp << 4;
        uint32_t kh[4], klr[4], vh[4], vlr[4];
        ldsm_x4(kh[0], kh[1], kh[2], kh[3],     Kh + KSWZ(C0 + kn, kk * 2));
        ldsm_x4(klr[0], klr[1], klr[2], klr[3], Kl + KSWZ(C0 + kn, kk * 2));
        ldsm_x4_t(vh[0], vh[1], vh[2], vh[3],   Vh + KSWZ(C0 + vt, vd));
        ldsm_x4_t(vlr[0], vlr[1], vlr[2], vlr[3], Vl + KSWZ(C0 + vt, vd));

        float S[2][2][4];
        #pragma unroll
        for (int mt = 0; mt < 2; mt++)
            #pragma unroll
            for (int q2 = 0; q2 < 2; q2++)
                #pragma unroll
                for (int i = 0; i < 4; i++) S[mt][q2][i] = 0.f;
        #pragma unroll
        for (int mt = 0; mt < 2; mt++) {
            mma_bf16(S[mt][0], qh[mt], kh[0], kh[1]);
            mma_bf16(S[mt][1], qh[mt], kh[2], kh[3]);
            mma_bf16(S[mt][0], ql[mt], kh[0], kh[1]);
            mma_bf16(S[mt][1], ql[mt], kh[2], kh[3]);
            mma_bf16(S[mt][0], qh[mt], klr[0], klr[1]);
            mma_bf16(S[mt][1], qh[mt], klr[2], klr[3]);
        }

        #pragma unroll
        for (int mt = 0; mt < 2; mt++) {
            float p[8];
            if (mt == 0 && ntp == last) {
                const int row0 = R0 + qrow;
                const int col0 = C0 + qcol;
                p[0] = (col0     <= row0    ) ? ex2f(S[0][0][0]) : 0.f;
                p[1] = (col0 + 1 <= row0    ) ? ex2f(S[0][0][1]) : 0.f;
                p[2] = (col0     <= row0 + 8) ? ex2f(S[0][0][2]) : 0.f;
                p[3] = (col0 + 1 <= row0 + 8) ? ex2f(S[0][0][3]) : 0.f;
                p[4] = (col0 + 8 <= row0    ) ? ex2f(S[0][1][0]) : 0.f;
                p[5] = (col0 + 9 <= row0    ) ? ex2f(S[0][1][1]) : 0.f;
                p[6] = (col0 + 8 <= row0 + 8) ? ex2f(S[0][1][2]) : 0.f;
                p[7] = (col0 + 9 <= row0 + 8) ? ex2f(S[0][1][3]) : 0.f;
            } else {
                p[0] = ex2f(S[mt][0][0]);
                p[1] = ex2f(S[mt][0][1]);
                p[2] = ex2f(S[mt][0][2]);
                p[3] = ex2f(S[mt][0][3]);
                p[4] = ex2f(S[mt][1][0]);
                p[5] = ex2f(S[mt][1][1]);
                p[6] = ex2f(S[mt][1][2]);
                p[7] = ex2f(S[mt][1][3]);
            }
            rs[mt][0] += (p[0] + p[1]) + (p[4] + p[5]);
            rs[mt][1] += (p[2] + p[3]) + (p[6] + p[7]);

            uint32_t ph[4], pl[4];
            cvt_pair(p[0], p[1], ph[0], pl[0]);
            cvt_pair(p[2], p[3], ph[1], pl[1]);
            cvt_pair(p[4], p[5], ph[2], pl[2]);
            cvt_pair(p[6], p[7], ph[3], pl[3]);

            mma_bf16(O[mt][0], ph, vh[0], vh[1]);
            mma_bf16(O[mt][1], ph, vh[2], vh[3]);
            mma_bf16(O[mt][0], pl, vh[0], vh[1]);
            mma_bf16(O[mt][1], pl, vh[2], vh[3]);
            mma_bf16(O[mt][0], ph, vlr[0], vlr[1]);
            mma_bf16(O[mt][1], ph, vlr[2], vlr[3]);
        }
    }

    // Epilogue tile: ntp = last+1, mt = 1 only (diagonal)
    {
        const int C0 = (last + 1) << 4;
        uint32_t kh[4], klr[4], vh[4], vlr[4];
        ldsm_x4(kh[0], kh[1], kh[2], kh[3],     Kh + KSWZ(C0 + kn, kk * 2));
        ldsm_x4(klr[0], klr[1], klr[2], klr[3], Kl + KSWZ(C0 + kn, kk * 2));
        ldsm_x4_t(vh[0], vh[1], vh[2], vh[3],   Vh + KSWZ(C0 + vt, vd));
        ldsm_x4_t(vlr[0], vlr[1], vlr[2], vlr[3], Vl + KSWZ(C0 + vt, vd));

        float S0[4] = {0.f,0.f,0.f,0.f}, S1[4] = {0.f,0.f,0.f,0.f};
        mma_bf16(S0, qh[1], kh[0], kh[1]);
        mma_bf16(S1, qh[1], kh[2], kh[3]);
        mma_bf16(S0, ql[1], kh[0], kh[1]);
        mma_bf16(S1, ql[1], kh[2], kh[3]);
        mma_bf16(S0, qh[1], klr[0], klr[1]);
        mma_bf16(S1, qh[1], klr[2], klr[3]);

        const int row0 = R0 + 16 + qrow;
        const int col0 = C0 + qcol;
        float p[8];
        p[0] = (col0     <= row0    ) ? ex2f(S0[0]) : 0.f;
        p[1] = (col0 + 1 <= row0    ) ? ex2f(S0[1]) : 0.f;
        p[2] = (col0     <= row0 + 8) ? ex2f(S0[2]) : 0.f;
        p[3] = (col0 + 1 <= row0 + 8) ? ex2f(S0[3]) : 0.f;
        p[4] = (col0 + 8 <= row0    ) ? ex2f(S1[0]) : 0.f;
        p[5] = (col0 + 9 <= row0    ) ? ex2f(S1[1]) : 0.f;
        p[6] = (col0 + 8 <= row0 + 8) ? ex2f(S1[2]) : 0.f;
        p[7] = (col0 + 9 <= row0 + 8) ? ex2f(S1[3]) : 0.f;
        rs[1][0] += (p[0] + p[1]) + (p[4] + p[5]);
        rs[1][1] += (p[2] + p[3]) + (p[6] + p[7]);

        uint32_t ph[4], pl[4];
        cvt_pair(p[0], p[1], ph[0], pl[0]);
        cvt_pair(p[2], p[3], ph[1], pl[1]);
        cvt_pair(p[4], p[5], ph[2], pl[2]);
        cvt_pair(p[6], p[7], ph[3], pl[3]);

        mma_bf16(O[1][0], ph, vh[0], vh[1]);
        mma_bf16(O[1][1], ph, vh[2], vh[3]);
        mma_bf16(O[1][0], pl, vh[0], vh[1]);
        mma_bf16(O[1][1], pl, vh[2], vh[3]);
        mma_bf16(O[1][0], ph, vlr[0], vlr[1]);
        mma_bf16(O[1][1], ph, vlr[2], vlr[3]);
    }

    // Row sums: reduce, normalize, write split hi/lo bf16 attention-out.
    #pragma unroll
    for (int mt = 0; mt < 2; mt++) {
        float s0 = rs[mt][0], s1 = rs[mt][1];
        s0 += __shfl_xor_sync(0xffffffffu, s0, 1);
        s0 += __shfl_xor_sync(0xffffffffu, s0, 2);
        s1 += __shfl_xor_sync(0xffffffffu, s1, 1);
        s1 += __shfl_xor_sync(0xffffffffu, s1, 2);
        const float i0 = 1.f / s0, i1 = 1.f / s1;
        const int row = R0 + mt * 16 + qrow;
        const int dc  = qcol;
        #pragma unroll
        for (int dt = 0; dt < 2; dt++) {
            const int d = dt * 8 + dc;
            size_t i0x = ((size_t)(b * S_ + row)     * J_ + j) * H_ + n * HS_ + d;
            size_t i1x = ((size_t)(b * S_ + row + 8) * J_ + j) * H_ + n * HS_ + d;
            uint32_t hi, lo;
            cvt_pair(O[mt][dt][0] * i0, O[mt][dt][1] * i0, hi, lo);
            *(uint32_t*)(g_aoh + i0x) = hi;
            *(uint32_t*)(g_aol + i0x) = lo;
            cvt_pair(O[mt][dt][2] * i1, O[mt][dt][3] * i1, hi, lo);
            *(uint32_t*)(g_aoh + i1x) = hi;
            *(uint32_t*)(g_aol + i1x) = lo;
        }
    }
}

__global__ __launch_bounds__(512, 1)
void attn_mma()
{
    extern __shared__ char smem[];
    const int tid = threadIdx.x, wid = tid >> 5, lane = tid & 31;
    const uint32_t sbase = smem_u32(smem);
    const int i0 = blockIdx.x * 2, i1 = i0 + 1;

    // Stage both instances' K/V (group 0, group 1)
    stage_kv(sbase,           i0, tid);
    CP_COMMIT;
    stage_kv(sbase + AT_HALF, i1, tid);
    CP_COMMIT;

    // Warp -> band permutation: SMSP g gets bands {g, 7-g, 8+g, 15-g}
    const int g  = wid & 3, iq = wid >> 2;
    const int band = (iq == 0) ? g : (iq == 1) ? (7 - g) : (iq == 2) ? (8 + g) : (15 - g);

    uint32_t qh[2][4], ql[2][4];
    load_q(i0, band, lane, qh, ql);      // LDGs overlap the staging wait
    CP_WAIT1;                            // group 0 (instance 0 K/V) ready
    __syncthreads();
    attn_one(sbase, i0, band, lane, qh, ql);

    load_q(i1, band, lane, qh, ql);      // overlap residual group-1 wait
    CP_WAIT0;                            // group 1 ready (arrived under i0)
    __syncthreads();
    attn_one(sbase + AT_HALF, i1, band, lane, qh, ql);
}

// ===========================================================================
// Kernel 3: output projection + residual + LayerNorm — fully pipelined.
// (unchanged from R14 — measured 50.3 us)
// ===========================================================================
#define P_AHI  0
#define P_ALO  17408
#define P_B0HI 34816
#define P_B0LO 53248
#define P_B1HI 71680
#define P_B1LO 90112
#define P_XS   34816          // x tile aliases B0 region (after p0 retires it)
#define P_XROW 544            // x row stride bytes (512 data + 32 pad)
#define P_TOTAL 108544

__global__ __launch_bounds__(256, 2)
void proj_mma(const float* __restrict__ x,
              const float* __restrict__ gamma,
              const float* __restrict__ beta,
              float* __restrict__ out)
{
    extern __shared__ char smem[];
    const int j   = blockIdx.y;
    const int r0  = blockIdx.x * 64;
    const int tid = threadIdx.x, wid = tid >> 5, lane = tid & 31;
    const uint32_t sb = smem_u32(smem);

    // --- group 0: A (attention-out rows, hi+lo) + B0 (proj cols 0..63) ---
    #pragma unroll 4
    for (int i = tid; i < 2048; i += 256) {
        int buf = i >> 10;               // 0 hi, 1 lo
        int row = (i >> 4) & 63;
        int ch  = i & 15;
        const char* src = (const char*)(buf ? g_aol : g_aoh)
            + ((size_t)(r0 + row) * J_ + j) * H_ * 2 + ch * 16;
        cpa16(sb + (buf ? P_ALO : P_AHI) + row * SAB_B + ch * 16, src);
    }
    #pragma unroll 4
    for (int i = tid; i < 2048; i += 256) {
        int buf = i >> 10;
        int k   = (i >> 3) & 127;
        int ch  = i & 7;
        const char* src = (const char*)(buf ? g_pl : g_ph)
            + ((size_t)j * H_ * H_ + (size_t)k * H_) * 2 + ch * 16;
        cpa16(sb + (buf ? P_B0LO : P_B0HI) + k * SBN + ch * 16, src);
    }
    CP_COMMIT;
    // --- group 1: B1 (proj cols 64..127) — arrives under gemm p0 ---
    #pragma unroll 4
    for (int i = tid; i < 2048; i += 256) {
        int buf = i >> 10;
        int k   = (i >> 3) & 127;
        int ch  = i & 7;
        const char* src = (const char*)(buf ? g_pl : g_ph)
            + ((size_t)j * H_ * H_ + (size_t)k * H_ + 64) * 2 + ch * 16;
        cpa16(sb + (buf ? P_B1LO : P_B1HI) + k * SBN + ch * 16, src);
    }
    CP_COMMIT;
    CP_WAIT1;          // A + B0 ready (B1 may still be in flight)
    __syncthreads();

    const int warpM = wid & 3, warpN = wid >> 2;
    const int ar = lane & 15, ac = (lane >> 4) << 3;
    const int bg = lane >> 3, blp = lane & 7;
    const int kt = ((bg & 1) << 3) + blp;
    const int nb = (bg >> 1) << 4;
    const uint32_t aRow = (uint32_t)(warpM * 16 + ar) * SAB_B;

    float acc[2][4][4];   // [pass][ntile][frag]
    #pragma unroll
    for (int p = 0; p < 2; p++)
        #pragma unroll
        for (int nt = 0; nt < 4; nt++)
            #pragma unroll
            for (int i = 0; i < 4; i++) acc[p][nt][i] = 0.f;

    // ---- gemm pass 0 (B0) ----
    #pragma unroll 1
    for (int sp = 0; sp < 3; sp++) {
        const uint32_t aB = sb + ((sp == 2) ? P_ALO : P_AHI) + aRow;
        const uint32_t bB = sb + ((sp == 1) ? P_B0LO : P_B0HI);
        #pragma unroll
        for (int k0 = 0; k0 < 8; k0++) {
            uint32_t a[4];
            ldsm_x4(a[0], a[1], a[2], a[3], aB + (uint32_t)(k0 * 16 + ac) * 2);
            #pragma unroll
            for (int ntp = 0; ntp < 2; ntp++) {
                uint32_t bfr[4];
                ldsm_x4_t(bfr[0], bfr[1], bfr[2], bfr[3],
                          bB + (uint32_t)(k0 * 16 + kt) * SBN
                             + (uint32_t)(warpN * 32 + ntp * 16) * 2 + nb);
                mma_bf16(acc[0][ntp * 2],     a, bfr[0], bfr[1]);
                mma_bf16(acc[0][ntp * 2 + 1], a, bfr[2], bfr[3]);
            }
        }
    }
    __syncthreads();   // all warps done reading B0 region

    // --- group 2: x residual tile into retired B0 region (under gemm p1) ---
    #pragma unroll 4
    for (int i = tid; i < 2048; i += 256) {
        int row = i >> 5;                // 64 rows x 32 chunks (512B/row)
        int ch  = i & 31;
        const char* src = (const char*)x
            + ((size_t)(r0 + row) * J_ + j) * H_ * 4 + ch * 16;
        cpa16(sb + P_XS + row * P_XROW + ch * 16, src);
    }
    CP_COMMIT;
    CP_WAIT1;          // B1 ready (x may still be in flight)
    __syncthreads();

    // ---- gemm pass 1 (B1) ----
    #pragma unroll 1
    for (int sp = 0; sp < 3; sp++) {
        const uint32_t aB = sb + ((sp == 2) ? P_ALO : P_AHI) + aRow;
        const uint32_t bB = sb + ((sp == 1) ? P_B1LO : P_B1HI);
        #pragma unroll
        for (int k0 = 0; k0 < 8; k0++) {
            uint32_t a[4];
            ldsm_x4(a[0], a[1], a[2], a[3], aB + (uint32_t)(k0 * 16 + ac) * 2);
            #pragma unroll
            for (int ntp = 0; ntp < 2; ntp++) {
                uint32_t bfr[4];
                ldsm_x4_t(bfr[0], bfr[1], bfr[2], bfr[3],
                          bB + (uint32_t)(k0 * 16 + kt) * SBN
                             + (uint32_t)(warpN * 32 + ntp * 16) * 2 + nb);
                mma_bf16(acc[1][ntp * 2],     a, bfr[0], bfr[1]);
                mma_bf16(acc[1][ntp * 2 + 1], a, bfr[2], bfr[3]);
            }
        }
    }
    CP_WAIT0;          // x arrived
    __syncthreads();   // all warps done reading A region

    // Stage C into retired A region: [64][132] floats (33792 B <= 34816 B)
    float* Cs = (float*)smem;
    #pragma unroll
    for (int p = 0; p < 2; p++) {
        int rb = warpM * 16 + (lane >> 2);
        #pragma unroll
        for (int nt = 0; nt < 4; nt++) {
            int col = p * 64 + warpN * 32 + nt * 8 + ((lane & 3) << 1);
            #pragma unroll
            for (int h = 0; h < 2; h++) {
                Cs[(rb + h * 8) * 132 + col]     = acc[p][nt][h * 2];
                Cs[(rb + h * 8) * 132 + col + 1] = acc[p][nt][h * 2 + 1];
            }
        }
    }
    __syncthreads();

    // Residual + LN: 4 threads per row (32 cols each); x from smem.
    {
        const int row = tid >> 2;
        const int q   = tid & 3;
        const int r   = r0 + row;
        const float* xr = (const float*)(smem + P_XS + row * P_XROW) + q * 32;
        float* crow     = Cs + row * 132 + q * 32;

        float sum = 0.f, sq = 0.f;
        #pragma unroll
        for (int i = 0; i < 8; i++) {
            float4 c4 = *(float4*)(crow + i * 4);
            float4 xv = *(const float4*)(xr + i * 4);
            c4.x += xv.x; c4.y += xv.y; c4.z += xv.z; c4.w += xv.w;
            *(float4*)(crow + i * 4) = c4;
            sum += c4.x + c4.y + c4.z + c4.w;
            sq  += c4.x*c4.x + c4.y*c4.y + c4.z*c4.z + c4.w*c4.w;
        }
        sum += __shfl_xor_sync(0xffffffffu, sum, 1);
        sum += __shfl_xor_sync(0xffffffffu, sum, 2);
        sq  += __shfl_xor_sync(0xffffffffu, sq, 1);
        sq  += __shfl_xor_sync(0xffffffffu, sq, 2);
        const float mu   = sum * (1.f / 128.f);
        const float var  = sq * (1.f / 128.f) - mu * mu;
        const float rstd = rsqrtf(var + 1e-5f);

        float* orow = out + ((size_t)r * J_ + j) * H_ + q * 32;
        const float* gp  = gamma + q * 32;
        const float* bp2 = beta  + q * 32;
        #pragma unroll
        for (int i = 0; i < 8; i++) {
            float4 c4 = *(float4*)(crow + i * 4);
            float4 o;
            o.x = (c4.x - mu) * rstd * gp[i*4+0] + bp2[i*4+0];
            o.y = (c4.y - mu) * rstd * gp[i*4+1] + bp2[i*4+1];
            o.z = (c4.z - mu) * rstd * gp[i*4+2] + bp2[i*4+2];
            o.w = (c4.w - mu) * rstd * gp[i*4+3] + bp2[i*4+3];
            *(float4*)(orow + i * 4) = o;
        }
    }
}

// ===========================================================================
extern "C" void kernel_launch(void* const* d_in, const int* in_sizes, int n_in,
                              void* d_out, int out_size)
{
    const float* x     = (const float*)d_in[0];
    // d_in[1]: additive causal mask (= triu(-1e9)) — implemented as causal skip.
    const float* qm    = (const float*)d_in[2];
    const float* km    = (const float*)d_in[3];
    const float* vm    = (const float*)d_in[4];
    const float* proj  = (const float*)d_in[5];
    const float* gamma = (const float*)d_in[6];
    const float* beta  = (const float*)d_in[7];
    float* out = (float*)d_out;

    cudaFuncSetAttribute(qkv_mma,  cudaFuncAttributeMaxDynamicSharedMemorySize, QK_TOTAL);
    cudaFuncSetAttribute(attn_mma, cudaFuncAttributeMaxDynamicSharedMemorySize, AT_TOTAL);
    cudaFuncSetAttribute(proj_mma, cudaFuncAttributeMaxDynamicSharedMemorySize, P_TOTAL);

    prep<<<PREP_T / 256, 256>>>(x, qm, km, vm, proj);
    qkv_mma<<<dim3(BS_/128, J_, 2), 256, QK_TOTAL>>>();
    attn_mma<<<INST_/2, 512, AT_TOTAL>>>();
    proj_mma<<<dim3(BS_/64, J_), 256, P_TOTAL>>>(x, gamma, beta, out);
}